// round 5
// baseline (speedup 1.0000x reference)
#include <cuda_runtime.h>
#include <cuda_bf16.h>

// ---------------------------------------------------------------------------
// RGCN link predictor:
//   counts -> inv -> CSR build (scan + scatter, shared by both layers)
//   GEMM1 (x @ [W1|root1], fused -> H1/Z1) -> CSR warp-per-node agg (no atomics)
//   GEMM2 (relu(Z1) @ [W2|root2], fused -> H2/Z2) -> CSR agg -> decoder MLP
// __device__ globals only referenced from device code (round-3 lesson).
// ---------------------------------------------------------------------------

#define NN    100000
#define REL   3
#define EMAX  1600000

// scratch (static device globals; no allocation allowed)
__device__ int      g_cnt[NN * REL];
__device__ float    g_inv[NN * REL];
__device__ int      g_off[NN + 1];
__device__ int      g_cur[NN];
__device__ unsigned g_epk[EMAX];     // src | (rel << 20), sorted by dst
__device__ float    g_H1[NN * 192];
__device__ float    g_Z1[NN * 64];
__device__ float    g_H2[NN * 96];
__device__ float    g_Z2[NN * 32];
__device__ float    g_Wc1[128 * 256];
__device__ float    g_Wc2[64 * 128];

// ---------------------------------------------------------------------------
__global__ void zero_cnt_kernel(int n) {
    int i = blockIdx.x * blockDim.x + threadIdx.x;
    if (i < n) g_cnt[i] = 0;
}

__global__ void count_kernel(const int* __restrict__ dst,
                             const int* __restrict__ et, int E) {
    int e = blockIdx.x * blockDim.x + threadIdx.x;
    if (e < E) atomicAdd(&g_cnt[dst[e] * 3 + et[e]], 1);
}

__global__ void inv_kernel(int n) {
    int i = blockIdx.x * blockDim.x + threadIdx.x;
    if (i < n) g_inv[i] = 1.0f / fmaxf((float)g_cnt[i], 1.0f);
}

// single-block hierarchical exclusive scan of node degrees -> g_off, g_cur
__global__ void __launch_bounds__(1024) scan_kernel() {
    __shared__ int ssum[1024];
    const int t = threadIdx.x;
    const int CH = (NN + 1023) / 1024;          // 98
    const int base = t * CH;
    const int lim = min(base + CH, NN);

    int sum = 0;
    for (int i = base; i < lim; i++)
        sum += g_cnt[3 * i] + g_cnt[3 * i + 1] + g_cnt[3 * i + 2];
    ssum[t] = sum;
    __syncthreads();

    // Hillis-Steele inclusive scan over 1024 entries
    for (int o = 1; o < 1024; o <<= 1) {
        int v = (t >= o) ? ssum[t - o] : 0;
        __syncthreads();
        ssum[t] += v;
        __syncthreads();
    }

    int run = (t == 0) ? 0 : ssum[t - 1];       // exclusive prefix of chunk
    for (int i = base; i < lim; i++) {
        g_off[i] = run;
        g_cur[i] = run;
        run += g_cnt[3 * i] + g_cnt[3 * i + 1] + g_cnt[3 * i + 2];
    }
    if (t == 1023) g_off[NN] = ssum[1023];
}

__global__ void scatter_kernel(const int* __restrict__ src,
                               const int* __restrict__ dst,
                               const int* __restrict__ et, int E) {
    int e = blockIdx.x * blockDim.x + threadIdx.x;
    if (e < E) {
        int pos = atomicAdd(&g_cur[dst[e]], 1);
        g_epk[pos] = (unsigned)src[e] | ((unsigned)et[e] << 20);
    }
}

// pack [W1 r0|r1|r2 | root1] -> g_Wc1 [128,256]
__global__ void wc1_kernel(const float* __restrict__ W1,
                           const float* __restrict__ root1) {
    int i = blockIdx.x * blockDim.x + threadIdx.x;
    if (i < 128 * 256) {
        int k = i >> 8, c = i & 255;
        float v;
        if (c < 192) {
            int r = c >> 6, j = c & 63;
            v = W1[r * 128 * 64 + k * 64 + j];
        } else {
            v = root1[k * 64 + (c - 192)];
        }
        g_Wc1[i] = v;
    }
}

// pack [W2 r0|r1|r2 | root2] -> g_Wc2 [64,128]
__global__ void wc2_kernel(const float* __restrict__ W2,
                           const float* __restrict__ root2) {
    int i = blockIdx.x * blockDim.x + threadIdx.x;
    if (i < 64 * 128) {
        int k = i >> 7, c = i & 127;
        float v;
        if (c < 96) {
            int r = c >> 5, j = c & 31;
            v = W2[r * 64 * 32 + k * 32 + j];
        } else {
            v = root2[k * 32 + (c - 96)];
        }
        g_Wc2[i] = v;
    }
}

// ---------------------------------------------------------------------------
// 128x128 tile fp32 GEMM, BK=16, 256 threads, 8x8 microtile, double-buffered.
// Fused epilogue: cols [0,HCOLS) -> H, cols [HCOLS,NTOT) -> Z (+bias).
// ---------------------------------------------------------------------------
template <int NTOT, int K, int HCOLS, bool RELU>
__device__ __forceinline__ void gemm_fused_core(
    const float* __restrict__ A, const float* __restrict__ B,
    float* __restrict__ H, float* __restrict__ Z,
    const float* __restrict__ bias, int M) {

    __shared__ float As[2][16][128];
    __shared__ float Bs[2][16][128];

    const int tid = threadIdx.x;
    const int tx = tid & 15, ty = tid >> 4;
    const int m0 = blockIdx.y * 128, n0 = blockIdx.x * 128;

    float4 aReg[2], bReg[2];
    float acc[8][8] = {};

    auto loadTiles = [&](int k0) {
#pragma unroll
        for (int i = 0; i < 2; i++) {
            int idx = tid + i * 256;
            int row = idx >> 2, c4 = idx & 3;
            int gr = m0 + row;
            float4 v = make_float4(0.f, 0.f, 0.f, 0.f);
            if (gr < M) v = *(const float4*)&A[(size_t)gr * K + k0 + c4 * 4];
            if (RELU) {
                v.x = fmaxf(v.x, 0.f); v.y = fmaxf(v.y, 0.f);
                v.z = fmaxf(v.z, 0.f); v.w = fmaxf(v.w, 0.f);
            }
            aReg[i] = v;
        }
#pragma unroll
        for (int i = 0; i < 2; i++) {
            int idx = tid + i * 256;
            int row = idx >> 5, c4 = idx & 31;
            bReg[i] = *(const float4*)&B[(size_t)(k0 + row) * NTOT + n0 + c4 * 4];
        }
    };
    auto storeTiles = [&](int buf) {
#pragma unroll
        for (int i = 0; i < 2; i++) {
            int idx = tid + i * 256;
            int row = idx >> 2, c4 = idx & 3;
            As[buf][c4 * 4 + 0][row] = aReg[i].x;
            As[buf][c4 * 4 + 1][row] = aReg[i].y;
            As[buf][c4 * 4 + 2][row] = aReg[i].z;
            As[buf][c4 * 4 + 3][row] = aReg[i].w;
        }
#pragma unroll
        for (int i = 0; i < 2; i++) {
            int idx = tid + i * 256;
            int row = idx >> 5, c4 = idx & 31;
            *(float4*)&Bs[buf][row][c4 * 4] = bReg[i];
        }
    };

    constexpr int KT = K / 16;
    loadTiles(0);
    storeTiles(0);
    __syncthreads();

    int buf = 0;
#pragma unroll
    for (int kt = 0; kt < KT; kt++) {
        if (kt + 1 < KT) loadTiles((kt + 1) * 16);

#pragma unroll
        for (int kk = 0; kk < 16; kk++) {
            float4 a0 = *(float4*)&As[buf][kk][ty * 8];
            float4 a1 = *(float4*)&As[buf][kk][ty * 8 + 4];
            float4 b0 = *(float4*)&Bs[buf][kk][tx * 8];
            float4 b1 = *(float4*)&Bs[buf][kk][tx * 8 + 4];
            float av[8] = {a0.x, a0.y, a0.z, a0.w, a1.x, a1.y, a1.z, a1.w};
            float bv[8] = {b0.x, b0.y, b0.z, b0.w, b1.x, b1.y, b1.z, b1.w};
#pragma unroll
            for (int i = 0; i < 8; i++)
#pragma unroll
                for (int j = 0; j < 8; j++)
                    acc[i][j] += av[i] * bv[j];
        }

        if (kt + 1 < KT) {
            buf ^= 1;
            storeTiles(buf);
            __syncthreads();
        }
    }

    const int cb = n0 + tx * 8;
    constexpr int ZW = NTOT - HCOLS;
    if (cb < HCOLS) {
#pragma unroll
        for (int i = 0; i < 8; i++) {
            int gr = m0 + ty * 8 + i;
            if (gr < M) {
                *(float4*)&H[(size_t)gr * HCOLS + cb] =
                    make_float4(acc[i][0], acc[i][1], acc[i][2], acc[i][3]);
                *(float4*)&H[(size_t)gr * HCOLS + cb + 4] =
                    make_float4(acc[i][4], acc[i][5], acc[i][6], acc[i][7]);
            }
        }
    } else {
        int zc = cb - HCOLS;
        float4 bia0 = *(const float4*)&bias[zc];
        float4 bia1 = *(const float4*)&bias[zc + 4];
#pragma unroll
        for (int i = 0; i < 8; i++) {
            int gr = m0 + ty * 8 + i;
            if (gr < M) {
                *(float4*)&Z[(size_t)gr * ZW + zc] =
                    make_float4(acc[i][0] + bia0.x, acc[i][1] + bia0.y,
                                acc[i][2] + bia0.z, acc[i][3] + bia0.w);
                *(float4*)&Z[(size_t)gr * ZW + zc + 4] =
                    make_float4(acc[i][4] + bia1.x, acc[i][5] + bia1.y,
                                acc[i][6] + bia1.z, acc[i][7] + bia1.w);
            }
        }
    }
}

__global__ void __launch_bounds__(256) gemm1_kernel(const float* __restrict__ x,
                                                    const float* __restrict__ b1) {
    gemm_fused_core<256, 128, 192, false>(x, g_Wc1, g_H1, g_Z1, b1, NN);
}
__global__ void __launch_bounds__(256) gemm2_kernel(const float* __restrict__ b2) {
    gemm_fused_core<128, 64, 96, true>(g_Z1, g_Wc2, g_H2, g_Z2, b2, NN);
}

// ---------------------------------------------------------------------------
// CSR warp-per-node aggregation, NO atomics:
//   Z[d, :] += sum_{e in edges(d)} inv[d][rel_e] * H[src_e, rel_e*C : +C]
// C=64: float2 per lane.  C=32: float per lane.
// ---------------------------------------------------------------------------
__global__ void __launch_bounds__(256) agg1_csr_kernel() {
    int d = (blockIdx.x * blockDim.x + threadIdx.x) >> 5;
    int lane = threadIdx.x & 31;
    if (d >= NN) return;
    int beg = g_off[d], end = g_off[d + 1];
    if (beg == end) return;
    float i0 = g_inv[3 * d], i1 = g_inv[3 * d + 1], i2 = g_inv[3 * d + 2];

    float2 acc = make_float2(0.f, 0.f);
    for (int i = beg; i < end; i++) {
        unsigned v = g_epk[i];
        int s = v & 0xFFFFF;
        int r = v >> 20;
        float sc = (r == 0) ? i0 : ((r == 1) ? i1 : i2);
        float2 h = *(const float2*)&g_H1[(size_t)s * 192 + r * 64 + lane * 2];
        acc.x += h.x * sc;
        acc.y += h.y * sc;
    }
    float2 z = *(float2*)&g_Z1[(size_t)d * 64 + lane * 2];
    z.x += acc.x; z.y += acc.y;
    *(float2*)&g_Z1[(size_t)d * 64 + lane * 2] = z;
}

__global__ void __launch_bounds__(256) agg2_csr_kernel() {
    int d = (blockIdx.x * blockDim.x + threadIdx.x) >> 5;
    int lane = threadIdx.x & 31;
    if (d >= NN) return;
    int beg = g_off[d], end = g_off[d + 1];
    if (beg == end) return;
    float i0 = g_inv[3 * d], i1 = g_inv[3 * d + 1], i2 = g_inv[3 * d + 2];

    float acc = 0.f;
    for (int i = beg; i < end; i++) {
        unsigned v = g_epk[i];
        int s = v & 0xFFFFF;
        int r = v >> 20;
        float sc = (r == 0) ? i0 : ((r == 1) ? i1 : i2);
        acc += g_H2[(size_t)s * 96 + r * 32 + lane] * sc;
    }
    g_Z2[(size_t)d * 32 + lane] += acc;
}

// ---------------------------------------------------------------------------
// decoder: out[p] = relu(concat(z2[s], z2[d]) @ Wd1 + bd1) @ Wd2 + bd2
// ---------------------------------------------------------------------------
__global__ void __launch_bounds__(128) decoder_kernel(
    const int* __restrict__ psrc, const int* __restrict__ pdst,
    const float* __restrict__ Wd1, const float* __restrict__ bd1,
    const float* __restrict__ Wd2, const float* __restrict__ bd2,
    float* __restrict__ out, int P) {
    __shared__ float sW[64 * 64];
    __shared__ float sB1[64];
    __shared__ float sW2[64];
    int tid = threadIdx.x;
    for (int i = tid; i < 64 * 64; i += 128) sW[i] = Wd1[i];
    if (tid < 64) { sB1[tid] = bd1[tid]; sW2[tid] = Wd2[tid]; }
    __syncthreads();

    int p = blockIdx.x * 128 + tid;
    if (p >= P) return;
    int s = psrc[p], d = pdst[p];

    float ef[64];
#pragma unroll
    for (int q = 0; q < 8; q++) {
        float4 v = *(const float4*)&g_Z2[(size_t)s * 32 + q * 4];
        ef[q * 4 + 0] = v.x; ef[q * 4 + 1] = v.y;
        ef[q * 4 + 2] = v.z; ef[q * 4 + 3] = v.w;
    }
#pragma unroll
    for (int q = 0; q < 8; q++) {
        float4 v = *(const float4*)&g_Z2[(size_t)d * 32 + q * 4];
        ef[32 + q * 4 + 0] = v.x; ef[32 + q * 4 + 1] = v.y;
        ef[32 + q * 4 + 2] = v.z; ef[32 + q * 4 + 3] = v.w;
    }

    float o = bd2[0];
    for (int j0 = 0; j0 < 64; j0 += 4) {
        float4 bb = *(float4*)&sB1[j0];
        float a0 = bb.x, a1 = bb.y, a2 = bb.z, a3 = bb.w;
#pragma unroll
        for (int k = 0; k < 64; k++) {
            float4 w = *(float4*)&sW[k * 64 + j0];
            float ev = ef[k];
            a0 += ev * w.x; a1 += ev * w.y; a2 += ev * w.z; a3 += ev * w.w;
        }
        float4 w2 = *(float4*)&sW2[j0];
        o += fmaxf(a0, 0.f) * w2.x + fmaxf(a1, 0.f) * w2.y +
             fmaxf(a2, 0.f) * w2.z + fmaxf(a3, 0.f) * w2.w;
    }
    out[p] = o;
}

// ---------------------------------------------------------------------------
extern "C" void kernel_launch(void* const* d_in, const int* in_sizes, int n_in,
                              void* d_out, int out_size) {
    const float* x     = (const float*)d_in[0];
    const int*   ei    = (const int*)d_in[1];
    const int*   et    = (const int*)d_in[2];
    const int*   pe    = (const int*)d_in[3];
    const float* W1    = (const float*)d_in[4];
    const float* root1 = (const float*)d_in[5];
    const float* b1    = (const float*)d_in[6];
    const float* W2    = (const float*)d_in[7];
    const float* root2 = (const float*)d_in[8];
    const float* b2    = (const float*)d_in[9];
    const float* Wd1   = (const float*)d_in[10];
    const float* bd1   = (const float*)d_in[11];
    const float* Wd2   = (const float*)d_in[12];
    const float* bd2   = (const float*)d_in[13];
    float* out = (float*)d_out;

    const int E = in_sizes[1] / 2;
    const int P = in_sizes[3] / 2;
    const int* src = ei;
    const int* dst = ei + E;
    const int* ps  = pe;
    const int* pd  = pe + P;

    // counts + inverse means + CSR (shared by both layers)
    zero_cnt_kernel<<<(NN * 3 + 255) / 256, 256>>>(NN * 3);
    count_kernel<<<(E + 255) / 256, 256>>>(dst, et, E);
    inv_kernel<<<(NN * 3 + 255) / 256, 256>>>(NN * 3);
    scan_kernel<<<1, 1024>>>();
    scatter_kernel<<<(E + 255) / 256, 256>>>(src, dst, et, E);

    // pack weights
    wc1_kernel<<<(128 * 256 + 255) / 256, 256>>>(W1, root1);
    wc2_kernel<<<(64 * 128 + 255) / 256, 256>>>(W2, root2);

    // layer 1
    {
        dim3 g(2, (NN + 127) / 128);
        gemm1_kernel<<<g, 256>>>(x, b1);
    }
    agg1_csr_kernel<<<(NN * 32 + 255) / 256, 256>>>();

    // layer 2 (relu folded into GEMM2 A-loads)
    {
        dim3 g(1, (NN + 127) / 128);
        gemm2_kernel<<<g, 256>>>(b2);
    }
    agg2_csr_kernel<<<(NN * 32 + 255) / 256, 256>>>();

    // decoder
    decoder_kernel<<<(P + 127) / 128, 128>>>(ps, pd, Wd1, bd1, Wd2, bd2, out, P);
}

// round 6
// speedup vs baseline: 1.4232x; 1.4232x over previous
#include <cuda_runtime.h>
#include <cuda_bf16.h>

// ---------------------------------------------------------------------------
// RGCN link predictor:
//   GEMM1 (x @ [W1|root1], fused -> H1/Z1)   [launched early for profiling]
//   counts -> inv -> parallel 3-phase scan -> CSR scatter
//   CSR warp-per-node agg (no atomics) -> GEMM2 -> agg -> decoder MLP
// __device__ globals only referenced from device code (round-3 lesson).
// ---------------------------------------------------------------------------

#define NN    100000
#define REL   3
#define EMAX  1600000
#define SCAN_BS   256
#define SCAN_NB   ((NN + SCAN_BS - 1) / SCAN_BS)   // 391

// scratch (static device globals; no allocation allowed)
__device__ int      g_cnt[NN * REL];
__device__ float    g_inv[NN * REL];
__device__ int      g_off[NN + 1];
__device__ int      g_cur[NN];
__device__ int      g_bsum[SCAN_NB];
__device__ int      g_bpre[SCAN_NB];
__device__ unsigned g_epk[EMAX];     // src | (rel << 20), sorted by dst
__device__ float    g_H1[NN * 192];
__device__ float    g_Z1[NN * 64];
__device__ float    g_H2[NN * 96];
__device__ float    g_Z2[NN * 32];
__device__ float    g_Wc1[128 * 256];
__device__ float    g_Wc2[64 * 128];

// ---------------------------------------------------------------------------
__global__ void zero_cnt_kernel(int n) {
    int i = blockIdx.x * blockDim.x + threadIdx.x;
    if (i < n) g_cnt[i] = 0;
}

__global__ void count_kernel(const int* __restrict__ dst,
                             const int* __restrict__ et, int E) {
    int e = blockIdx.x * blockDim.x + threadIdx.x;
    if (e < E) atomicAdd(&g_cnt[dst[e] * 3 + et[e]], 1);
}

__global__ void inv_kernel(int n) {
    int i = blockIdx.x * blockDim.x + threadIdx.x;
    if (i < n) g_inv[i] = 1.0f / fmaxf((float)g_cnt[i], 1.0f);
}

// ---- parallel 3-phase exclusive scan of node degrees ----------------------
// phase 1: block-local exclusive scan, block sums out
__global__ void __launch_bounds__(SCAN_BS) scan1_kernel() {
    __shared__ int s[SCAN_BS];
    int t = threadIdx.x;
    int i = blockIdx.x * SCAN_BS + t;
    int d = 0;
    if (i < NN) d = g_cnt[3 * i] + g_cnt[3 * i + 1] + g_cnt[3 * i + 2];
    s[t] = d;
    __syncthreads();
#pragma unroll
    for (int o = 1; o < SCAN_BS; o <<= 1) {
        int v = (t >= o) ? s[t - o] : 0;
        __syncthreads();
        s[t] += v;
        __syncthreads();
    }
    if (i < NN) g_off[i] = s[t] - d;            // exclusive local prefix
    if (t == SCAN_BS - 1) g_bsum[blockIdx.x] = s[t];
}

// phase 2: scan the block sums (single block; SCAN_NB <= 512)
__global__ void __launch_bounds__(512) scan2_kernel() {
    __shared__ int s[512];
    int t = threadIdx.x;
    int v0 = (t < SCAN_NB) ? g_bsum[t] : 0;
    s[t] = v0;
    __syncthreads();
#pragma unroll
    for (int o = 1; o < 512; o <<= 1) {
        int v = (t >= o) ? s[t - o] : 0;
        __syncthreads();
        s[t] += v;
        __syncthreads();
    }
    if (t < SCAN_NB) g_bpre[t] = s[t] - v0;     // exclusive block prefix
    if (t == 511) g_off[NN] = s[511];           // grand total
}

// phase 3: add block prefix, init cursors
__global__ void scan3_kernel() {
    int i = blockIdx.x * blockDim.x + threadIdx.x;
    if (i < NN) {
        int off = g_off[i] + g_bpre[i / SCAN_BS];
        g_off[i] = off;
        g_cur[i] = off;
    }
}

__global__ void scatter_kernel(const int* __restrict__ src,
                               const int* __restrict__ dst,
                               const int* __restrict__ et, int E) {
    int e = blockIdx.x * blockDim.x + threadIdx.x;
    if (e < E) {
        int pos = atomicAdd(&g_cur[dst[e]], 1);
        g_epk[pos] = (unsigned)src[e] | ((unsigned)et[e] << 20);
    }
}

// pack [W1 r0|r1|r2 | root1] -> g_Wc1 [128,256]
__global__ void wc1_kernel(const float* __restrict__ W1,
                           const float* __restrict__ root1) {
    int i = blockIdx.x * blockDim.x + threadIdx.x;
    if (i < 128 * 256) {
        int k = i >> 8, c = i & 255;
        float v;
        if (c < 192) {
            int r = c >> 6, j = c & 63;
            v = W1[r * 128 * 64 + k * 64 + j];
        } else {
            v = root1[k * 64 + (c - 192)];
        }
        g_Wc1[i] = v;
    }
}

// pack [W2 r0|r1|r2 | root2] -> g_Wc2 [64,128]
__global__ void wc2_kernel(const float* __restrict__ W2,
                           const float* __restrict__ root2) {
    int i = blockIdx.x * blockDim.x + threadIdx.x;
    if (i < 64 * 128) {
        int k = i >> 7, c = i & 127;
        float v;
        if (c < 96) {
            int r = c >> 5, j = c & 31;
            v = W2[r * 64 * 32 + k * 32 + j];
        } else {
            v = root2[k * 32 + (c - 96)];
        }
        g_Wc2[i] = v;
    }
}

// ---------------------------------------------------------------------------
// 128x128 tile fp32 GEMM, BK=16, 256 threads, 8x8 microtile, double-buffered.
// Fused epilogue: cols [0,HCOLS) -> H, cols [HCOLS,NTOT) -> Z (+bias).
// ---------------------------------------------------------------------------
template <int NTOT, int K, int HCOLS, bool RELU>
__device__ __forceinline__ void gemm_fused_core(
    const float* __restrict__ A, const float* __restrict__ B,
    float* __restrict__ H, float* __restrict__ Z,
    const float* __restrict__ bias, int M) {

    __shared__ float As[2][16][128];
    __shared__ float Bs[2][16][128];

    const int tid = threadIdx.x;
    const int tx = tid & 15, ty = tid >> 4;
    const int m0 = blockIdx.y * 128, n0 = blockIdx.x * 128;

    float4 aReg[2], bReg[2];
    float acc[8][8] = {};

    auto loadTiles = [&](int k0) {
#pragma unroll
        for (int i = 0; i < 2; i++) {
            int idx = tid + i * 256;
            int row = idx >> 2, c4 = idx & 3;
            int gr = m0 + row;
            float4 v = make_float4(0.f, 0.f, 0.f, 0.f);
            if (gr < M) v = *(const float4*)&A[(size_t)gr * K + k0 + c4 * 4];
            if (RELU) {
                v.x = fmaxf(v.x, 0.f); v.y = fmaxf(v.y, 0.f);
                v.z = fmaxf(v.z, 0.f); v.w = fmaxf(v.w, 0.f);
            }
            aReg[i] = v;
        }
#pragma unroll
        for (int i = 0; i < 2; i++) {
            int idx = tid + i * 256;
            int row = idx >> 5, c4 = idx & 31;
            bReg[i] = *(const float4*)&B[(size_t)(k0 + row) * NTOT + n0 + c4 * 4];
        }
    };
    auto storeTiles = [&](int buf) {
#pragma unroll
        for (int i = 0; i < 2; i++) {
            int idx = tid + i * 256;
            int row = idx >> 2, c4 = idx & 3;
            As[buf][c4 * 4 + 0][row] = aReg[i].x;
            As[buf][c4 * 4 + 1][row] = aReg[i].y;
            As[buf][c4 * 4 + 2][row] = aReg[i].z;
            As[buf][c4 * 4 + 3][row] = aReg[i].w;
        }
#pragma unroll
        for (int i = 0; i < 2; i++) {
            int idx = tid + i * 256;
            int row = idx >> 5, c4 = idx & 31;
            *(float4*)&Bs[buf][row][c4 * 4] = bReg[i];
        }
    };

    constexpr int KT = K / 16;
    loadTiles(0);
    storeTiles(0);
    __syncthreads();

    int buf = 0;
#pragma unroll
    for (int kt = 0; kt < KT; kt++) {
        if (kt + 1 < KT) loadTiles((kt + 1) * 16);

#pragma unroll
        for (int kk = 0; kk < 16; kk++) {
            float4 a0 = *(float4*)&As[buf][kk][ty * 8];
            float4 a1 = *(float4*)&As[buf][kk][ty * 8 + 4];
            float4 b0 = *(float4*)&Bs[buf][kk][tx * 8];
            float4 b1 = *(float4*)&Bs[buf][kk][tx * 8 + 4];
            float av[8] = {a0.x, a0.y, a0.z, a0.w, a1.x, a1.y, a1.z, a1.w};
            float bv[8] = {b0.x, b0.y, b0.z, b0.w, b1.x, b1.y, b1.z, b1.w};
#pragma unroll
            for (int i = 0; i < 8; i++)
#pragma unroll
                for (int j = 0; j < 8; j++)
                    acc[i][j] += av[i] * bv[j];
        }

        if (kt + 1 < KT) {
            buf ^= 1;
            storeTiles(buf);
            __syncthreads();
        }
    }

    const int cb = n0 + tx * 8;
    constexpr int ZW = NTOT - HCOLS;
    if (cb < HCOLS) {
#pragma unroll
        for (int i = 0; i < 8; i++) {
            int gr = m0 + ty * 8 + i;
            if (gr < M) {
                *(float4*)&H[(size_t)gr * HCOLS + cb] =
                    make_float4(acc[i][0], acc[i][1], acc[i][2], acc[i][3]);
                *(float4*)&H[(size_t)gr * HCOLS + cb + 4] =
                    make_float4(acc[i][4], acc[i][5], acc[i][6], acc[i][7]);
            }
        }
    } else {
        int zc = cb - HCOLS;
        float4 bia0 = *(const float4*)&bias[zc];
        float4 bia1 = *(const float4*)&bias[zc + 4];
#pragma unroll
        for (int i = 0; i < 8; i++) {
            int gr = m0 + ty * 8 + i;
            if (gr < M) {
                *(float4*)&Z[(size_t)gr * ZW + zc] =
                    make_float4(acc[i][0] + bia0.x, acc[i][1] + bia0.y,
                                acc[i][2] + bia0.z, acc[i][3] + bia0.w);
                *(float4*)&Z[(size_t)gr * ZW + zc + 4] =
                    make_float4(acc[i][4] + bia1.x, acc[i][5] + bia1.y,
                                acc[i][6] + bia1.z, acc[i][7] + bia1.w);
            }
        }
    }
}

__global__ void __launch_bounds__(256) gemm1_kernel(const float* __restrict__ x,
                                                    const float* __restrict__ b1) {
    gemm_fused_core<256, 128, 192, false>(x, g_Wc1, g_H1, g_Z1, b1, NN);
}
__global__ void __launch_bounds__(256) gemm2_kernel(const float* __restrict__ b2) {
    gemm_fused_core<128, 64, 96, true>(g_Z1, g_Wc2, g_H2, g_Z2, b2, NN);
}

// ---------------------------------------------------------------------------
// CSR warp-per-node aggregation, NO atomics.
// ---------------------------------------------------------------------------
__global__ void __launch_bounds__(256) agg1_csr_kernel() {
    int d = (blockIdx.x * blockDim.x + threadIdx.x) >> 5;
    int lane = threadIdx.x & 31;
    if (d >= NN) return;
    int beg = g_off[d], end = g_off[d + 1];
    if (beg == end) return;
    float i0 = g_inv[3 * d], i1 = g_inv[3 * d + 1], i2 = g_inv[3 * d + 2];

    float2 acc = make_float2(0.f, 0.f);
    for (int i = beg; i < end; i++) {
        unsigned v = g_epk[i];
        int s = v & 0xFFFFF;
        int r = v >> 20;
        float sc = (r == 0) ? i0 : ((r == 1) ? i1 : i2);
        float2 h = *(const float2*)&g_H1[(size_t)s * 192 + r * 64 + lane * 2];
        acc.x += h.x * sc;
        acc.y += h.y * sc;
    }
    float2 z = *(float2*)&g_Z1[(size_t)d * 64 + lane * 2];
    z.x += acc.x; z.y += acc.y;
    *(float2*)&g_Z1[(size_t)d * 64 + lane * 2] = z;
}

__global__ void __launch_bounds__(256) agg2_csr_kernel() {
    int d = (blockIdx.x * blockDim.x + threadIdx.x) >> 5;
    int lane = threadIdx.x & 31;
    if (d >= NN) return;
    int beg = g_off[d], end = g_off[d + 1];
    if (beg == end) return;
    float i0 = g_inv[3 * d], i1 = g_inv[3 * d + 1], i2 = g_inv[3 * d + 2];

    float acc = 0.f;
    for (int i = beg; i < end; i++) {
        unsigned v = g_epk[i];
        int s = v & 0xFFFFF;
        int r = v >> 20;
        float sc = (r == 0) ? i0 : ((r == 1) ? i1 : i2);
        acc += g_H2[(size_t)s * 96 + r * 32 + lane] * sc;
    }
    g_Z2[(size_t)d * 32 + lane] += acc;
}

// ---------------------------------------------------------------------------
// decoder: out[p] = relu(concat(z2[s], z2[d]) @ Wd1 + bd1) @ Wd2 + bd2
// ---------------------------------------------------------------------------
__global__ void __launch_bounds__(128) decoder_kernel(
    const int* __restrict__ psrc, const int* __restrict__ pdst,
    const float* __restrict__ Wd1, const float* __restrict__ bd1,
    const float* __restrict__ Wd2, const float* __restrict__ bd2,
    float* __restrict__ out, int P) {
    __shared__ float sW[64 * 64];
    __shared__ float sB1[64];
    __shared__ float sW2[64];
    int tid = threadIdx.x;
    for (int i = tid; i < 64 * 64; i += 128) sW[i] = Wd1[i];
    if (tid < 64) { sB1[tid] = bd1[tid]; sW2[tid] = Wd2[tid]; }
    __syncthreads();

    int p = blockIdx.x * 128 + tid;
    if (p >= P) return;
    int s = psrc[p], d = pdst[p];

    float ef[64];
#pragma unroll
    for (int q = 0; q < 8; q++) {
        float4 v = *(const float4*)&g_Z2[(size_t)s * 32 + q * 4];
        ef[q * 4 + 0] = v.x; ef[q * 4 + 1] = v.y;
        ef[q * 4 + 2] = v.z; ef[q * 4 + 3] = v.w;
    }
#pragma unroll
    for (int q = 0; q < 8; q++) {
        float4 v = *(const float4*)&g_Z2[(size_t)d * 32 + q * 4];
        ef[32 + q * 4 + 0] = v.x; ef[32 + q * 4 + 1] = v.y;
        ef[32 + q * 4 + 2] = v.z; ef[32 + q * 4 + 3] = v.w;
    }

    float o = bd2[0];
    for (int j0 = 0; j0 < 64; j0 += 4) {
        float4 bb = *(float4*)&sB1[j0];
        float a0 = bb.x, a1 = bb.y, a2 = bb.z, a3 = bb.w;
#pragma unroll
        for (int k = 0; k < 64; k++) {
            float4 w = *(float4*)&sW[k * 64 + j0];
            float ev = ef[k];
            a0 += ev * w.x; a1 += ev * w.y; a2 += ev * w.z; a3 += ev * w.w;
        }
        float4 w2 = *(float4*)&sW2[j0];
        o += fmaxf(a0, 0.f) * w2.x + fmaxf(a1, 0.f) * w2.y +
             fmaxf(a2, 0.f) * w2.z + fmaxf(a3, 0.f) * w2.w;
    }
    out[p] = o;
}

// ---------------------------------------------------------------------------
extern "C" void kernel_launch(void* const* d_in, const int* in_sizes, int n_in,
                              void* d_out, int out_size) {
    const float* x     = (const float*)d_in[0];
    const int*   ei    = (const int*)d_in[1];
    const int*   et    = (const int*)d_in[2];
    const int*   pe    = (const int*)d_in[3];
    const float* W1    = (const float*)d_in[4];
    const float* root1 = (const float*)d_in[5];
    const float* b1    = (const float*)d_in[6];
    const float* W2    = (const float*)d_in[7];
    const float* root2 = (const float*)d_in[8];
    const float* b2    = (const float*)d_in[9];
    const float* Wd1   = (const float*)d_in[10];
    const float* bd1   = (const float*)d_in[11];
    const float* Wd2   = (const float*)d_in[12];
    const float* bd2   = (const float*)d_in[13];
    float* out = (float*)d_out;

    const int E = in_sizes[1] / 2;
    const int P = in_sizes[3] / 2;
    const int* src = ei;
    const int* dst = ei + E;
    const int* ps  = pe;
    const int* pd  = pe + P;

    // launch order puts gemm1 at index 3 (the slot ncu -s captures)
    zero_cnt_kernel<<<(NN * 3 + 255) / 256, 256>>>(NN * 3);
    wc1_kernel<<<(128 * 256 + 255) / 256, 256>>>(W1, root1);
    wc2_kernel<<<(64 * 128 + 255) / 256, 256>>>(W2, root2);
    {
        dim3 g(2, (NN + 127) / 128);
        gemm1_kernel<<<g, 256>>>(x, b1);
    }

    // counts + inverse means + CSR (shared by both layers)
    count_kernel<<<(E + 255) / 256, 256>>>(dst, et, E);
    inv_kernel<<<(NN * 3 + 255) / 256, 256>>>(NN * 3);
    scan1_kernel<<<SCAN_NB, SCAN_BS>>>();
    scan2_kernel<<<1, 512>>>();
    scan3_kernel<<<(NN + 255) / 256, 256>>>();
    scatter_kernel<<<(E + 255) / 256, 256>>>(src, dst, et, E);

    // layer 1 aggregation
    agg1_csr_kernel<<<(NN * 32 + 255) / 256, 256>>>();

    // layer 2 (relu folded into GEMM2 A-loads)
    {
        dim3 g(1, (NN + 127) / 128);
        gemm2_kernel<<<g, 256>>>(b2);
    }
    agg2_csr_kernel<<<(NN * 32 + 255) / 256, 256>>>();

    // decoder
    decoder_kernel<<<(P + 127) / 128, 128>>>(ps, pd, Wd1, bd1, Wd2, bd2, out, P);
}

// round 7
// speedup vs baseline: 1.5520x; 1.0905x over previous
#include <cuda_runtime.h>
#include <cuda_bf16.h>

// ---------------------------------------------------------------------------
// RGCN link predictor:
//   GEMM1 (x @ [W1|root1], fused -> H1/Z1, FFMA2 inner loop)
//   counts -> inv -> parallel 3-phase scan -> CSR scatter
//   CSR warp-per-node agg (no atomics) -> GEMM2 -> agg -> decoder MLP
// __device__ globals only referenced from device code (round-3 lesson).
// ---------------------------------------------------------------------------

#define NN    100000
#define REL   3
#define EMAX  1600000
#define SCAN_BS   256
#define SCAN_NB   ((NN + SCAN_BS - 1) / SCAN_BS)   // 391

// scratch (static device globals; no allocation allowed)
__device__ int      g_cnt[NN * REL];
__device__ float    g_inv[NN * REL];
__device__ int      g_off[NN + 1];
__device__ int      g_cur[NN];
__device__ int      g_bsum[SCAN_NB];
__device__ int      g_bpre[SCAN_NB];
__device__ unsigned g_epk[EMAX];     // src | (rel << 20), sorted by dst
__device__ float    g_H1[NN * 192];
__device__ float    g_Z1[NN * 64];
__device__ float    g_H2[NN * 96];
__device__ float    g_Z2[NN * 32];
__device__ float    g_Wc1[128 * 256];
__device__ float    g_Wc2[64 * 128];

// ---------------------------------------------------------------------------
__global__ void zero_cnt_kernel(int n) {
    int i = blockIdx.x * blockDim.x + threadIdx.x;
    if (i < n) g_cnt[i] = 0;
}

__global__ void count_kernel(const int* __restrict__ dst,
                             const int* __restrict__ et, int E) {
    int e = blockIdx.x * blockDim.x + threadIdx.x;
    if (e < E) atomicAdd(&g_cnt[dst[e] * 3 + et[e]], 1);
}

__global__ void inv_kernel(int n) {
    int i = blockIdx.x * blockDim.x + threadIdx.x;
    if (i < n) g_inv[i] = 1.0f / fmaxf((float)g_cnt[i], 1.0f);
}

// ---- parallel 3-phase exclusive scan of node degrees ----------------------
__global__ void __launch_bounds__(SCAN_BS) scan1_kernel() {
    __shared__ int s[SCAN_BS];
    int t = threadIdx.x;
    int i = blockIdx.x * SCAN_BS + t;
    int d = 0;
    if (i < NN) d = g_cnt[3 * i] + g_cnt[3 * i + 1] + g_cnt[3 * i + 2];
    s[t] = d;
    __syncthreads();
#pragma unroll
    for (int o = 1; o < SCAN_BS; o <<= 1) {
        int v = (t >= o) ? s[t - o] : 0;
        __syncthreads();
        s[t] += v;
        __syncthreads();
    }
    if (i < NN) g_off[i] = s[t] - d;
    if (t == SCAN_BS - 1) g_bsum[blockIdx.x] = s[t];
}

__global__ void __launch_bounds__(512) scan2_kernel() {
    __shared__ int s[512];
    int t = threadIdx.x;
    int v0 = (t < SCAN_NB) ? g_bsum[t] : 0;
    s[t] = v0;
    __syncthreads();
#pragma unroll
    for (int o = 1; o < 512; o <<= 1) {
        int v = (t >= o) ? s[t - o] : 0;
        __syncthreads();
        s[t] += v;
        __syncthreads();
    }
    if (t < SCAN_NB) g_bpre[t] = s[t] - v0;
    if (t == 511) g_off[NN] = s[511];
}

__global__ void scan3_kernel() {
    int i = blockIdx.x * blockDim.x + threadIdx.x;
    if (i < NN) {
        int off = g_off[i] + g_bpre[i / SCAN_BS];
        g_off[i] = off;
        g_cur[i] = off;
    }
}

__global__ void scatter_kernel(const int* __restrict__ src,
                               const int* __restrict__ dst,
                               const int* __restrict__ et, int E) {
    int e = blockIdx.x * blockDim.x + threadIdx.x;
    if (e < E) {
        int pos = atomicAdd(&g_cur[dst[e]], 1);
        g_epk[pos] = (unsigned)src[e] | ((unsigned)et[e] << 20);
    }
}

// pack [W1 r0|r1|r2 | root1] -> g_Wc1 [128,256]
__global__ void wc1_kernel(const float* __restrict__ W1,
                           const float* __restrict__ root1) {
    int i = blockIdx.x * blockDim.x + threadIdx.x;
    if (i < 128 * 256) {
        int k = i >> 8, c = i & 255;
        float v;
        if (c < 192) {
            int r = c >> 6, j = c & 63;
            v = W1[r * 128 * 64 + k * 64 + j];
        } else {
            v = root1[k * 64 + (c - 192)];
        }
        g_Wc1[i] = v;
    }
}

// pack [W2 r0|r1|r2 | root2] -> g_Wc2 [64,128]
__global__ void wc2_kernel(const float* __restrict__ W2,
                           const float* __restrict__ root2) {
    int i = blockIdx.x * blockDim.x + threadIdx.x;
    if (i < 64 * 128) {
        int k = i >> 7, c = i & 127;
        float v;
        if (c < 96) {
            int r = c >> 5, j = c & 31;
            v = W2[r * 64 * 32 + k * 32 + j];
        } else {
            v = root2[k * 32 + (c - 96)];
        }
        g_Wc2[i] = v;
    }
}

// ---------------------------------------------------------------------------
// 128x128 tile fp32 GEMM, BK=16, 256 threads, 8x8 microtile, double-buffered.
// Inner loop uses packed fma.rn.f32x2 (FFMA2): bit-exact fp32, half the
// fma-pipe issue. Accumulators are f32x2 pairs over the j dimension.
// Fused epilogue: cols [0,HCOLS) -> H, cols [HCOLS,NTOT) -> Z (+bias).
// ---------------------------------------------------------------------------
template <int NTOT, int K, int HCOLS, bool RELU>
__device__ __forceinline__ void gemm_fused_core(
    const float* __restrict__ A, const float* __restrict__ B,
    float* __restrict__ H, float* __restrict__ Z,
    const float* __restrict__ bias, int M) {

    __shared__ float As[2][16][128];
    __shared__ float Bs[2][16][128];

    const int tid = threadIdx.x;
    const int tx = tid & 15, ty = tid >> 4;
    const int m0 = blockIdx.y * 128, n0 = blockIdx.x * 128;

    float4 aReg[2], bReg[2];
    unsigned long long acc2[8][4] = {};   // f32x2 {0,0} == 0ull

    auto loadTiles = [&](int k0) {
#pragma unroll
        for (int i = 0; i < 2; i++) {
            int idx = tid + i * 256;
            int row = idx >> 2, c4 = idx & 3;
            int gr = m0 + row;
            float4 v = make_float4(0.f, 0.f, 0.f, 0.f);
            if (gr < M) v = *(const float4*)&A[(size_t)gr * K + k0 + c4 * 4];
            if (RELU) {
                v.x = fmaxf(v.x, 0.f); v.y = fmaxf(v.y, 0.f);
                v.z = fmaxf(v.z, 0.f); v.w = fmaxf(v.w, 0.f);
            }
            aReg[i] = v;
        }
#pragma unroll
        for (int i = 0; i < 2; i++) {
            int idx = tid + i * 256;
            int row = idx >> 5, c4 = idx & 31;
            bReg[i] = *(const float4*)&B[(size_t)(k0 + row) * NTOT + n0 + c4 * 4];
        }
    };
    auto storeTiles = [&](int buf) {
#pragma unroll
        for (int i = 0; i < 2; i++) {
            int idx = tid + i * 256;
            int row = idx >> 2, c4 = idx & 3;
            As[buf][c4 * 4 + 0][row] = aReg[i].x;
            As[buf][c4 * 4 + 1][row] = aReg[i].y;
            As[buf][c4 * 4 + 2][row] = aReg[i].z;
            As[buf][c4 * 4 + 3][row] = aReg[i].w;
        }
#pragma unroll
        for (int i = 0; i < 2; i++) {
            int idx = tid + i * 256;
            int row = idx >> 5, c4 = idx & 31;
            *(float4*)&Bs[buf][row][c4 * 4] = bReg[i];
        }
    };

    constexpr int KT = K / 16;
    loadTiles(0);
    storeTiles(0);
    __syncthreads();

    int buf = 0;
#pragma unroll
    for (int kt = 0; kt < KT; kt++) {
        if (kt + 1 < KT) loadTiles((kt + 1) * 16);

#pragma unroll
        for (int kk = 0; kk < 16; kk++) {
            float4 a0 = *(float4*)&As[buf][kk][ty * 8];
            float4 a1 = *(float4*)&As[buf][kk][ty * 8 + 4];
            // b pairs (j, j+1) straight out of smem as 64-bit values
            const unsigned long long* bp =
                (const unsigned long long*)&Bs[buf][kk][tx * 8];
            unsigned long long bb0 = bp[0], bb1 = bp[1],
                               bb2 = bp[2], bb3 = bp[3];
            float av[8] = {a0.x, a0.y, a0.z, a0.w, a1.x, a1.y, a1.z, a1.w};
#pragma unroll
            for (int i = 0; i < 8; i++) {
                unsigned long long pa;
                asm("mov.b64 %0, {%1, %1};"
                    : "=l"(pa) : "r"(__float_as_uint(av[i])));
                asm("fma.rn.f32x2 %0, %1, %2, %0;"
                    : "+l"(acc2[i][0]) : "l"(pa), "l"(bb0));
                asm("fma.rn.f32x2 %0, %1, %2, %0;"
                    : "+l"(acc2[i][1]) : "l"(pa), "l"(bb1));
                asm("fma.rn.f32x2 %0, %1, %2, %0;"
                    : "+l"(acc2[i][2]) : "l"(pa), "l"(bb2));
                asm("fma.rn.f32x2 %0, %1, %2, %0;"
                    : "+l"(acc2[i][3]) : "l"(pa), "l"(bb3));
            }
        }

        if (kt + 1 < KT) {
            buf ^= 1;
            storeTiles(buf);
            __syncthreads();
        }
    }

    // unpack accumulators
    float acc[8][8];
#pragma unroll
    for (int i = 0; i < 8; i++)
#pragma unroll
        for (int jp = 0; jp < 4; jp++) {
            unsigned lo, hi;
            asm("mov.b64 {%0, %1}, %2;" : "=r"(lo), "=r"(hi) : "l"(acc2[i][jp]));
            acc[i][jp * 2]     = __uint_as_float(lo);
            acc[i][jp * 2 + 1] = __uint_as_float(hi);
        }

    const int cb = n0 + tx * 8;
    constexpr int ZW = NTOT - HCOLS;
    if (cb < HCOLS) {
#pragma unroll
        for (int i = 0; i < 8; i++) {
            int gr = m0 + ty * 8 + i;
            if (gr < M) {
                *(float4*)&H[(size_t)gr * HCOLS + cb] =
                    make_float4(acc[i][0], acc[i][1], acc[i][2], acc[i][3]);
                *(float4*)&H[(size_t)gr * HCOLS + cb + 4] =
                    make_float4(acc[i][4], acc[i][5], acc[i][6], acc[i][7]);
            }
        }
    } else {
        int zc = cb - HCOLS;
        float4 bia0 = *(const float4*)&bias[zc];
        float4 bia1 = *(const float4*)&bias[zc + 4];
#pragma unroll
        for (int i = 0; i < 8; i++) {
            int gr = m0 + ty * 8 + i;
            if (gr < M) {
                *(float4*)&Z[(size_t)gr * ZW + zc] =
                    make_float4(acc[i][0] + bia0.x, acc[i][1] + bia0.y,
                                acc[i][2] + bia0.z, acc[i][3] + bia0.w);
                *(float4*)&Z[(size_t)gr * ZW + zc + 4] =
                    make_float4(acc[i][4] + bia1.x, acc[i][5] + bia1.y,
                                acc[i][6] + bia1.z, acc[i][7] + bia1.w);
            }
        }
    }
}

__global__ void __launch_bounds__(256) gemm1_kernel(const float* __restrict__ x,
                                                    const float* __restrict__ b1) {
    gemm_fused_core<256, 128, 192, false>(x, g_Wc1, g_H1, g_Z1, b1, NN);
}
__global__ void __launch_bounds__(256) gemm2_kernel(const float* __restrict__ b2) {
    gemm_fused_core<128, 64, 96, true>(g_Z1, g_Wc2, g_H2, g_Z2, b2, NN);
}

// ---------------------------------------------------------------------------
// CSR warp-per-node aggregation, NO atomics.
// ---------------------------------------------------------------------------
__global__ void __launch_bounds__(256) agg1_csr_kernel() {
    int d = (blockIdx.x * blockDim.x + threadIdx.x) >> 5;
    int lane = threadIdx.x & 31;
    if (d >= NN) return;
    int beg = g_off[d], end = g_off[d + 1];
    if (beg == end) return;
    float i0 = g_inv[3 * d], i1 = g_inv[3 * d + 1], i2 = g_inv[3 * d + 2];

    float2 acc = make_float2(0.f, 0.f);
    for (int i = beg; i < end; i++) {
        unsigned v = g_epk[i];
        int s = v & 0xFFFFF;
        int r = v >> 20;
        float sc = (r == 0) ? i0 : ((r == 1) ? i1 : i2);
        float2 h = *(const float2*)&g_H1[(size_t)s * 192 + r * 64 + lane * 2];
        acc.x += h.x * sc;
        acc.y += h.y * sc;
    }
    float2 z = *(float2*)&g_Z1[(size_t)d * 64 + lane * 2];
    z.x += acc.x; z.y += acc.y;
    *(float2*)&g_Z1[(size_t)d * 64 + lane * 2] = z;
}

__global__ void __launch_bounds__(256) agg2_csr_kernel() {
    int d = (blockIdx.x * blockDim.x + threadIdx.x) >> 5;
    int lane = threadIdx.x & 31;
    if (d >= NN) return;
    int beg = g_off[d], end = g_off[d + 1];
    if (beg == end) return;
    float i0 = g_inv[3 * d], i1 = g_inv[3 * d + 1], i2 = g_inv[3 * d + 2];

    float acc = 0.f;
    for (int i = beg; i < end; i++) {
        unsigned v = g_epk[i];
        int s = v & 0xFFFFF;
        int r = v >> 20;
        float sc = (r == 0) ? i0 : ((r == 1) ? i1 : i2);
        acc += g_H2[(size_t)s * 96 + r * 32 + lane] * sc;
    }
    g_Z2[(size_t)d * 32 + lane] += acc;
}

// ---------------------------------------------------------------------------
// decoder: out[p] = relu(concat(z2[s], z2[d]) @ Wd1 + bd1) @ Wd2 + bd2
// ---------------------------------------------------------------------------
__global__ void __launch_bounds__(128) decoder_kernel(
    const int* __restrict__ psrc, const int* __restrict__ pdst,
    const float* __restrict__ Wd1, const float* __restrict__ bd1,
    const float* __restrict__ Wd2, const float* __restrict__ bd2,
    float* __restrict__ out, int P) {
    __shared__ float sW[64 * 64];
    __shared__ float sB1[64];
    __shared__ float sW2[64];
    int tid = threadIdx.x;
    for (int i = tid; i < 64 * 64; i += 128) sW[i] = Wd1[i];
    if (tid < 64) { sB1[tid] = bd1[tid]; sW2[tid] = Wd2[tid]; }
    __syncthreads();

    int p = blockIdx.x * 128 + tid;
    if (p >= P) return;
    int s = psrc[p], d = pdst[p];

    float ef[64];
#pragma unroll
    for (int q = 0; q < 8; q++) {
        float4 v = *(const float4*)&g_Z2[(size_t)s * 32 + q * 4];
        ef[q * 4 + 0] = v.x; ef[q * 4 + 1] = v.y;
        ef[q * 4 + 2] = v.z; ef[q * 4 + 3] = v.w;
    }
#pragma unroll
    for (int q = 0; q < 8; q++) {
        float4 v = *(const float4*)&g_Z2[(size_t)d * 32 + q * 4];
        ef[32 + q * 4 + 0] = v.x; ef[32 + q * 4 + 1] = v.y;
        ef[32 + q * 4 + 2] = v.z; ef[32 + q * 4 + 3] = v.w;
    }

    float o = bd2[0];
    for (int j0 = 0; j0 < 64; j0 += 4) {
        float4 bb = *(float4*)&sB1[j0];
        float a0 = bb.x, a1 = bb.y, a2 = bb.z, a3 = bb.w;
#pragma unroll
        for (int k = 0; k < 64; k++) {
            float4 w = *(float4*)&sW[k * 64 + j0];
            float ev = ef[k];
            a0 += ev * w.x; a1 += ev * w.y; a2 += ev * w.z; a3 += ev * w.w;
        }
        float4 w2 = *(float4*)&sW2[j0];
        o += fmaxf(a0, 0.f) * w2.x + fmaxf(a1, 0.f) * w2.y +
             fmaxf(a2, 0.f) * w2.z + fmaxf(a3, 0.f) * w2.w;
    }
    out[p] = o;
}

// ---------------------------------------------------------------------------
extern "C" void kernel_launch(void* const* d_in, const int* in_sizes, int n_in,
                              void* d_out, int out_size) {
    const float* x     = (const float*)d_in[0];
    const int*   ei    = (const int*)d_in[1];
    const int*   et    = (const int*)d_in[2];
    const int*   pe    = (const int*)d_in[3];
    const float* W1    = (const float*)d_in[4];
    const float* root1 = (const float*)d_in[5];
    const float* b1    = (const float*)d_in[6];
    const float* W2    = (const float*)d_in[7];
    const float* root2 = (const float*)d_in[8];
    const float* b2    = (const float*)d_in[9];
    const float* Wd1   = (const float*)d_in[10];
    const float* bd1   = (const float*)d_in[11];
    const float* Wd2   = (const float*)d_in[12];
    const float* bd2   = (const float*)d_in[13];
    float* out = (float*)d_out;

    const int E = in_sizes[1] / 2;
    const int P = in_sizes[3] / 2;
    const int* src = ei;
    const int* dst = ei + E;
    const int* ps  = pe;
    const int* pd  = pe + P;

    zero_cnt_kernel<<<(NN * 3 + 255) / 256, 256>>>(NN * 3);
    wc1_kernel<<<(128 * 256 + 255) / 256, 256>>>(W1, root1);
    wc2_kernel<<<(64 * 128 + 255) / 256, 256>>>(W2, root2);
    {
        dim3 g(2, (NN + 127) / 128);
        gemm1_kernel<<<g, 256>>>(x, b1);
    }

    // counts + inverse means + CSR (shared by both layers)
    count_kernel<<<(E + 255) / 256, 256>>>(dst, et, E);
    inv_kernel<<<(NN * 3 + 255) / 256, 256>>>(NN * 3);
    scan1_kernel<<<SCAN_NB, SCAN_BS>>>();
    scan2_kernel<<<1, 512>>>();
    scan3_kernel<<<(NN + 255) / 256, 256>>>();
    scatter_kernel<<<(E + 255) / 256, 256>>>(src, dst, et, E);

    // layer 1 aggregation
    agg1_csr_kernel<<<(NN * 32 + 255) / 256, 256>>>();

    // layer 2 (relu folded into GEMM2 A-loads)
    {
        dim3 g(1, (NN + 127) / 128);
        gemm2_kernel<<<g, 256>>>(b2);
    }
    agg2_csr_kernel<<<(NN * 32 + 255) / 256, 256>>>();

    // decoder
    decoder_kernel<<<(P + 127) / 128, 128>>>(ps, pd, Wd1, bd1, Wd2, bd2, out, P);
}

// round 8
// speedup vs baseline: 1.6329x; 1.0521x over previous
#include <cuda_runtime.h>
#include <cuda_bf16.h>

// ---------------------------------------------------------------------------
// RGCN link predictor:
//   GEMM1 (x @ [W1|root1], fused -> H1/Z1, FFMA2 + cp.async B, 2 CTA/SM)
//   counts -> inv -> parallel 3-phase scan -> CSR scatter
//   CSR warp-per-node agg (no atomics) -> GEMM2 -> agg -> decoder MLP
// __device__ globals only referenced from device code (round-3 lesson).
// ---------------------------------------------------------------------------

#define NN    100000
#define REL   3
#define EMAX  1600000
#define SCAN_BS   256
#define SCAN_NB   ((NN + SCAN_BS - 1) / SCAN_BS)   // 391

// scratch (static device globals; no allocation allowed)
__device__ int      g_cnt[NN * REL];
__device__ float    g_inv[NN * REL];
__device__ int      g_off[NN + 1];
__device__ int      g_cur[NN];
__device__ int      g_bsum[SCAN_NB];
__device__ int      g_bpre[SCAN_NB];
__device__ unsigned g_epk[EMAX];     // src | (rel << 20), sorted by dst
__device__ float    g_H1[NN * 192];
__device__ float    g_Z1[NN * 64];
__device__ float    g_H2[NN * 96];
__device__ float    g_Z2[NN * 32];
__device__ float    g_Wc1[128 * 256];
__device__ float    g_Wc2[64 * 128];

// ---------------------------------------------------------------------------
__global__ void zero_cnt_kernel(int n) {
    int i = blockIdx.x * blockDim.x + threadIdx.x;
    if (i < n) g_cnt[i] = 0;
}

__global__ void count_kernel(const int* __restrict__ dst,
                             const int* __restrict__ et, int E) {
    int e = blockIdx.x * blockDim.x + threadIdx.x;
    if (e < E) atomicAdd(&g_cnt[dst[e] * 3 + et[e]], 1);
}

__global__ void inv_kernel(int n) {
    int i = blockIdx.x * blockDim.x + threadIdx.x;
    if (i < n) g_inv[i] = 1.0f / fmaxf((float)g_cnt[i], 1.0f);
}

// ---- parallel 3-phase exclusive scan of node degrees ----------------------
__global__ void __launch_bounds__(SCAN_BS) scan1_kernel() {
    __shared__ int s[SCAN_BS];
    int t = threadIdx.x;
    int i = blockIdx.x * SCAN_BS + t;
    int d = 0;
    if (i < NN) d = g_cnt[3 * i] + g_cnt[3 * i + 1] + g_cnt[3 * i + 2];
    s[t] = d;
    __syncthreads();
#pragma unroll
    for (int o = 1; o < SCAN_BS; o <<= 1) {
        int v = (t >= o) ? s[t - o] : 0;
        __syncthreads();
        s[t] += v;
        __syncthreads();
    }
    if (i < NN) g_off[i] = s[t] - d;
    if (t == SCAN_BS - 1) g_bsum[blockIdx.x] = s[t];
}

__global__ void __launch_bounds__(512) scan2_kernel() {
    __shared__ int s[512];
    int t = threadIdx.x;
    int v0 = (t < SCAN_NB) ? g_bsum[t] : 0;
    s[t] = v0;
    __syncthreads();
#pragma unroll
    for (int o = 1; o < 512; o <<= 1) {
        int v = (t >= o) ? s[t - o] : 0;
        __syncthreads();
        s[t] += v;
        __syncthreads();
    }
    if (t < SCAN_NB) g_bpre[t] = s[t] - v0;
    if (t == 511) g_off[NN] = s[511];
}

__global__ void scan3_kernel() {
    int i = blockIdx.x * blockDim.x + threadIdx.x;
    if (i < NN) {
        int off = g_off[i] + g_bpre[i / SCAN_BS];
        g_off[i] = off;
        g_cur[i] = off;
    }
}

__global__ void scatter_kernel(const int* __restrict__ src,
                               const int* __restrict__ dst,
                               const int* __restrict__ et, int E) {
    int e = blockIdx.x * blockDim.x + threadIdx.x;
    if (e < E) {
        int pos = atomicAdd(&g_cur[dst[e]], 1);
        g_epk[pos] = (unsigned)src[e] | ((unsigned)et[e] << 20);
    }
}

// pack [W1 r0|r1|r2 | root1] -> g_Wc1 [128,256]
__global__ void wc1_kernel(const float* __restrict__ W1,
                           const float* __restrict__ root1) {
    int i = blockIdx.x * blockDim.x + threadIdx.x;
    if (i < 128 * 256) {
        int k = i >> 8, c = i & 255;
        float v;
        if (c < 192) {
            int r = c >> 6, j = c & 63;
            v = W1[r * 128 * 64 + k * 64 + j];
        } else {
            v = root1[k * 64 + (c - 192)];
        }
        g_Wc1[i] = v;
    }
}

// pack [W2 r0|r1|r2 | root2] -> g_Wc2 [64,128]
__global__ void wc2_kernel(const float* __restrict__ W2,
                           const float* __restrict__ root2) {
    int i = blockIdx.x * blockDim.x + threadIdx.x;
    if (i < 64 * 128) {
        int k = i >> 7, c = i & 127;
        float v;
        if (c < 96) {
            int r = c >> 5, j = c & 31;
            v = W2[r * 64 * 32 + k * 32 + j];
        } else {
            v = root2[k * 32 + (c - 96)];
        }
        g_Wc2[i] = v;
    }
}

// ---------------------------------------------------------------------------
// cp.async helpers
// ---------------------------------------------------------------------------
__device__ __forceinline__ void cp_async16(void* smem_dst, const void* gmem_src) {
    unsigned saddr = (unsigned)__cvta_generic_to_shared(smem_dst);
    asm volatile("cp.async.cg.shared.global [%0], [%1], 16;\n"
                 :: "r"(saddr), "l"(gmem_src) : "memory");
}
__device__ __forceinline__ void cp_async_commit() {
    asm volatile("cp.async.commit_group;\n" ::: "memory");
}
__device__ __forceinline__ void cp_async_wait0() {
    asm volatile("cp.async.wait_group 0;\n" ::: "memory");
}

// ---------------------------------------------------------------------------
// 128x128 tile fp32 GEMM, BK=16, 256 threads, 8x8 microtile, double-buffered.
// A staged through regs (transpose store), B via cp.async direct to smem.
// Inner loop: packed fma.rn.f32x2 (bit-exact fp32, half fma issue).
// Fused epilogue: cols [0,HCOLS) -> H, cols [HCOLS,NTOT) -> Z (+bias).
// ---------------------------------------------------------------------------
template <int NTOT, int K, int HCOLS, bool RELU>
__device__ __forceinline__ void gemm_fused_core(
    const float* __restrict__ A, const float* __restrict__ B,
    float* __restrict__ H, float* __restrict__ Z,
    const float* __restrict__ bias, int M) {

    __shared__ float As[2][16][128];
    __shared__ float Bs[2][16][128];

    const int tid = threadIdx.x;
    const int tx = tid & 15, ty = tid >> 4;
    const int m0 = blockIdx.y * 128, n0 = blockIdx.x * 128;

    float4 aReg[2];
    unsigned long long acc2[8][4] = {};   // f32x2 {0,0} == 0ull

    auto loadA = [&](int k0) {
#pragma unroll
        for (int i = 0; i < 2; i++) {
            int idx = tid + i * 256;
            int row = idx >> 2, c4 = idx & 3;
            int gr = m0 + row;
            float4 v = make_float4(0.f, 0.f, 0.f, 0.f);
            if (gr < M) v = *(const float4*)&A[(size_t)gr * K + k0 + c4 * 4];
            if (RELU) {
                v.x = fmaxf(v.x, 0.f); v.y = fmaxf(v.y, 0.f);
                v.z = fmaxf(v.z, 0.f); v.w = fmaxf(v.w, 0.f);
            }
            aReg[i] = v;
        }
    };
    auto storeA = [&](int buf) {
#pragma unroll
        for (int i = 0; i < 2; i++) {
            int idx = tid + i * 256;
            int row = idx >> 2, c4 = idx & 3;
            As[buf][c4 * 4 + 0][row] = aReg[i].x;
            As[buf][c4 * 4 + 1][row] = aReg[i].y;
            As[buf][c4 * 4 + 2][row] = aReg[i].z;
            As[buf][c4 * 4 + 3][row] = aReg[i].w;
        }
    };
    auto issueB = [&](int k0, int buf) {
#pragma unroll
        for (int i = 0; i < 2; i++) {
            int idx = tid + i * 256;
            int row = idx >> 5, c4 = idx & 31;
            cp_async16(&Bs[buf][row][c4 * 4],
                       &B[(size_t)(k0 + row) * NTOT + n0 + c4 * 4]);
        }
        cp_async_commit();
    };

    constexpr int KT = K / 16;
    loadA(0);
    issueB(0, 0);
    storeA(0);
    cp_async_wait0();
    __syncthreads();

    int buf = 0;
#pragma unroll
    for (int kt = 0; kt < KT; kt++) {
        if (kt + 1 < KT) {
            loadA((kt + 1) * 16);
            issueB((kt + 1) * 16, buf ^ 1);
        }

#pragma unroll
        for (int kk = 0; kk < 16; kk++) {
            float4 a0 = *(float4*)&As[buf][kk][ty * 8];
            float4 a1 = *(float4*)&As[buf][kk][ty * 8 + 4];
            float4 b0 = *(float4*)&Bs[buf][kk][tx * 8];
            float4 b1 = *(float4*)&Bs[buf][kk][tx * 8 + 4];
            unsigned long long bb0, bb1, bb2, bb3;
            asm("mov.b64 %0, {%1, %2};" : "=l"(bb0)
                : "r"(__float_as_uint(b0.x)), "r"(__float_as_uint(b0.y)));
            asm("mov.b64 %0, {%1, %2};" : "=l"(bb1)
                : "r"(__float_as_uint(b0.z)), "r"(__float_as_uint(b0.w)));
            asm("mov.b64 %0, {%1, %2};" : "=l"(bb2)
                : "r"(__float_as_uint(b1.x)), "r"(__float_as_uint(b1.y)));
            asm("mov.b64 %0, {%1, %2};" : "=l"(bb3)
                : "r"(__float_as_uint(b1.z)), "r"(__float_as_uint(b1.w)));
            float av[8] = {a0.x, a0.y, a0.z, a0.w, a1.x, a1.y, a1.z, a1.w};
#pragma unroll
            for (int i = 0; i < 8; i++) {
                unsigned long long pa;
                asm("mov.b64 %0, {%1, %1};"
                    : "=l"(pa) : "r"(__float_as_uint(av[i])));
                asm("fma.rn.f32x2 %0, %1, %2, %0;"
                    : "+l"(acc2[i][0]) : "l"(pa), "l"(bb0));
                asm("fma.rn.f32x2 %0, %1, %2, %0;"
                    : "+l"(acc2[i][1]) : "l"(pa), "l"(bb1));
                asm("fma.rn.f32x2 %0, %1, %2, %0;"
                    : "+l"(acc2[i][2]) : "l"(pa), "l"(bb2));
                asm("fma.rn.f32x2 %0, %1, %2, %0;"
                    : "+l"(acc2[i][3]) : "l"(pa), "l"(bb3));
            }
        }

        if (kt + 1 < KT) {
            storeA(buf ^ 1);         // other buffer: no hazard with compute(buf)
            cp_async_wait0();
            __syncthreads();
            buf ^= 1;
        }
    }

    // unpack accumulators
    float acc[8][8];
#pragma unroll
    for (int i = 0; i < 8; i++)
#pragma unroll
        for (int jp = 0; jp < 4; jp++) {
            unsigned lo, hi;
            asm("mov.b64 {%0, %1}, %2;" : "=r"(lo), "=r"(hi) : "l"(acc2[i][jp]));
            acc[i][jp * 2]     = __uint_as_float(lo);
            acc[i][jp * 2 + 1] = __uint_as_float(hi);
        }

    const int cb = n0 + tx * 8;
    constexpr int ZW = NTOT - HCOLS;
    if (cb < HCOLS) {
#pragma unroll
        for (int i = 0; i < 8; i++) {
            int gr = m0 + ty * 8 + i;
            if (gr < M) {
                *(float4*)&H[(size_t)gr * HCOLS + cb] =
                    make_float4(acc[i][0], acc[i][1], acc[i][2], acc[i][3]);
                *(float4*)&H[(size_t)gr * HCOLS + cb + 4] =
                    make_float4(acc[i][4], acc[i][5], acc[i][6], acc[i][7]);
            }
        }
    } else {
        int zc = cb - HCOLS;
        float4 bia0 = *(const float4*)&bias[zc];
        float4 bia1 = *(const float4*)&bias[zc + 4];
#pragma unroll
        for (int i = 0; i < 8; i++) {
            int gr = m0 + ty * 8 + i;
            if (gr < M) {
                *(float4*)&Z[(size_t)gr * ZW + zc] =
                    make_float4(acc[i][0] + bia0.x, acc[i][1] + bia0.y,
                                acc[i][2] + bia0.z, acc[i][3] + bia0.w);
                *(float4*)&Z[(size_t)gr * ZW + zc + 4] =
                    make_float4(acc[i][4] + bia1.x, acc[i][5] + bia1.y,
                                acc[i][6] + bia1.z, acc[i][7] + bia1.w);
            }
        }
    }
}

__global__ void __launch_bounds__(256, 2) gemm1_kernel(const float* __restrict__ x,
                                                       const float* __restrict__ b1) {
    gemm_fused_core<256, 128, 192, false>(x, g_Wc1, g_H1, g_Z1, b1, NN);
}
__global__ void __launch_bounds__(256, 2) gemm2_kernel(const float* __restrict__ b2) {
    gemm_fused_core<128, 64, 96, true>(g_Z1, g_Wc2, g_H2, g_Z2, b2, NN);
}

// ---------------------------------------------------------------------------
// CSR warp-per-node aggregation, NO atomics.
// ---------------------------------------------------------------------------
__global__ void __launch_bounds__(256) agg1_csr_kernel() {
    int d = (blockIdx.x * blockDim.x + threadIdx.x) >> 5;
    int lane = threadIdx.x & 31;
    if (d >= NN) return;
    int beg = g_off[d], end = g_off[d + 1];
    if (beg == end) return;
    float i0 = g_inv[3 * d], i1 = g_inv[3 * d + 1], i2 = g_inv[3 * d + 2];

    float2 acc = make_float2(0.f, 0.f);
    for (int i = beg; i < end; i++) {
        unsigned v = g_epk[i];
        int s = v & 0xFFFFF;
        int r = v >> 20;
        float sc = (r == 0) ? i0 : ((r == 1) ? i1 : i2);
        float2 h = *(const float2*)&g_H1[(size_t)s * 192 + r * 64 + lane * 2];
        acc.x += h.x * sc;
        acc.y += h.y * sc;
    }
    float2 z = *(float2*)&g_Z1[(size_t)d * 64 + lane * 2];
    z.x += acc.x; z.y += acc.y;
    *(float2*)&g_Z1[(size_t)d * 64 + lane * 2] = z;
}

__global__ void __launch_bounds__(256) agg2_csr_kernel() {
    int d = (blockIdx.x * blockDim.x + threadIdx.x) >> 5;
    int lane = threadIdx.x & 31;
    if (d >= NN) return;
    int beg = g_off[d], end = g_off[d + 1];
    if (beg == end) return;
    float i0 = g_inv[3 * d], i1 = g_inv[3 * d + 1], i2 = g_inv[3 * d + 2];

    float acc = 0.f;
    for (int i = beg; i < end; i++) {
        unsigned v = g_epk[i];
        int s = v & 0xFFFFF;
        int r = v >> 20;
        float sc = (r == 0) ? i0 : ((r == 1) ? i1 : i2);
        acc += g_H2[(size_t)s * 96 + r * 32 + lane] * sc;
    }
    g_Z2[(size_t)d * 32 + lane] += acc;
}

// ---------------------------------------------------------------------------
// decoder: out[p] = relu(concat(z2[s], z2[d]) @ Wd1 + bd1) @ Wd2 + bd2
// ---------------------------------------------------------------------------
__global__ void __launch_bounds__(128) decoder_kernel(
    const int* __restrict__ psrc, const int* __restrict__ pdst,
    const float* __restrict__ Wd1, const float* __restrict__ bd1,
    const float* __restrict__ Wd2, const float* __restrict__ bd2,
    float* __restrict__ out, int P) {
    __shared__ float sW[64 * 64];
    __shared__ float sB1[64];
    __shared__ float sW2[64];
    int tid = threadIdx.x;
    for (int i = tid; i < 64 * 64; i += 128) sW[i] = Wd1[i];
    if (tid < 64) { sB1[tid] = bd1[tid]; sW2[tid] = Wd2[tid]; }
    __syncthreads();

    int p = blockIdx.x * 128 + tid;
    if (p >= P) return;
    int s = psrc[p], d = pdst[p];

    float ef[64];
#pragma unroll
    for (int q = 0; q < 8; q++) {
        float4 v = *(const float4*)&g_Z2[(size_t)s * 32 + q * 4];
        ef[q * 4 + 0] = v.x; ef[q * 4 + 1] = v.y;
        ef[q * 4 + 2] = v.z; ef[q * 4 + 3] = v.w;
    }
#pragma unroll
    for (int q = 0; q < 8; q++) {
        float4 v = *(const float4*)&g_Z2[(size_t)d * 32 + q * 4];
        ef[32 + q * 4 + 0] = v.x; ef[32 + q * 4 + 1] = v.y;
        ef[32 + q * 4 + 2] = v.z; ef[32 + q * 4 + 3] = v.w;
    }

    float o = bd2[0];
    for (int j0 = 0; j0 < 64; j0 += 4) {
        float4 bb = *(float4*)&sB1[j0];
        float a0 = bb.x, a1 = bb.y, a2 = bb.z, a3 = bb.w;
#pragma unroll
        for (int k = 0; k < 64; k++) {
            float4 w = *(float4*)&sW[k * 64 + j0];
            float ev = ef[k];
            a0 += ev * w.x; a1 += ev * w.y; a2 += ev * w.z; a3 += ev * w.w;
        }
        float4 w2 = *(float4*)&sW2[j0];
        o += fmaxf(a0, 0.f) * w2.x + fmaxf(a1, 0.f) * w2.y +
             fmaxf(a2, 0.f) * w2.z + fmaxf(a3, 0.f) * w2.w;
    }
    out[p] = o;
}

// ---------------------------------------------------------------------------
extern "C" void kernel_launch(void* const* d_in, const int* in_sizes, int n_in,
                              void* d_out, int out_size) {
    const float* x     = (const float*)d_in[0];
    const int*   ei    = (const int*)d_in[1];
    const int*   et    = (const int*)d_in[2];
    const int*   pe    = (const int*)d_in[3];
    const float* W1    = (const float*)d_in[4];
    const float* root1 = (const float*)d_in[5];
    const float* b1    = (const float*)d_in[6];
    const float* W2    = (const float*)d_in[7];
    const float* root2 = (const float*)d_in[8];
    const float* b2    = (const float*)d_in[9];
    const float* Wd1   = (const float*)d_in[10];
    const float* bd1   = (const float*)d_in[11];
    const float* Wd2   = (const float*)d_in[12];
    const float* bd2   = (const float*)d_in[13];
    float* out = (float*)d_out;

    const int E = in_sizes[1] / 2;
    const int P = in_sizes[3] / 2;
    const int* src = ei;
    const int* dst = ei + E;
    const int* ps  = pe;
    const int* pd  = pe + P;

    zero_cnt_kernel<<<(NN * 3 + 255) / 256, 256>>>(NN * 3);
    wc1_kernel<<<(128 * 256 + 255) / 256, 256>>>(W1, root1);
    wc2_kernel<<<(64 * 128 + 255) / 256, 256>>>(W2, root2);
    {
        dim3 g(2, (NN + 127) / 128);
        gemm1_kernel<<<g, 256>>>(x, b1);
    }

    // counts + inverse means + CSR (shared by both layers)
    count_kernel<<<(E + 255) / 256, 256>>>(dst, et, E);
    inv_kernel<<<(NN * 3 + 255) / 256, 256>>>(NN * 3);
    scan1_kernel<<<SCAN_NB, SCAN_BS>>>();
    scan2_kernel<<<1, 512>>>();
    scan3_kernel<<<(NN + 255) / 256, 256>>>();
    scatter_kernel<<<(E + 255) / 256, 256>>>(src, dst, et, E);

    // layer 1 aggregation
    agg1_csr_kernel<<<(NN * 32 + 255) / 256, 256>>>();

    // layer 2 (relu folded into GEMM2 A-loads)
    {
        dim3 g(1, (NN + 127) / 128);
        gemm2_kernel<<<g, 256>>>(b2);
    }
    agg2_csr_kernel<<<(NN * 32 + 255) / 256, 256>>>();

    // decoder
    decoder_kernel<<<(P + 127) / 128, 128>>>(ps, pd, Wd1, bd1, Wd2, bd2, out, P);
}

// round 9
// speedup vs baseline: 1.7206x; 1.0537x over previous
#include <cuda_runtime.h>
#include <cuda_bf16.h>

// ---------------------------------------------------------------------------
// RGCN link predictor:
//   GEMM1 (x @ [W1|root1], fused -> H1/Z1, FFMA2 + cp.async B, 2 CTA/SM)
//   counts -> inv -> parallel scan -> CSR scatter
//   CSR warp-per-node agg (no atomics, unroll-2) -> GEMM2 -> agg
//   decoder decomposed: UV = Z2 @ [Wd1_top|Wd1_bot] (per-node GEMM), then
//   per-edge: out = relu(U[s]+V[d]+bd1) . Wd2 + bd2
// __device__ globals only referenced from device code (round-3 lesson).
// ---------------------------------------------------------------------------

#define NN    100000
#define REL   3
#define EMAX  1600000
#define SCAN_BS   256
#define SCAN_NB   ((NN + SCAN_BS - 1) / SCAN_BS)   // 391

// scratch (static device globals; no allocation allowed)
__device__ int      g_cnt[NN * REL];
__device__ float    g_inv[NN * REL];
__device__ int      g_off[NN + 1];
__device__ int      g_cur[NN];
__device__ int      g_bsum[SCAN_NB];
__device__ int      g_bpre[SCAN_NB];
__device__ unsigned g_epk[EMAX];     // src | (rel << 20), sorted by dst
__device__ float    g_H1[NN * 192];
__device__ float    g_Z1[NN * 64];
__device__ float    g_H2[NN * 96];
__device__ float    g_Z2[NN * 32];
__device__ float    g_UV[NN * 128];  // cols 0-63: U = Z2 @ Wd1_top, 64-127: V
__device__ float    g_Wc1[128 * 256];
__device__ float    g_Wc2[64 * 128];
__device__ float    g_Wd1c[32 * 128];

// ---------------------------------------------------------------------------
__global__ void zero_cnt_kernel(int n) {
    int i = blockIdx.x * blockDim.x + threadIdx.x;
    if (i < n) g_cnt[i] = 0;
}

__global__ void count_kernel(const int* __restrict__ dst,
                             const int* __restrict__ et, int E) {
    int e = blockIdx.x * blockDim.x + threadIdx.x;
    if (e < E) atomicAdd(&g_cnt[dst[e] * 3 + et[e]], 1);
}

__global__ void inv_kernel(int n) {
    int i = blockIdx.x * blockDim.x + threadIdx.x;
    if (i < n) g_inv[i] = 1.0f / fmaxf((float)g_cnt[i], 1.0f);
}

// ---- parallel 3-phase exclusive scan of node degrees ----------------------
__global__ void __launch_bounds__(SCAN_BS) scan1_kernel() {
    __shared__ int s[SCAN_BS];
    int t = threadIdx.x;
    int i = blockIdx.x * SCAN_BS + t;
    int d = 0;
    if (i < NN) d = g_cnt[3 * i] + g_cnt[3 * i + 1] + g_cnt[3 * i + 2];
    s[t] = d;
    __syncthreads();
#pragma unroll
    for (int o = 1; o < SCAN_BS; o <<= 1) {
        int v = (t >= o) ? s[t - o] : 0;
        __syncthreads();
        s[t] += v;
        __syncthreads();
    }
    if (i < NN) g_off[i] = s[t] - d;
    if (t == SCAN_BS - 1) g_bsum[blockIdx.x] = s[t];
}

__global__ void __launch_bounds__(512) scan2_kernel() {
    __shared__ int s[512];
    int t = threadIdx.x;
    int v0 = (t < SCAN_NB) ? g_bsum[t] : 0;
    s[t] = v0;
    __syncthreads();
#pragma unroll
    for (int o = 1; o < 512; o <<= 1) {
        int v = (t >= o) ? s[t - o] : 0;
        __syncthreads();
        s[t] += v;
        __syncthreads();
    }
    if (t < SCAN_NB) g_bpre[t] = s[t] - v0;
    if (t == 511) g_off[NN] = s[511];
}

__global__ void scan3_kernel() {
    int i = blockIdx.x * blockDim.x + threadIdx.x;
    if (i < NN) {
        int off = g_off[i] + g_bpre[i / SCAN_BS];
        g_off[i] = off;
        g_cur[i] = off;
    }
}

__global__ void scatter_kernel(const int* __restrict__ src,
                               const int* __restrict__ dst,
                               const int* __restrict__ et, int E) {
    int e = blockIdx.x * blockDim.x + threadIdx.x;
    if (e < E) {
        int pos = atomicAdd(&g_cur[dst[e]], 1);
        g_epk[pos] = (unsigned)src[e] | ((unsigned)et[e] << 20);
    }
}

// pack [W1 r0|r1|r2 | root1] -> g_Wc1 [128,256]
__global__ void wc1_kernel(const float* __restrict__ W1,
                           const float* __restrict__ root1) {
    int i = blockIdx.x * blockDim.x + threadIdx.x;
    if (i < 128 * 256) {
        int k = i >> 8, c = i & 255;
        float v;
        if (c < 192) {
            int r = c >> 6, j = c & 63;
            v = W1[r * 128 * 64 + k * 64 + j];
        } else {
            v = root1[k * 64 + (c - 192)];
        }
        g_Wc1[i] = v;
    }
}

// pack [W2 r0|r1|r2 | root2] -> g_Wc2 [64,128]
__global__ void wc2_kernel(const float* __restrict__ W2,
                           const float* __restrict__ root2) {
    int i = blockIdx.x * blockDim.x + threadIdx.x;
    if (i < 64 * 128) {
        int k = i >> 7, c = i & 127;
        float v;
        if (c < 96) {
            int r = c >> 5, j = c & 31;
            v = W2[r * 64 * 32 + k * 32 + j];
        } else {
            v = root2[k * 32 + (c - 96)];
        }
        g_Wc2[i] = v;
    }
}

// pack Wd1 [64,64] -> g_Wd1c [32,128]: row k, col c<64 -> Wd1[k][c] (top),
// c>=64 -> Wd1[32+k][c-64] (bottom)
__global__ void wd1c_kernel(const float* __restrict__ Wd1) {
    int i = blockIdx.x * blockDim.x + threadIdx.x;
    if (i < 32 * 128) {
        int k = i >> 7, c = i & 127;
        g_Wd1c[i] = (c < 64) ? Wd1[k * 64 + c] : Wd1[(32 + k) * 64 + (c - 64)];
    }
}

// ---------------------------------------------------------------------------
// cp.async helpers
// ---------------------------------------------------------------------------
__device__ __forceinline__ void cp_async16(void* smem_dst, const void* gmem_src) {
    unsigned saddr = (unsigned)__cvta_generic_to_shared(smem_dst);
    asm volatile("cp.async.cg.shared.global [%0], [%1], 16;\n"
                 :: "r"(saddr), "l"(gmem_src) : "memory");
}
__device__ __forceinline__ void cp_async_commit() {
    asm volatile("cp.async.commit_group;\n" ::: "memory");
}
__device__ __forceinline__ void cp_async_wait0() {
    asm volatile("cp.async.wait_group 0;\n" ::: "memory");
}

// ---------------------------------------------------------------------------
// 128x128 tile fp32 GEMM, BK=16, 256 threads, 8x8 microtile, double-buffered.
// A staged through regs (transpose store), B via cp.async direct to smem.
// Inner loop: packed fma.rn.f32x2 (bit-exact fp32, half fma issue).
// Fused epilogue: cols [0,HCOLS) -> H, cols [HCOLS,NTOT) -> Z (+bias).
// ---------------------------------------------------------------------------
template <int NTOT, int K, int HCOLS, bool RELU>
__device__ __forceinline__ void gemm_fused_core(
    const float* __restrict__ A, const float* __restrict__ B,
    float* __restrict__ H, float* __restrict__ Z,
    const float* __restrict__ bias, int M) {

    __shared__ float As[2][16][128];
    __shared__ float Bs[2][16][128];

    const int tid = threadIdx.x;
    const int tx = tid & 15, ty = tid >> 4;
    const int m0 = blockIdx.y * 128, n0 = blockIdx.x * 128;

    float4 aReg[2];
    unsigned long long acc2[8][4] = {};   // f32x2 {0,0} == 0ull

    auto loadA = [&](int k0) {
#pragma unroll
        for (int i = 0; i < 2; i++) {
            int idx = tid + i * 256;
            int row = idx >> 2, c4 = idx & 3;
            int gr = m0 + row;
            float4 v = make_float4(0.f, 0.f, 0.f, 0.f);
            if (gr < M) v = *(const float4*)&A[(size_t)gr * K + k0 + c4 * 4];
            if (RELU) {
                v.x = fmaxf(v.x, 0.f); v.y = fmaxf(v.y, 0.f);
                v.z = fmaxf(v.z, 0.f); v.w = fmaxf(v.w, 0.f);
            }
            aReg[i] = v;
        }
    };
    auto storeA = [&](int buf) {
#pragma unroll
        for (int i = 0; i < 2; i++) {
            int idx = tid + i * 256;
            int row = idx >> 2, c4 = idx & 3;
            As[buf][c4 * 4 + 0][row] = aReg[i].x;
            As[buf][c4 * 4 + 1][row] = aReg[i].y;
            As[buf][c4 * 4 + 2][row] = aReg[i].z;
            As[buf][c4 * 4 + 3][row] = aReg[i].w;
        }
    };
    auto issueB = [&](int k0, int buf) {
#pragma unroll
        for (int i = 0; i < 2; i++) {
            int idx = tid + i * 256;
            int row = idx >> 5, c4 = idx & 31;
            cp_async16(&Bs[buf][row][c4 * 4],
                       &B[(size_t)(k0 + row) * NTOT + n0 + c4 * 4]);
        }
        cp_async_commit();
    };

    constexpr int KT = K / 16;
    loadA(0);
    issueB(0, 0);
    storeA(0);
    cp_async_wait0();
    __syncthreads();

    int buf = 0;
#pragma unroll
    for (int kt = 0; kt < KT; kt++) {
        if (kt + 1 < KT) {
            loadA((kt + 1) * 16);
            issueB((kt + 1) * 16, buf ^ 1);
        }

#pragma unroll
        for (int kk = 0; kk < 16; kk++) {
            float4 a0 = *(float4*)&As[buf][kk][ty * 8];
            float4 a1 = *(float4*)&As[buf][kk][ty * 8 + 4];
            float4 b0 = *(float4*)&Bs[buf][kk][tx * 8];
            float4 b1 = *(float4*)&Bs[buf][kk][tx * 8 + 4];
            unsigned long long bb0, bb1, bb2, bb3;
            asm("mov.b64 %0, {%1, %2};" : "=l"(bb0)
                : "r"(__float_as_uint(b0.x)), "r"(__float_as_uint(b0.y)));
            asm("mov.b64 %0, {%1, %2};" : "=l"(bb1)
                : "r"(__float_as_uint(b0.z)), "r"(__float_as_uint(b0.w)));
            asm("mov.b64 %0, {%1, %2};" : "=l"(bb2)
                : "r"(__float_as_uint(b1.x)), "r"(__float_as_uint(b1.y)));
            asm("mov.b64 %0, {%1, %2};" : "=l"(bb3)
                : "r"(__float_as_uint(b1.z)), "r"(__float_as_uint(b1.w)));
            float av[8] = {a0.x, a0.y, a0.z, a0.w, a1.x, a1.y, a1.z, a1.w};
#pragma unroll
            for (int i = 0; i < 8; i++) {
                unsigned long long pa;
                asm("mov.b64 %0, {%1, %1};"
                    : "=l"(pa) : "r"(__float_as_uint(av[i])));
                asm("fma.rn.f32x2 %0, %1, %2, %0;"
                    : "+l"(acc2[i][0]) : "l"(pa), "l"(bb0));
                asm("fma.rn.f32x2 %0, %1, %2, %0;"
                    : "+l"(acc2[i][1]) : "l"(pa), "l"(bb1));
                asm("fma.rn.f32x2 %0, %1, %2, %0;"
                    : "+l"(acc2[i][2]) : "l"(pa), "l"(bb2));
                asm("fma.rn.f32x2 %0, %1, %2, %0;"
                    : "+l"(acc2[i][3]) : "l"(pa), "l"(bb3));
            }
        }

        if (kt + 1 < KT) {
            storeA(buf ^ 1);
            cp_async_wait0();
            __syncthreads();
            buf ^= 1;
        }
    }

    // unpack accumulators
    float acc[8][8];
#pragma unroll
    for (int i = 0; i < 8; i++)
#pragma unroll
        for (int jp = 0; jp < 4; jp++) {
            unsigned lo, hi;
            asm("mov.b64 {%0, %1}, %2;" : "=r"(lo), "=r"(hi) : "l"(acc2[i][jp]));
            acc[i][jp * 2]     = __uint_as_float(lo);
            acc[i][jp * 2 + 1] = __uint_as_float(hi);
        }

    const int cb = n0 + tx * 8;
    constexpr int ZW = (NTOT - HCOLS) > 0 ? (NTOT - HCOLS) : 1;
    if (cb < HCOLS) {
#pragma unroll
        for (int i = 0; i < 8; i++) {
            int gr = m0 + ty * 8 + i;
            if (gr < M) {
                *(float4*)&H[(size_t)gr * HCOLS + cb] =
                    make_float4(acc[i][0], acc[i][1], acc[i][2], acc[i][3]);
                *(float4*)&H[(size_t)gr * HCOLS + cb + 4] =
                    make_float4(acc[i][4], acc[i][5], acc[i][6], acc[i][7]);
            }
        }
    } else {
        int zc = cb - HCOLS;
        float4 bia0 = *(const float4*)&bias[zc];
        float4 bia1 = *(const float4*)&bias[zc + 4];
#pragma unroll
        for (int i = 0; i < 8; i++) {
            int gr = m0 + ty * 8 + i;
            if (gr < M) {
                *(float4*)&Z[(size_t)gr * ZW + zc] =
                    make_float4(acc[i][0] + bia0.x, acc[i][1] + bia0.y,
                                acc[i][2] + bia0.z, acc[i][3] + bia0.w);
                *(float4*)&Z[(size_t)gr * ZW + zc + 4] =
                    make_float4(acc[i][4] + bia1.x, acc[i][5] + bia1.y,
                                acc[i][6] + bia1.z, acc[i][7] + bia1.w);
            }
        }
    }
}

__global__ void __launch_bounds__(256, 2) gemm1_kernel(const float* __restrict__ x,
                                                       const float* __restrict__ b1) {
    gemm_fused_core<256, 128, 192, false>(x, g_Wc1, g_H1, g_Z1, b1, NN);
}
__global__ void __launch_bounds__(256, 2) gemm2_kernel(const float* __restrict__ b2) {
    gemm_fused_core<128, 64, 96, true>(g_Z1, g_Wc2, g_H2, g_Z2, b2, NN);
}
// UV = Z2 @ Wd1cat  (all 128 cols -> "H" = g_UV; bias path never taken)
__global__ void __launch_bounds__(256, 2) gemm_uv_kernel(const float* __restrict__ dummy_bias) {
    gemm_fused_core<128, 32, 128, false>(g_Z2, g_Wd1c, g_UV, g_UV, dummy_bias, NN);
}

// ---------------------------------------------------------------------------
// CSR warp-per-node aggregation, NO atomics, unroll-2 for MLP.
// ---------------------------------------------------------------------------
__global__ void __launch_bounds__(256) agg1_csr_kernel() {
    int d = (blockIdx.x * blockDim.x + threadIdx.x) >> 5;
    int lane = threadIdx.x & 31;
    if (d >= NN) return;
    int beg = g_off[d], end = g_off[d + 1];
    if (beg == end) return;
    float i0 = g_inv[3 * d], i1 = g_inv[3 * d + 1], i2 = g_inv[3 * d + 2];

    float2 acc = make_float2(0.f, 0.f);
    int i = beg;
    for (; i + 1 < end; i += 2) {
        unsigned va = g_epk[i], vb = g_epk[i + 1];
        int sa = va & 0xFFFFF, ra = va >> 20;
        int sb = vb & 0xFFFFF, rb = vb >> 20;
        float sca = (ra == 0) ? i0 : ((ra == 1) ? i1 : i2);
        float scb = (rb == 0) ? i0 : ((rb == 1) ? i1 : i2);
        float2 ha = *(const float2*)&g_H1[(size_t)sa * 192 + ra * 64 + lane * 2];
        float2 hb = *(const float2*)&g_H1[(size_t)sb * 192 + rb * 64 + lane * 2];
        acc.x += ha.x * sca; acc.y += ha.y * sca;
        acc.x += hb.x * scb; acc.y += hb.y * scb;
    }
    if (i < end) {
        unsigned v = g_epk[i];
        int s = v & 0xFFFFF, r = v >> 20;
        float sc = (r == 0) ? i0 : ((r == 1) ? i1 : i2);
        float2 h = *(const float2*)&g_H1[(size_t)s * 192 + r * 64 + lane * 2];
        acc.x += h.x * sc; acc.y += h.y * sc;
    }
    float2 z = *(float2*)&g_Z1[(size_t)d * 64 + lane * 2];
    z.x += acc.x; z.y += acc.y;
    *(float2*)&g_Z1[(size_t)d * 64 + lane * 2] = z;
}

__global__ void __launch_bounds__(256) agg2_csr_kernel() {
    int d = (blockIdx.x * blockDim.x + threadIdx.x) >> 5;
    int lane = threadIdx.x & 31;
    if (d >= NN) return;
    int beg = g_off[d], end = g_off[d + 1];
    if (beg == end) return;
    float i0 = g_inv[3 * d], i1 = g_inv[3 * d + 1], i2 = g_inv[3 * d + 2];

    float acc = 0.f;
    int i = beg;
    for (; i + 1 < end; i += 2) {
        unsigned va = g_epk[i], vb = g_epk[i + 1];
        int sa = va & 0xFFFFF, ra = va >> 20;
        int sb = vb & 0xFFFFF, rb = vb >> 20;
        float sca = (ra == 0) ? i0 : ((ra == 1) ? i1 : i2);
        float scb = (rb == 0) ? i0 : ((rb == 1) ? i1 : i2);
        float ha = g_H2[(size_t)sa * 96 + ra * 32 + lane];
        float hb = g_H2[(size_t)sb * 96 + rb * 32 + lane];
        acc += ha * sca + hb * scb;
    }
    if (i < end) {
        unsigned v = g_epk[i];
        int s = v & 0xFFFFF, r = v >> 20;
        float sc = (r == 0) ? i0 : ((r == 1) ? i1 : i2);
        acc += g_H2[(size_t)s * 96 + r * 32 + lane] * sc;
    }
    g_Z2[(size_t)d * 32 + lane] += acc;
}

// ---------------------------------------------------------------------------
// per-edge decoder: out[p] = relu(U[s] + V[d] + bd1) . Wd2 + bd2
// ---------------------------------------------------------------------------
__global__ void __launch_bounds__(256) decoder2_kernel(
    const int* __restrict__ psrc, const int* __restrict__ pdst,
    const float* __restrict__ bd1, const float* __restrict__ Wd2,
    const float* __restrict__ bd2, float* __restrict__ out, int P) {
    __shared__ float sB1[64];
    __shared__ float sW2[64];
    int tid = threadIdx.x;
    if (tid < 64) { sB1[tid] = bd1[tid]; sW2[tid] = Wd2[tid]; }
    __syncthreads();

    int p = blockIdx.x * 256 + tid;
    if (p >= P) return;
    int s = psrc[p], d = pdst[p];
    const float* u = &g_UV[(size_t)s * 128];
    const float* v = &g_UV[(size_t)d * 128 + 64];

    float o = bd2[0];
#pragma unroll
    for (int q = 0; q < 16; q++) {
        float4 uu = *(const float4*)&u[q * 4];
        float4 vv = *(const float4*)&v[q * 4];
        float4 bb = *(const float4*)&sB1[q * 4];
        float4 ww = *(const float4*)&sW2[q * 4];
        o += fmaxf(uu.x + vv.x + bb.x, 0.f) * ww.x;
        o += fmaxf(uu.y + vv.y + bb.y, 0.f) * ww.y;
        o += fmaxf(uu.z + vv.z + bb.z, 0.f) * ww.z;
        o += fmaxf(uu.w + vv.w + bb.w, 0.f) * ww.w;
    }
    out[p] = o;
}

// ---------------------------------------------------------------------------
extern "C" void kernel_launch(void* const* d_in, const int* in_sizes, int n_in,
                              void* d_out, int out_size) {
    const float* x     = (const float*)d_in[0];
    const int*   ei    = (const int*)d_in[1];
    const int*   et    = (const int*)d_in[2];
    const int*   pe    = (const int*)d_in[3];
    const float* W1    = (const float*)d_in[4];
    const float* root1 = (const float*)d_in[5];
    const float* b1    = (const float*)d_in[6];
    const float* W2    = (const float*)d_in[7];
    const float* root2 = (const float*)d_in[8];
    const float* b2    = (const float*)d_in[9];
    const float* Wd1   = (const float*)d_in[10];
    const float* bd1   = (const float*)d_in[11];
    const float* Wd2   = (const float*)d_in[12];
    const float* bd2   = (const float*)d_in[13];
    float* out = (float*)d_out;

    const int E = in_sizes[1] / 2;
    const int P = in_sizes[3] / 2;
    const int* src = ei;
    const int* dst = ei + E;
    const int* ps  = pe;
    const int* pd  = pe + P;

    zero_cnt_kernel<<<(NN * 3 + 255) / 256, 256>>>(NN * 3);
    wc1_kernel<<<(128 * 256 + 255) / 256, 256>>>(W1, root1);
    wc2_kernel<<<(64 * 128 + 255) / 256, 256>>>(W2, root2);
    {
        dim3 g(2, (NN + 127) / 128);
        gemm1_kernel<<<g, 256>>>(x, b1);
    }
    wd1c_kernel<<<(32 * 128 + 255) / 256, 256>>>(Wd1);

    // counts + inverse means + CSR (shared by both layers)
    count_kernel<<<(E + 255) / 256, 256>>>(dst, et, E);
    inv_kernel<<<(NN * 3 + 255) / 256, 256>>>(NN * 3);
    scan1_kernel<<<SCAN_NB, SCAN_BS>>>();
    scan2_kernel<<<1, 512>>>();
    scan3_kernel<<<(NN + 255) / 256, 256>>>();
    scatter_kernel<<<(E + 255) / 256, 256>>>(src, dst, et, E);

    // layer 1 aggregation
    agg1_csr_kernel<<<(NN * 32 + 255) / 256, 256>>>();

    // layer 2 (relu folded into GEMM2 A-loads)
    {
        dim3 g(1, (NN + 127) / 128);
        gemm2_kernel<<<g, 256>>>(b2);
    }
    agg2_csr_kernel<<<(NN * 32 + 255) / 256, 256>>>();

    // decoder: per-node GEMM (UV), then cheap per-edge kernel
    {
        dim3 g(1, (NN + 127) / 128);
        gemm_uv_kernel<<<g, 256>>>(bd1);
    }
    decoder2_kernel<<<(P + 255) / 256, 256>>>(ps, pd, bd1, Wd2, bd2, out, P);
}

// round 10
// speedup vs baseline: 1.9354x; 1.1248x over previous
#include <cuda_runtime.h>
#include <cuda_bf16.h>

// ---------------------------------------------------------------------------
// RGCN link predictor:
//   split x -> bf16 hi/lo; GEMM1 = tensor-core bf16 3-term compensated
//   (x @ [W1|root1] fused -> H1/Z1);  prep: counts/inv/scan/CSR scatter;
//   CSR warp-per-node agg; GEMM2 (fp32 FFMA2) -> agg; decoder decomposed.
// __device__ globals only referenced from device code (round-3 lesson).
// ---------------------------------------------------------------------------

#define NN    100000
#define REL   3
#define EMAX  1600000
#define SCAN_BS   256
#define SCAN_NB   ((NN + SCAN_BS - 1) / SCAN_BS)   // 391
#define BF_RS 24   // bf16 smem row stride (48 B): 16B-aligned + conflict-free

// scratch (static device globals; no allocation allowed)
__device__ int      g_cnt[NN * REL];
__device__ float    g_inv[NN * REL];
__device__ int      g_off[NN + 1];
__device__ int      g_cur[NN];
__device__ int      g_bsum[SCAN_NB];
__device__ int      g_bpre[SCAN_NB];
__device__ unsigned g_epk[EMAX];     // src | (rel << 20), sorted by dst
__device__ float    g_H1[NN * 192];
__device__ float    g_Z1[NN * 64];
__device__ float    g_H2[NN * 96];
__device__ float    g_Z2[NN * 32];
__device__ float    g_UV[NN * 128];  // cols 0-63: U, 64-127: V
__device__ float    g_Wc2[64 * 128];
__device__ float    g_Wd1c[32 * 128];
__device__ __nv_bfloat16 g_xh[(size_t)NN * 128];
__device__ __nv_bfloat16 g_xl[(size_t)NN * 128];
__device__ __nv_bfloat16 g_w1h[256 * 128];   // [n][k] transposed
__device__ __nv_bfloat16 g_w1l[256 * 128];

// ---------------------------------------------------------------------------
__global__ void zero_cnt_kernel(int n) {
    int i = blockIdx.x * blockDim.x + threadIdx.x;
    if (i < n) g_cnt[i] = 0;
}

// split x into bf16 hi + lo (hi = bf16(x), lo = bf16(x - hi))
__global__ void splitx_kernel(const float* __restrict__ x) {
    int i = blockIdx.x * blockDim.x + threadIdx.x;   // one float4
    if (i < NN * 32) {
        float4 v = ((const float4*)x)[i];
        __nv_bfloat16 h0 = __float2bfloat16(v.x), h1 = __float2bfloat16(v.y);
        __nv_bfloat16 h2 = __float2bfloat16(v.z), h3 = __float2bfloat16(v.w);
        __nv_bfloat16 l0 = __float2bfloat16(v.x - __bfloat162float(h0));
        __nv_bfloat16 l1 = __float2bfloat16(v.y - __bfloat162float(h1));
        __nv_bfloat16 l2 = __float2bfloat16(v.z - __bfloat162float(h2));
        __nv_bfloat16 l3 = __float2bfloat16(v.w - __bfloat162float(h3));
        __nv_bfloat162* oh = (__nv_bfloat162*)g_xh;
        __nv_bfloat162* ol = (__nv_bfloat162*)g_xl;
        oh[i * 2]     = __nv_bfloat162(h0, h1);
        oh[i * 2 + 1] = __nv_bfloat162(h2, h3);
        ol[i * 2]     = __nv_bfloat162(l0, l1);
        ol[i * 2 + 1] = __nv_bfloat162(l2, l3);
    }
}

// pack [W1 r0|r1|r2 | root1] transposed -> g_w1h/g_w1l [256][128] bf16
__global__ void wt1_kernel(const float* __restrict__ W1,
                           const float* __restrict__ root1) {
    int i = blockIdx.x * blockDim.x + threadIdx.x;
    if (i < 256 * 128) {
        int n = i >> 7, k = i & 127;
        float w;
        if (n < 192) {
            int r = n >> 6, j = n & 63;
            w = W1[r * 128 * 64 + k * 64 + j];
        } else {
            w = root1[k * 64 + (n - 192)];
        }
        __nv_bfloat16 h = __float2bfloat16(w);
        g_w1h[i] = h;
        g_w1l[i] = __float2bfloat16(w - __bfloat162float(h));
    }
}

__global__ void count_kernel(const int* __restrict__ dst,
                             const int* __restrict__ et, int E) {
    int e = blockIdx.x * blockDim.x + threadIdx.x;
    if (e < E) atomicAdd(&g_cnt[dst[e] * 3 + et[e]], 1);
}

__global__ void inv_kernel(int n) {
    int i = blockIdx.x * blockDim.x + threadIdx.x;
    if (i < n) g_inv[i] = 1.0f / fmaxf((float)g_cnt[i], 1.0f);
}

// ---- parallel 3-phase exclusive scan of node degrees ----------------------
__global__ void __launch_bounds__(SCAN_BS) scan1_kernel() {
    __shared__ int s[SCAN_BS];
    int t = threadIdx.x;
    int i = blockIdx.x * SCAN_BS + t;
    int d = 0;
    if (i < NN) d = g_cnt[3 * i] + g_cnt[3 * i + 1] + g_cnt[3 * i + 2];
    s[t] = d;
    __syncthreads();
#pragma unroll
    for (int o = 1; o < SCAN_BS; o <<= 1) {
        int v = (t >= o) ? s[t - o] : 0;
        __syncthreads();
        s[t] += v;
        __syncthreads();
    }
    if (i < NN) g_off[i] = s[t] - d;
    if (t == SCAN_BS - 1) g_bsum[blockIdx.x] = s[t];
}

__global__ void __launch_bounds__(512) scan2_kernel() {
    __shared__ int s[512];
    int t = threadIdx.x;
    int v0 = (t < SCAN_NB) ? g_bsum[t] : 0;
    s[t] = v0;
    __syncthreads();
#pragma unroll
    for (int o = 1; o < 512; o <<= 1) {
        int v = (t >= o) ? s[t - o] : 0;
        __syncthreads();
        s[t] += v;
        __syncthreads();
    }
    if (t < SCAN_NB) g_bpre[t] = s[t] - v0;
    if (t == 511) g_off[NN] = s[511];
}

__global__ void scan3_kernel() {
    int i = blockIdx.x * blockDim.x + threadIdx.x;
    if (i < NN) {
        int off = g_off[i] + g_bpre[i / SCAN_BS];
        g_off[i] = off;
        g_cur[i] = off;
    }
}

__global__ void scatter_kernel(const int* __restrict__ src,
                               const int* __restrict__ dst,
                               const int* __restrict__ et, int E) {
    int e = blockIdx.x * blockDim.x + threadIdx.x;
    if (e < E) {
        int pos = atomicAdd(&g_cur[dst[e]], 1);
        g_epk[pos] = (unsigned)src[e] | ((unsigned)et[e] << 20);
    }
}

// pack [W2 r0|r1|r2 | root2] -> g_Wc2 [64,128]
__global__ void wc2_kernel(const float* __restrict__ W2,
                           const float* __restrict__ root2) {
    int i = blockIdx.x * blockDim.x + threadIdx.x;
    if (i < 64 * 128) {
        int k = i >> 7, c = i & 127;
        float v;
        if (c < 96) {
            int r = c >> 5, j = c & 31;
            v = W2[r * 64 * 32 + k * 32 + j];
        } else {
            v = root2[k * 32 + (c - 96)];
        }
        g_Wc2[i] = v;
    }
}

// pack Wd1 [64,64] -> g_Wd1c [32,128]
__global__ void wd1c_kernel(const float* __restrict__ Wd1) {
    int i = blockIdx.x * blockDim.x + threadIdx.x;
    if (i < 32 * 128) {
        int k = i >> 7, c = i & 127;
        g_Wd1c[i] = (c < 64) ? Wd1[k * 64 + c] : Wd1[(32 + k) * 64 + (c - 64)];
    }
}

// ---------------------------------------------------------------------------
// cp.async helpers
// ---------------------------------------------------------------------------
__device__ __forceinline__ void cp_async16(void* smem_dst, const void* gmem_src) {
    unsigned saddr = (unsigned)__cvta_generic_to_shared(smem_dst);
    asm volatile("cp.async.cg.shared.global [%0], [%1], 16;\n"
                 :: "r"(saddr), "l"(gmem_src) : "memory");
}
__device__ __forceinline__ void cp_async_commit() {
    asm volatile("cp.async.commit_group;\n" ::: "memory");
}
__device__ __forceinline__ void cp_async_wait0() {
    asm volatile("cp.async.wait_group 0;\n" ::: "memory");
}

#define MMA_BF16(c, a0, a1, a2, a3, b0, b1)                                   \
    asm volatile(                                                             \
        "mma.sync.aligned.m16n8k16.row.col.f32.bf16.bf16.f32 "                \
        "{%0,%1,%2,%3}, {%4,%5,%6,%7}, {%8,%9}, {%0,%1,%2,%3};"               \
        : "+f"((c)[0]), "+f"((c)[1]), "+f"((c)[2]), "+f"((c)[3])              \
        : "r"(a0), "r"(a1), "r"(a2), "r"(a3), "r"(b0), "r"(b1))

// ---------------------------------------------------------------------------
// GEMM1 bf16 tensor-core, 3-term compensated (Ahi*Bhi + Ahi*Blo + Alo*Bhi).
// Block 128x128, BK=16, 256 thr = 8 warps (4m x 2n), warp tile 32x64.
// Fused epilogue: cols <192 -> H1, cols >=192 -> Z1 (+b1).
// ---------------------------------------------------------------------------
__global__ void __launch_bounds__(256, 2) gemm1_bf16_kernel(
    const float* __restrict__ b1) {

    __shared__ __align__(16) __nv_bfloat16 Ah[2][128][BF_RS];
    __shared__ __align__(16) __nv_bfloat16 Al[2][128][BF_RS];
    __shared__ __align__(16) __nv_bfloat16 Bh[2][128][BF_RS];
    __shared__ __align__(16) __nv_bfloat16 Bl[2][128][BF_RS];

    const int tid = threadIdx.x, lane = tid & 31, wid = tid >> 5;
    const int wm = wid & 3, wn = wid >> 2;         // 4m x 2n
    const int g = lane >> 2, tg = lane & 3;
    const int m0 = blockIdx.y * 128, n0 = blockIdx.x * 128;
    const int row = tid >> 1, ch = tid & 1;        // cp.async mapping

    float acc[2][8][4] = {};

    auto issue = [&](int k0, int buf) {
        int gr = min(m0 + row, NN - 1);
        cp_async16(&Ah[buf][row][ch * 8], &g_xh[(size_t)gr * 128 + k0 + ch * 8]);
        cp_async16(&Al[buf][row][ch * 8], &g_xl[(size_t)gr * 128 + k0 + ch * 8]);
        cp_async16(&Bh[buf][row][ch * 8], &g_w1h[(n0 + row) * 128 + k0 + ch * 8]);
        cp_async16(&Bl[buf][row][ch * 8], &g_w1l[(n0 + row) * 128 + k0 + ch * 8]);
        cp_async_commit();
    };

    issue(0, 0);
    cp_async_wait0();
    __syncthreads();

    int buf = 0;
    for (int kt = 0; kt < 8; kt++) {
        if (kt < 7) issue((kt + 1) * 16, buf ^ 1);

        // cache all B fragments for this warp's 8 n-tiles
        unsigned bh[8][2], bl[8][2];
#pragma unroll
        for (int nj = 0; nj < 8; nj++) {
            int br = wn * 64 + nj * 8 + g;
            bh[nj][0] = *(const unsigned*)&Bh[buf][br][2 * tg];
            bh[nj][1] = *(const unsigned*)&Bh[buf][br][2 * tg + 8];
            bl[nj][0] = *(const unsigned*)&Bl[buf][br][2 * tg];
            bl[nj][1] = *(const unsigned*)&Bl[buf][br][2 * tg + 8];
        }
#pragma unroll
        for (int mi = 0; mi < 2; mi++) {
            int ar = wm * 32 + mi * 16 + g;
            unsigned ah0 = *(const unsigned*)&Ah[buf][ar][2 * tg];
            unsigned ah1 = *(const unsigned*)&Ah[buf][ar + 8][2 * tg];
            unsigned ah2 = *(const unsigned*)&Ah[buf][ar][2 * tg + 8];
            unsigned ah3 = *(const unsigned*)&Ah[buf][ar + 8][2 * tg + 8];
            unsigned al0 = *(const unsigned*)&Al[buf][ar][2 * tg];
            unsigned al1 = *(const unsigned*)&Al[buf][ar + 8][2 * tg];
            unsigned al2 = *(const unsigned*)&Al[buf][ar][2 * tg + 8];
            unsigned al3 = *(const unsigned*)&Al[buf][ar + 8][2 * tg + 8];
#pragma unroll
            for (int nj = 0; nj < 8; nj++) {
                MMA_BF16(acc[mi][nj], ah0, ah1, ah2, ah3, bh[nj][0], bh[nj][1]);
                MMA_BF16(acc[mi][nj], ah0, ah1, ah2, ah3, bl[nj][0], bl[nj][1]);
                MMA_BF16(acc[mi][nj], al0, al1, al2, al3, bh[nj][0], bh[nj][1]);
            }
        }

        if (kt < 7) {
            cp_async_wait0();
            __syncthreads();
            buf ^= 1;
        }
    }

    // fused epilogue (region uniform per warp: boundary 192 = n0 + wn*64 edge)
    const bool isZ = (n0 + wn * 64) >= 192;
#pragma unroll
    for (int mi = 0; mi < 2; mi++) {
#pragma unroll
        for (int nj = 0; nj < 8; nj++) {
            int r0 = m0 + wm * 32 + mi * 16 + g;
            int cb = n0 + wn * 64 + nj * 8 + 2 * tg;
            float* c = acc[mi][nj];
            if (isZ) {
                int zc = cb - 192;
                float bx = b1[zc], by = b1[zc + 1];
                if (r0 < NN)
                    *(float2*)&g_Z1[(size_t)r0 * 64 + zc] =
                        make_float2(c[0] + bx, c[1] + by);
                if (r0 + 8 < NN)
                    *(float2*)&g_Z1[(size_t)(r0 + 8) * 64 + zc] =
                        make_float2(c[2] + bx, c[3] + by);
            } else {
                if (r0 < NN)
                    *(float2*)&g_H1[(size_t)r0 * 192 + cb] =
                        make_float2(c[0], c[1]);
                if (r0 + 8 < NN)
                    *(float2*)&g_H1[(size_t)(r0 + 8) * 192 + cb] =
                        make_float2(c[2], c[3]);
            }
        }
    }
}

// ---------------------------------------------------------------------------
// fp32 FFMA2 GEMM core (for gemm2 / uv), unchanged from round 9
// ---------------------------------------------------------------------------
template <int NTOT, int K, int HCOLS, bool RELU>
__device__ __forceinline__ void gemm_fused_core(
    const float* __restrict__ A, const float* __restrict__ B,
    float* __restrict__ H, float* __restrict__ Z,
    const float* __restrict__ bias, int M) {

    __shared__ float As[2][16][128];
    __shared__ float Bs[2][16][128];

    const int tid = threadIdx.x;
    const int tx = tid & 15, ty = tid >> 4;
    const int m0 = blockIdx.y * 128, n0 = blockIdx.x * 128;

    float4 aReg[2];
    unsigned long long acc2[8][4] = {};

    auto loadA = [&](int k0) {
#pragma unroll
        for (int i = 0; i < 2; i++) {
            int idx = tid + i * 256;
            int row = idx >> 2, c4 = idx & 3;
            int gr = m0 + row;
            float4 v = make_float4(0.f, 0.f, 0.f, 0.f);
            if (gr < M) v = *(const float4*)&A[(size_t)gr * K + k0 + c4 * 4];
            if (RELU) {
                v.x = fmaxf(v.x, 0.f); v.y = fmaxf(v.y, 0.f);
                v.z = fmaxf(v.z, 0.f); v.w = fmaxf(v.w, 0.f);
            }
            aReg[i] = v;
        }
    };
    auto storeA = [&](int buf) {
#pragma unroll
        for (int i = 0; i < 2; i++) {
            int idx = tid + i * 256;
            int row = idx >> 2, c4 = idx & 3;
            As[buf][c4 * 4 + 0][row] = aReg[i].x;
            As[buf][c4 * 4 + 1][row] = aReg[i].y;
            As[buf][c4 * 4 + 2][row] = aReg[i].z;
            As[buf][c4 * 4 + 3][row] = aReg[i].w;
        }
    };
    auto issueB = [&](int k0, int buf) {
#pragma unroll
        for (int i = 0; i < 2; i++) {
            int idx = tid + i * 256;
            int row = idx >> 5, c4 = idx & 31;
            cp_async16(&Bs[buf][row][c4 * 4],
                       &B[(size_t)(k0 + row) * NTOT + n0 + c4 * 4]);
        }
        cp_async_commit();
    };

    constexpr int KT = K / 16;
    loadA(0);
    issueB(0, 0);
    storeA(0);
    cp_async_wait0();
    __syncthreads();

    int buf = 0;
#pragma unroll
    for (int kt = 0; kt < KT; kt++) {
        if (kt + 1 < KT) {
            loadA((kt + 1) * 16);
            issueB((kt + 1) * 16, buf ^ 1);
        }

#pragma unroll
        for (int kk = 0; kk < 16; kk++) {
            float4 a0 = *(float4*)&As[buf][kk][ty * 8];
            float4 a1 = *(float4*)&As[buf][kk][ty * 8 + 4];
            float4 b0 = *(float4*)&Bs[buf][kk][tx * 8];
            float4 b1 = *(float4*)&Bs[buf][kk][tx * 8 + 4];
            unsigned long long bb0, bb1, bb2, bb3;
            asm("mov.b64 %0, {%1, %2};" : "=l"(bb0)
                : "r"(__float_as_uint(b0.x)), "r"(__float_as_uint(b0.y)));
            asm("mov.b64 %0, {%1, %2};" : "=l"(bb1)
                : "r"(__float_as_uint(b0.z)), "r"(__float_as_uint(b0.w)));
            asm("mov.b64 %0, {%1, %2};" : "=l"(bb2)
                : "r"(__float_as_uint(b1.x)), "r"(__float_as_uint(b1.y)));
            asm("mov.b64 %0, {%1, %2};" : "=l"(bb3)
                : "r"(__float_as_uint(b1.z)), "r"(__float_as_uint(b1.w)));
            float av[8] = {a0.x, a0.y, a0.z, a0.w, a1.x, a1.y, a1.z, a1.w};
#pragma unroll
            for (int i = 0; i < 8; i++) {
                unsigned long long pa;
                asm("mov.b64 %0, {%1, %1};"
                    : "=l"(pa) : "r"(__float_as_uint(av[i])));
                asm("fma.rn.f32x2 %0, %1, %2, %0;"
                    : "+l"(acc2[i][0]) : "l"(pa), "l"(bb0));
                asm("fma.rn.f32x2 %0, %1, %2, %0;"
                    : "+l"(acc2[i][1]) : "l"(pa), "l"(bb1));
                asm("fma.rn.f32x2 %0, %1, %2, %0;"
                    : "+l"(acc2[i][2]) : "l"(pa), "l"(bb2));
                asm("fma.rn.f32x2 %0, %1, %2, %0;"
                    : "+l"(acc2[i][3]) : "l"(pa), "l"(bb3));
            }
        }

        if (kt + 1 < KT) {
            storeA(buf ^ 1);
            cp_async_wait0();
            __syncthreads();
            buf ^= 1;
        }
    }

    float acc[8][8];
#pragma unroll
    for (int i = 0; i < 8; i++)
#pragma unroll
        for (int jp = 0; jp < 4; jp++) {
            unsigned lo, hi;
            asm("mov.b64 {%0, %1}, %2;" : "=r"(lo), "=r"(hi) : "l"(acc2[i][jp]));
            acc[i][jp * 2]     = __uint_as_float(lo);
            acc[i][jp * 2 + 1] = __uint_as_float(hi);
        }

    const int cb = n0 + tx * 8;
    constexpr int ZW = (NTOT - HCOLS) > 0 ? (NTOT - HCOLS) : 1;
    if (cb < HCOLS) {
#pragma unroll
        for (int i = 0; i < 8; i++) {
            int gr = m0 + ty * 8 + i;
            if (gr < M) {
                *(float4*)&H[(size_t)gr * HCOLS + cb] =
                    make_float4(acc[i][0], acc[i][1], acc[i][2], acc[i][3]);
                *(float4*)&H[(size_t)gr * HCOLS + cb + 4] =
                    make_float4(acc[i][4], acc[i][5], acc[i][6], acc[i][7]);
            }
        }
    } else {
        int zc = cb - HCOLS;
        float4 bia0 = *(const float4*)&bias[zc];
        float4 bia1 = *(const float4*)&bias[zc + 4];
#pragma unroll
        for (int i = 0; i < 8; i++) {
            int gr = m0 + ty * 8 + i;
            if (gr < M) {
                *(float4*)&Z[(size_t)gr * ZW + zc] =
                    make_float4(acc[i][0] + bia0.x, acc[i][1] + bia0.y,
                                acc[i][2] + bia0.z, acc[i][3] + bia0.w);
                *(float4*)&Z[(size_t)gr * ZW + zc + 4] =
                    make_float4(acc[i][4] + bia1.x, acc[i][5] + bia1.y,
                                acc[i][6] + bia1.z, acc[i][7] + bia1.w);
            }
        }
    }
}

__global__ void __launch_bounds__(256, 2) gemm2_kernel(const float* __restrict__ b2) {
    gemm_fused_core<128, 64, 96, true>(g_Z1, g_Wc2, g_H2, g_Z2, b2, NN);
}
__global__ void __launch_bounds__(256, 2) gemm_uv_kernel(const float* __restrict__ dummy_bias) {
    gemm_fused_core<128, 32, 128, false>(g_Z2, g_Wd1c, g_UV, g_UV, dummy_bias, NN);
}

// ---------------------------------------------------------------------------
// CSR warp-per-node aggregation, NO atomics, unroll-2.
// ---------------------------------------------------------------------------
__global__ void __launch_bounds__(256) agg1_csr_kernel() {
    int d = (blockIdx.x * blockDim.x + threadIdx.x) >> 5;
    int lane = threadIdx.x & 31;
    if (d >= NN) return;
    int beg = g_off[d], end = g_off[d + 1];
    if (beg == end) return;
    float i0 = g_inv[3 * d], i1 = g_inv[3 * d + 1], i2 = g_inv[3 * d + 2];

    float2 acc = make_float2(0.f, 0.f);
    int i = beg;
    for (; i + 1 < end; i += 2) {
        unsigned va = g_epk[i], vb = g_epk[i + 1];
        int sa = va & 0xFFFFF, ra = va >> 20;
        int sb = vb & 0xFFFFF, rb = vb >> 20;
        float sca = (ra == 0) ? i0 : ((ra == 1) ? i1 : i2);
        float scb = (rb == 0) ? i0 : ((rb == 1) ? i1 : i2);
        float2 ha = *(const float2*)&g_H1[(size_t)sa * 192 + ra * 64 + lane * 2];
        float2 hb = *(const float2*)&g_H1[(size_t)sb * 192 + rb * 64 + lane * 2];
        acc.x += ha.x * sca; acc.y += ha.y * sca;
        acc.x += hb.x * scb; acc.y += hb.y * scb;
    }
    if (i < end) {
        unsigned v = g_epk[i];
        int s = v & 0xFFFFF, r = v >> 20;
        float sc = (r == 0) ? i0 : ((r == 1) ? i1 : i2);
        float2 h = *(const float2*)&g_H1[(size_t)s * 192 + r * 64 + lane * 2];
        acc.x += h.x * sc; acc.y += h.y * sc;
    }
    float2 z = *(float2*)&g_Z1[(size_t)d * 64 + lane * 2];
    z.x += acc.x; z.y += acc.y;
    *(float2*)&g_Z1[(size_t)d * 64 + lane * 2] = z;
}

__global__ void __launch_bounds__(256) agg2_csr_kernel() {
    int d = (blockIdx.x * blockDim.x + threadIdx.x) >> 5;
    int lane = threadIdx.x & 31;
    if (d >= NN) return;
    int beg = g_off[d], end = g_off[d + 1];
    if (beg == end) return;
    float i0 = g_inv[3 * d], i1 = g_inv[3 * d + 1], i2 = g_inv[3 * d + 2];

    float acc = 0.f;
    int i = beg;
    for (; i + 1 < end; i += 2) {
        unsigned va = g_epk[i], vb = g_epk[i + 1];
        int sa = va & 0xFFFFF, ra = va >> 20;
        int sb = vb & 0xFFFFF, rb = vb >> 20;
        float sca = (ra == 0) ? i0 : ((ra == 1) ? i1 : i2);
        float scb = (rb == 0) ? i0 : ((rb == 1) ? i1 : i2);
        float ha = g_H2[(size_t)sa * 96 + ra * 32 + lane];
        float hb = g_H2[(size_t)sb * 96 + rb * 32 + lane];
        acc += ha * sca + hb * scb;
    }
    if (i < end) {
        unsigned v = g_epk[i];
        int s = v & 0xFFFFF, r = v >> 20;
        float sc = (r == 0) ? i0 : ((r == 1) ? i1 : i2);
        acc += g_H2[(size_t)s * 96 + r * 32 + lane] * sc;
    }
    g_Z2[(size_t)d * 32 + lane] += acc;
}

// ---------------------------------------------------------------------------
// per-edge decoder: out[p] = relu(U[s] + V[d] + bd1) . Wd2 + bd2
// ---------------------------------------------------------------------------
__global__ void __launch_bounds__(256) decoder2_kernel(
    const int* __restrict__ psrc, const int* __restrict__ pdst,
    const float* __restrict__ bd1, const float* __restrict__ Wd2,
    const float* __restrict__ bd2, float* __restrict__ out, int P) {
    __shared__ float sB1[64];
    __shared__ float sW2[64];
    int tid = threadIdx.x;
    if (tid < 64) { sB1[tid] = bd1[tid]; sW2[tid] = Wd2[tid]; }
    __syncthreads();

    int p = blockIdx.x * 256 + tid;
    if (p >= P) return;
    int s = psrc[p], d = pdst[p];
    const float* u = &g_UV[(size_t)s * 128];
    const float* v = &g_UV[(size_t)d * 128 + 64];

    float o = bd2[0];
#pragma unroll
    for (int q = 0; q < 16; q++) {
        float4 uu = *(const float4*)&u[q * 4];
        float4 vv = *(const float4*)&v[q * 4];
        float4 bb = *(const float4*)&sB1[q * 4];
        float4 ww = *(const float4*)&sW2[q * 4];
        o += fmaxf(uu.x + vv.x + bb.x, 0.f) * ww.x;
        o += fmaxf(uu.y + vv.y + bb.y, 0.f) * ww.y;
        o += fmaxf(uu.z + vv.z + bb.z, 0.f) * ww.z;
        o += fmaxf(uu.w + vv.w + bb.w, 0.f) * ww.w;
    }
    out[p] = o;
}

// ---------------------------------------------------------------------------
extern "C" void kernel_launch(void* const* d_in, const int* in_sizes, int n_in,
                              void* d_out, int out_size) {
    const float* x     = (const float*)d_in[0];
    const int*   ei    = (const int*)d_in[1];
    const int*   et    = (const int*)d_in[2];
    const int*   pe    = (const int*)d_in[3];
    const float* W1    = (const float*)d_in[4];
    const float* root1 = (const float*)d_in[5];
    const float* b1    = (const float*)d_in[6];
    const float* W2    = (const float*)d_in[7];
    const float* root2 = (const float*)d_in[8];
    const float* b2    = (const float*)d_in[9];
    const float* Wd1   = (const float*)d_in[10];
    const float* bd1   = (const float*)d_in[11];
    const float* Wd2   = (const float*)d_in[12];
    const float* bd2   = (const float*)d_in[13];
    float* out = (float*)d_out;

    const int E = in_sizes[1] / 2;
    const int P = in_sizes[3] / 2;
    const int* src = ei;
    const int* dst = ei + E;
    const int* ps  = pe;
    const int* pd  = pe + P;

    // index 3 = gemm1_bf16 (ncu capture slot)
    zero_cnt_kernel<<<(NN * 3 + 255) / 256, 256>>>(NN * 3);
    splitx_kernel<<<(NN * 32 + 255) / 256, 256>>>(x);
    wt1_kernel<<<(256 * 128 + 255) / 256, 256>>>(W1, root1);
    {
        dim3 g(2, (NN + 127) / 128);
        gemm1_bf16_kernel<<<g, 256>>>(b1);
    }
    wc2_kernel<<<(64 * 128 + 255) / 256, 256>>>(W2, root2);
    wd1c_kernel<<<(32 * 128 + 255) / 256, 256>>>(Wd1);

    // counts + inverse means + CSR (shared by both layers)
    count_kernel<<<(E + 255) / 256, 256>>>(dst, et, E);
    inv_kernel<<<(NN * 3 + 255) / 256, 256>>>(NN * 3);
    scan1_kernel<<<SCAN_NB, SCAN_BS>>>();
    scan2_kernel<<<1, 512>>>();
    scan3_kernel<<<(NN + 255) / 256, 256>>>();
    scatter_kernel<<<(E + 255) / 256, 256>>>(src, dst, et, E);

    // layer 1 aggregation
    agg1_csr_kernel<<<(NN * 32 + 255) / 256, 256>>>();

    // layer 2 (relu folded into GEMM2 A-loads)
    {
        dim3 g(1, (NN + 127) / 128);
        gemm2_kernel<<<g, 256>>>(b2);
    }
    agg2_csr_kernel<<<(NN * 32 + 255) / 256, 256>>>();

    // decoder: per-node GEMM (UV), then cheap per-edge kernel
    {
        dim3 g(1, (NN + 127) / 128);
        gemm_uv_kernel<<<g, 256>>>(bd1);
    }
    decoder2_kernel<<<(P + 255) / 256, 256>>>(ps, pd, bd1, Wd2, bd2, out, P);
}

// round 11
// speedup vs baseline: 2.0884x; 1.0791x over previous
#include <cuda_runtime.h>
#include <cuda_bf16.h>

// ---------------------------------------------------------------------------
// RGCN link predictor:
//   split x -> bf16 hi/lo; GEMM1 + GEMM2 = tensor-core bf16 3-term compensated
//   fused H/Z epilogues; prep: counts/inv/scan/CSR scatter;
//   CSR warp-per-node agg (no atomics, unroll-4); decoder decomposed (UV GEMM
//   fp32 + cheap per-edge kernel).
// __device__ globals only referenced from device code (round-3 lesson).
// ---------------------------------------------------------------------------

#define NN    100000
#define REL   3
#define EMAX  1600000
#define SCAN_BS   256
#define SCAN_NB   ((NN + SCAN_BS - 1) / SCAN_BS)   // 391
#define BF_RS 24   // bf16 smem row stride (48 B): 16B-aligned + conflict-free

// scratch (static device globals; no allocation allowed)
__device__ int      g_cnt[NN * REL];
__device__ float    g_inv[NN * REL];
__device__ int      g_off[NN + 1];
__device__ int      g_cur[NN];
__device__ int      g_bsum[SCAN_NB];
__device__ int      g_bpre[SCAN_NB];
__device__ unsigned g_epk[EMAX];     // src | (rel << 20), sorted by dst
__device__ float    g_H1[NN * 192];
__device__ float    g_Z1[NN * 64];
__device__ float    g_H2[NN * 96];
__device__ float    g_Z2[NN * 32];
__device__ float    g_UV[NN * 128];  // cols 0-63: U, 64-127: V
__device__ float    g_Wd1c[32 * 128];
__device__ __nv_bfloat16 g_xh[(size_t)NN * 128];
__device__ __nv_bfloat16 g_xl[(size_t)NN * 128];
__device__ __nv_bfloat16 g_z1h[(size_t)NN * 64];
__device__ __nv_bfloat16 g_z1l[(size_t)NN * 64];
__device__ __nv_bfloat16 g_w1h[256 * 128];   // [n][k] transposed
__device__ __nv_bfloat16 g_w1l[256 * 128];
__device__ __nv_bfloat16 g_w2h[128 * 64];    // [n][k] transposed
__device__ __nv_bfloat16 g_w2l[128 * 64];

// ---------------------------------------------------------------------------
__global__ void zero_cnt_kernel(int n) {
    int i = blockIdx.x * blockDim.x + threadIdx.x;
    if (i < n) g_cnt[i] = 0;
}

// split x into bf16 hi + lo
__global__ void splitx_kernel(const float* __restrict__ x) {
    int i = blockIdx.x * blockDim.x + threadIdx.x;   // one float4
    if (i < NN * 32) {
        float4 v = ((const float4*)x)[i];
        __nv_bfloat16 h0 = __float2bfloat16(v.x), h1 = __float2bfloat16(v.y);
        __nv_bfloat16 h2 = __float2bfloat16(v.z), h3 = __float2bfloat16(v.w);
        __nv_bfloat16 l0 = __float2bfloat16(v.x - __bfloat162float(h0));
        __nv_bfloat16 l1 = __float2bfloat16(v.y - __bfloat162float(h1));
        __nv_bfloat16 l2 = __float2bfloat16(v.z - __bfloat162float(h2));
        __nv_bfloat16 l3 = __float2bfloat16(v.w - __bfloat162float(h3));
        __nv_bfloat162* oh = (__nv_bfloat162*)g_xh;
        __nv_bfloat162* ol = (__nv_bfloat162*)g_xl;
        oh[i * 2]     = __nv_bfloat162(h0, h1);
        oh[i * 2 + 1] = __nv_bfloat162(h2, h3);
        ol[i * 2]     = __nv_bfloat162(l0, l1);
        ol[i * 2 + 1] = __nv_bfloat162(l2, l3);
    }
}

// relu(Z1) -> bf16 hi/lo
__global__ void splitz1_kernel() {
    int i = blockIdx.x * blockDim.x + threadIdx.x;   // one float4
    if (i < NN * 16) {
        float4 v = ((const float4*)g_Z1)[i];
        v.x = fmaxf(v.x, 0.f); v.y = fmaxf(v.y, 0.f);
        v.z = fmaxf(v.z, 0.f); v.w = fmaxf(v.w, 0.f);
        __nv_bfloat16 h0 = __float2bfloat16(v.x), h1 = __float2bfloat16(v.y);
        __nv_bfloat16 h2 = __float2bfloat16(v.z), h3 = __float2bfloat16(v.w);
        __nv_bfloat16 l0 = __float2bfloat16(v.x - __bfloat162float(h0));
        __nv_bfloat16 l1 = __float2bfloat16(v.y - __bfloat162float(h1));
        __nv_bfloat16 l2 = __float2bfloat16(v.z - __bfloat162float(h2));
        __nv_bfloat16 l3 = __float2bfloat16(v.w - __bfloat162float(h3));
        __nv_bfloat162* oh = (__nv_bfloat162*)g_z1h;
        __nv_bfloat162* ol = (__nv_bfloat162*)g_z1l;
        oh[i * 2]     = __nv_bfloat162(h0, h1);
        oh[i * 2 + 1] = __nv_bfloat162(h2, h3);
        ol[i * 2]     = __nv_bfloat162(l0, l1);
        ol[i * 2 + 1] = __nv_bfloat162(l2, l3);
    }
}

// pack [W1 r0|r1|r2 | root1] transposed -> g_w1h/g_w1l [256][128] bf16
__global__ void wt1_kernel(const float* __restrict__ W1,
                           const float* __restrict__ root1) {
    int i = blockIdx.x * blockDim.x + threadIdx.x;
    if (i < 256 * 128) {
        int n = i >> 7, k = i & 127;
        float w;
        if (n < 192) {
            int r = n >> 6, j = n & 63;
            w = W1[r * 128 * 64 + k * 64 + j];
        } else {
            w = root1[k * 64 + (n - 192)];
        }
        __nv_bfloat16 h = __float2bfloat16(w);
        g_w1h[i] = h;
        g_w1l[i] = __float2bfloat16(w - __bfloat162float(h));
    }
}

// pack [W2 r0|r1|r2 | root2] transposed -> g_w2h/g_w2l [128][64] bf16
__global__ void wt2_kernel(const float* __restrict__ W2,
                           const float* __restrict__ root2) {
    int i = blockIdx.x * blockDim.x + threadIdx.x;
    if (i < 128 * 64) {
        int n = i >> 6, k = i & 63;
        float w;
        if (n < 96) {
            int r = n >> 5, j = n & 31;
            w = W2[r * 64 * 32 + k * 32 + j];
        } else {
            w = root2[k * 32 + (n - 96)];
        }
        __nv_bfloat16 h = __float2bfloat16(w);
        g_w2h[i] = h;
        g_w2l[i] = __float2bfloat16(w - __bfloat162float(h));
    }
}

__global__ void count_kernel(const int* __restrict__ dst,
                             const int* __restrict__ et, int E) {
    int e = blockIdx.x * blockDim.x + threadIdx.x;
    if (e < E) atomicAdd(&g_cnt[dst[e] * 3 + et[e]], 1);
}

__global__ void inv_kernel(int n) {
    int i = blockIdx.x * blockDim.x + threadIdx.x;
    if (i < n) g_inv[i] = 1.0f / fmaxf((float)g_cnt[i], 1.0f);
}

// ---- parallel 3-phase exclusive scan of node degrees ----------------------
__global__ void __launch_bounds__(SCAN_BS) scan1_kernel() {
    __shared__ int s[SCAN_BS];
    int t = threadIdx.x;
    int i = blockIdx.x * SCAN_BS + t;
    int d = 0;
    if (i < NN) d = g_cnt[3 * i] + g_cnt[3 * i + 1] + g_cnt[3 * i + 2];
    s[t] = d;
    __syncthreads();
#pragma unroll
    for (int o = 1; o < SCAN_BS; o <<= 1) {
        int v = (t >= o) ? s[t - o] : 0;
        __syncthreads();
        s[t] += v;
        __syncthreads();
    }
    if (i < NN) g_off[i] = s[t] - d;
    if (t == SCAN_BS - 1) g_bsum[blockIdx.x] = s[t];
}

__global__ void __launch_bounds__(512) scan2_kernel() {
    __shared__ int s[512];
    int t = threadIdx.x;
    int v0 = (t < SCAN_NB) ? g_bsum[t] : 0;
    s[t] = v0;
    __syncthreads();
#pragma unroll
    for (int o = 1; o < 512; o <<= 1) {
        int v = (t >= o) ? s[t - o] : 0;
        __syncthreads();
        s[t] += v;
        __syncthreads();
    }
    if (t < SCAN_NB) g_bpre[t] = s[t] - v0;
    if (t == 511) g_off[NN] = s[511];
}

__global__ void scan3_kernel() {
    int i = blockIdx.x * blockDim.x + threadIdx.x;
    if (i < NN) {
        int off = g_off[i] + g_bpre[i / SCAN_BS];
        g_off[i] = off;
        g_cur[i] = off;
    }
}

__global__ void scatter_kernel(const int* __restrict__ src,
                               const int* __restrict__ dst,
                               const int* __restrict__ et, int E) {
    int e = blockIdx.x * blockDim.x + threadIdx.x;
    if (e < E) {
        int pos = atomicAdd(&g_cur[dst[e]], 1);
        g_epk[pos] = (unsigned)src[e] | ((unsigned)et[e] << 20);
    }
}

// pack Wd1 [64,64] -> g_Wd1c [32,128]
__global__ void wd1c_kernel(const float* __restrict__ Wd1) {
    int i = blockIdx.x * blockDim.x + threadIdx.x;
    if (i < 32 * 128) {
        int k = i >> 7, c = i & 127;
        g_Wd1c[i] = (c < 64) ? Wd1[k * 64 + c] : Wd1[(32 + k) * 64 + (c - 64)];
    }
}

// ---------------------------------------------------------------------------
// cp.async helpers
// ---------------------------------------------------------------------------
__device__ __forceinline__ void cp_async16(void* smem_dst, const void* gmem_src) {
    unsigned saddr = (unsigned)__cvta_generic_to_shared(smem_dst);
    asm volatile("cp.async.cg.shared.global [%0], [%1], 16;\n"
                 :: "r"(saddr), "l"(gmem_src) : "memory");
}
__device__ __forceinline__ void cp_async_commit() {
    asm volatile("cp.async.commit_group;\n" ::: "memory");
}
__device__ __forceinline__ void cp_async_wait0() {
    asm volatile("cp.async.wait_group 0;\n" ::: "memory");
}

#define MMA_BF16(c, a0, a1, a2, a3, b0, b1)                                   \
    asm volatile(                                                             \
        "mma.sync.aligned.m16n8k16.row.col.f32.bf16.bf16.f32 "                \
        "{%0,%1,%2,%3}, {%4,%5,%6,%7}, {%8,%9}, {%0,%1,%2,%3};"               \
        : "+f"((c)[0]), "+f"((c)[1]), "+f"((c)[2]), "+f"((c)[3])              \
        : "r"(a0), "r"(a1), "r"(a2), "r"(a3), "r"(b0), "r"(b1))

// ---------------------------------------------------------------------------
// bf16 tensor-core GEMM core, 3-term compensated.
// Block 128x128, BK=16, 256 thr = 8 warps (4m x 2n), warp tile 32x64.
// Epilogue per 8-col n-tile: col < HCOLS -> Hd (stride HCOLS) else Zd (+bias).
// ---------------------------------------------------------------------------
template <int K, int HCOLS, int ZW>
__device__ __forceinline__ void gemm_bf16_core(
    const __nv_bfloat16* __restrict__ Ahg, const __nv_bfloat16* __restrict__ Alg,
    const __nv_bfloat16* __restrict__ Bhg, const __nv_bfloat16* __restrict__ Blg,
    float* __restrict__ Hd, float* __restrict__ Zd,
    const float* __restrict__ bias) {

    __shared__ __align__(16) __nv_bfloat16 Ah[2][128][BF_RS];
    __shared__ __align__(16) __nv_bfloat16 Al[2][128][BF_RS];
    __shared__ __align__(16) __nv_bfloat16 Bh[2][128][BF_RS];
    __shared__ __align__(16) __nv_bfloat16 Bl[2][128][BF_RS];

    const int tid = threadIdx.x, lane = tid & 31, wid = tid >> 5;
    const int wm = wid & 3, wn = wid >> 2;
    const int g = lane >> 2, tg = lane & 3;
    const int m0 = blockIdx.y * 128, n0 = blockIdx.x * 128;
    const int row = tid >> 1, ch = tid & 1;

    float acc[2][8][4] = {};

    auto issue = [&](int k0, int buf) {
        int gr = min(m0 + row, NN - 1);
        cp_async16(&Ah[buf][row][ch * 8], &Ahg[(size_t)gr * K + k0 + ch * 8]);
        cp_async16(&Al[buf][row][ch * 8], &Alg[(size_t)gr * K + k0 + ch * 8]);
        cp_async16(&Bh[buf][row][ch * 8], &Bhg[(n0 + row) * K + k0 + ch * 8]);
        cp_async16(&Bl[buf][row][ch * 8], &Blg[(n0 + row) * K + k0 + ch * 8]);
        cp_async_commit();
    };

    issue(0, 0);
    cp_async_wait0();
    __syncthreads();

    constexpr int KT = K / 16;
    int buf = 0;
#pragma unroll
    for (int kt = 0; kt < KT; kt++) {
        if (kt + 1 < KT) issue((kt + 1) * 16, buf ^ 1);

        unsigned bh[8][2], bl[8][2];
#pragma unroll
        for (int nj = 0; nj < 8; nj++) {
            int br = wn * 64 + nj * 8 + g;
            bh[nj][0] = *(const unsigned*)&Bh[buf][br][2 * tg];
            bh[nj][1] = *(const unsigned*)&Bh[buf][br][2 * tg + 8];
            bl[nj][0] = *(const unsigned*)&Bl[buf][br][2 * tg];
            bl[nj][1] = *(const unsigned*)&Bl[buf][br][2 * tg + 8];
        }
#pragma unroll
        for (int mi = 0; mi < 2; mi++) {
            int ar = wm * 32 + mi * 16 + g;
            unsigned ah0 = *(const unsigned*)&Ah[buf][ar][2 * tg];
            unsigned ah1 = *(const unsigned*)&Ah[buf][ar + 8][2 * tg];
            unsigned ah2 = *(const unsigned*)&Ah[buf][ar][2 * tg + 8];
            unsigned ah3 = *(const unsigned*)&Ah[buf][ar + 8][2 * tg + 8];
            unsigned al0 = *(const unsigned*)&Al[buf][ar][2 * tg];
            unsigned al1 = *(const unsigned*)&Al[buf][ar + 8][2 * tg];
            unsigned al2 = *(const unsigned*)&Al[buf][ar][2 * tg + 8];
            unsigned al3 = *(const unsigned*)&Al[buf][ar + 8][2 * tg + 8];
#pragma unroll
            for (int nj = 0; nj < 8; nj++) {
                MMA_BF16(acc[mi][nj], ah0, ah1, ah2, ah3, bh[nj][0], bh[nj][1]);
                MMA_BF16(acc[mi][nj], ah0, ah1, ah2, ah3, bl[nj][0], bl[nj][1]);
                MMA_BF16(acc[mi][nj], al0, al1, al2, al3, bh[nj][0], bh[nj][1]);
            }
        }

        if (kt + 1 < KT) {
            cp_async_wait0();
            __syncthreads();
            buf ^= 1;
        }
    }

#pragma unroll
    for (int mi = 0; mi < 2; mi++) {
#pragma unroll
        for (int nj = 0; nj < 8; nj++) {
            int r0 = m0 + wm * 32 + mi * 16 + g;
            int cb = n0 + wn * 64 + nj * 8 + 2 * tg;
            float* c = acc[mi][nj];
            if (cb >= HCOLS) {                   // uniform per nj (8 | HCOLS)
                int zc = cb - HCOLS;
                float bx = bias[zc], by = bias[zc + 1];
                if (r0 < NN)
                    *(float2*)&Zd[(size_t)r0 * ZW + zc] =
                        make_float2(c[0] + bx, c[1] + by);
                if (r0 + 8 < NN)
                    *(float2*)&Zd[(size_t)(r0 + 8) * ZW + zc] =
                        make_float2(c[2] + bx, c[3] + by);
            } else {
                if (r0 < NN)
                    *(float2*)&Hd[(size_t)r0 * HCOLS + cb] =
                        make_float2(c[0], c[1]);
                if (r0 + 8 < NN)
                    *(float2*)&Hd[(size_t)(r0 + 8) * HCOLS + cb] =
                        make_float2(c[2], c[3]);
            }
        }
    }
}

__global__ void __launch_bounds__(256, 2) gemm1_bf16_kernel(
    const float* __restrict__ b1) {
    gemm_bf16_core<128, 192, 64>(g_xh, g_xl, g_w1h, g_w1l, g_H1, g_Z1, b1);
}
__global__ void __launch_bounds__(256, 2) gemm2_bf16_kernel(
    const float* __restrict__ b2) {
    gemm_bf16_core<64, 96, 32>(g_z1h, g_z1l, g_w2h, g_w2l, g_H2, g_Z2, b2);
}

// ---------------------------------------------------------------------------
// fp32 FFMA2 GEMM core (UV only)
// ---------------------------------------------------------------------------
template <int NTOT, int K, int HCOLS, bool RELU>
__device__ __forceinline__ void gemm_fused_core(
    const float* __restrict__ A, const float* __restrict__ B,
    float* __restrict__ H, float* __restrict__ Z,
    const float* __restrict__ bias, int M) {

    __shared__ float As[2][16][128];
    __shared__ float Bs[2][16][128];

    const int tid = threadIdx.x;
    const int tx = tid & 15, ty = tid >> 4;
    const int m0 = blockIdx.y * 128, n0 = blockIdx.x * 128;

    float4 aReg[2];
    unsigned long long acc2[8][4] = {};

    auto loadA = [&](int k0) {
#pragma unroll
        for (int i = 0; i < 2; i++) {
            int idx = tid + i * 256;
            int row = idx >> 2, c4 = idx & 3;
            int gr = m0 + row;
            float4 v = make_float4(0.f, 0.f, 0.f, 0.f);
            if (gr < M) v = *(const float4*)&A[(size_t)gr * K + k0 + c4 * 4];
            if (RELU) {
                v.x = fmaxf(v.x, 0.f); v.y = fmaxf(v.y, 0.f);
                v.z = fmaxf(v.z, 0.f); v.w = fmaxf(v.w, 0.f);
            }
            aReg[i] = v;
        }
    };
    auto storeA = [&](int buf) {
#pragma unroll
        for (int i = 0; i < 2; i++) {
            int idx = tid + i * 256;
            int row = idx >> 2, c4 = idx & 3;
            As[buf][c4 * 4 + 0][row] = aReg[i].x;
            As[buf][c4 * 4 + 1][row] = aReg[i].y;
            As[buf][c4 * 4 + 2][row] = aReg[i].z;
            As[buf][c4 * 4 + 3][row] = aReg[i].w;
        }
    };
    auto issueB = [&](int k0, int buf) {
#pragma unroll
        for (int i = 0; i < 2; i++) {
            int idx = tid + i * 256;
            int row = idx >> 5, c4 = idx & 31;
            cp_async16(&Bs[buf][row][c4 * 4],
                       &B[(size_t)(k0 + row) * NTOT + n0 + c4 * 4]);
        }
        cp_async_commit();
    };

    constexpr int KT = K / 16;
    loadA(0);
    issueB(0, 0);
    storeA(0);
    cp_async_wait0();
    __syncthreads();

    int buf = 0;
#pragma unroll
    for (int kt = 0; kt < KT; kt++) {
        if (kt + 1 < KT) {
            loadA((kt + 1) * 16);
            issueB((kt + 1) * 16, buf ^ 1);
        }

#pragma unroll
        for (int kk = 0; kk < 16; kk++) {
            float4 a0 = *(float4*)&As[buf][kk][ty * 8];
            float4 a1 = *(float4*)&As[buf][kk][ty * 8 + 4];
            float4 b0 = *(float4*)&Bs[buf][kk][tx * 8];
            float4 b1 = *(float4*)&Bs[buf][kk][tx * 8 + 4];
            unsigned long long bb0, bb1, bb2, bb3;
            asm("mov.b64 %0, {%1, %2};" : "=l"(bb0)
                : "r"(__float_as_uint(b0.x)), "r"(__float_as_uint(b0.y)));
            asm("mov.b64 %0, {%1, %2};" : "=l"(bb1)
                : "r"(__float_as_uint(b0.z)), "r"(__float_as_uint(b0.w)));
            asm("mov.b64 %0, {%1, %2};" : "=l"(bb2)
                : "r"(__float_as_uint(b1.x)), "r"(__float_as_uint(b1.y)));
            asm("mov.b64 %0, {%1, %2};" : "=l"(bb3)
                : "r"(__float_as_uint(b1.z)), "r"(__float_as_uint(b1.w)));
            float av[8] = {a0.x, a0.y, a0.z, a0.w, a1.x, a1.y, a1.z, a1.w};
#pragma unroll
            for (int i = 0; i < 8; i++) {
                unsigned long long pa;
                asm("mov.b64 %0, {%1, %1};"
                    : "=l"(pa) : "r"(__float_as_uint(av[i])));
                asm("fma.rn.f32x2 %0, %1, %2, %0;"
                    : "+l"(acc2[i][0]) : "l"(pa), "l"(bb0));
                asm("fma.rn.f32x2 %0, %1, %2, %0;"
                    : "+l"(acc2[i][1]) : "l"(pa), "l"(bb1));
                asm("fma.rn.f32x2 %0, %1, %2, %0;"
                    : "+l"(acc2[i][2]) : "l"(pa), "l"(bb2));
                asm("fma.rn.f32x2 %0, %1, %2, %0;"
                    : "+l"(acc2[i][3]) : "l"(pa), "l"(bb3));
            }
        }

        if (kt + 1 < KT) {
            storeA(buf ^ 1);
            cp_async_wait0();
            __syncthreads();
            buf ^= 1;
        }
    }

    float acc[8][8];
#pragma unroll
    for (int i = 0; i < 8; i++)
#pragma unroll
        for (int jp = 0; jp < 4; jp++) {
            unsigned lo, hi;
            asm("mov.b64 {%0, %1}, %2;" : "=r"(lo), "=r"(hi) : "l"(acc2[i][jp]));
            acc[i][jp * 2]     = __uint_as_float(lo);
            acc[i][jp * 2 + 1] = __uint_as_float(hi);
        }

    const int cb = n0 + tx * 8;
    if (cb < HCOLS) {
#pragma unroll
        for (int i = 0; i < 8; i++) {
            int gr = m0 + ty * 8 + i;
            if (gr < M) {
                *(float4*)&H[(size_t)gr * HCOLS + cb] =
                    make_float4(acc[i][0], acc[i][1], acc[i][2], acc[i][3]);
                *(float4*)&H[(size_t)gr * HCOLS + cb + 4] =
                    make_float4(acc[i][4], acc[i][5], acc[i][6], acc[i][7]);
            }
        }
    }
}

__global__ void __launch_bounds__(256, 2) gemm_uv_kernel(const float* __restrict__ dummy_bias) {
    gemm_fused_core<128, 32, 128, false>(g_Z2, g_Wd1c, g_UV, g_UV, dummy_bias, NN);
}

// ---------------------------------------------------------------------------
// CSR warp-per-node aggregation, NO atomics, unroll-4.
// ---------------------------------------------------------------------------
__global__ void __launch_bounds__(256) agg1_csr_kernel() {
    int d = (blockIdx.x * blockDim.x + threadIdx.x) >> 5;
    int lane = threadIdx.x & 31;
    if (d >= NN) return;
    int beg = g_off[d], end = g_off[d + 1];
    if (beg == end) return;
    float i0 = g_inv[3 * d], i1 = g_inv[3 * d + 1], i2 = g_inv[3 * d + 2];

    float2 acc = make_float2(0.f, 0.f);
    int i = beg;
    for (; i + 3 < end; i += 4) {
        unsigned v0 = g_epk[i],     v1 = g_epk[i + 1];
        unsigned v2 = g_epk[i + 2], v3 = g_epk[i + 3];
        int s0 = v0 & 0xFFFFF, r0 = v0 >> 20;
        int s1 = v1 & 0xFFFFF, r1 = v1 >> 20;
        int s2 = v2 & 0xFFFFF, r2 = v2 >> 20;
        int s3 = v3 & 0xFFFFF, r3 = v3 >> 20;
        float c0 = (r0 == 0) ? i0 : ((r0 == 1) ? i1 : i2);
        float c1 = (r1 == 0) ? i0 : ((r1 == 1) ? i1 : i2);
        float c2 = (r2 == 0) ? i0 : ((r2 == 1) ? i1 : i2);
        float c3 = (r3 == 0) ? i0 : ((r3 == 1) ? i1 : i2);
        float2 h0 = *(const float2*)&g_H1[(size_t)s0 * 192 + r0 * 64 + lane * 2];
        float2 h1 = *(const float2*)&g_H1[(size_t)s1 * 192 + r1 * 64 + lane * 2];
        float2 h2 = *(const float2*)&g_H1[(size_t)s2 * 192 + r2 * 64 + lane * 2];
        float2 h3 = *(const float2*)&g_H1[(size_t)s3 * 192 + r3 * 64 + lane * 2];
        acc.x += h0.x * c0 + h1.x * c1 + h2.x * c2 + h3.x * c3;
        acc.y += h0.y * c0 + h1.y * c1 + h2.y * c2 + h3.y * c3;
    }
    for (; i < end; i++) {
        unsigned v = g_epk[i];
        int s = v & 0xFFFFF, r = v >> 20;
        float sc = (r == 0) ? i0 : ((r == 1) ? i1 : i2);
        float2 h = *(const float2*)&g_H1[(size_t)s * 192 + r * 64 + lane * 2];
        acc.x += h.x * sc; acc.y += h.y * sc;
    }
    float2 z = *(float2*)&g_Z1[(size_t)d * 64 + lane * 2];
    z.x += acc.x; z.y += acc.y;
    *(float2*)&g_Z1[(size_t)d * 64 + lane * 2] = z;
}

__global__ void __launch_bounds__(256) agg2_csr_kernel() {
    int d = (blockIdx.x * blockDim.x + threadIdx.x) >> 5;
    int lane = threadIdx.x & 31;
    if (d >= NN) return;
    int beg = g_off[d], end = g_off[d + 1];
    if (beg == end) return;
    float i0 = g_inv[3 * d], i1 = g_inv[3 * d + 1], i2 = g_inv[3 * d + 2];

    float acc = 0.f;
    int i = beg;
    for (; i + 3 < end; i += 4) {
        unsigned v0 = g_epk[i],     v1 = g_epk[i + 1];
        unsigned v2 = g_epk[i + 2], v3 = g_epk[i + 3];
        int s0 = v0 & 0xFFFFF, r0 = v0 >> 20;
        int s1 = v1 & 0xFFFFF, r1 = v1 >> 20;
        int s2 = v2 & 0xFFFFF, r2 = v2 >> 20;
        int s3 = v3 & 0xFFFFF, r3 = v3 >> 20;
        float c0 = (r0 == 0) ? i0 : ((r0 == 1) ? i1 : i2);
        float c1 = (r1 == 0) ? i0 : ((r1 == 1) ? i1 : i2);
        float c2 = (r2 == 0) ? i0 : ((r2 == 1) ? i1 : i2);
        float c3 = (r3 == 0) ? i0 : ((r3 == 1) ? i1 : i2);
        float h0 = g_H2[(size_t)s0 * 96 + r0 * 32 + lane];
        float h1 = g_H2[(size_t)s1 * 96 + r1 * 32 + lane];
        float h2 = g_H2[(size_t)s2 * 96 + r2 * 32 + lane];
        float h3 = g_H2[(size_t)s3 * 96 + r3 * 32 + lane];
        acc += h0 * c0 + h1 * c1 + h2 * c2 + h3 * c3;
    }
    for (; i < end; i++) {
        unsigned v = g_epk[i];
        int s = v & 0xFFFFF, r = v >> 20;
        float sc = (r == 0) ? i0 : ((r == 1) ? i1 : i2);
        acc += g_H2[(size_t)s * 96 + r * 32 + lane] * sc;
    }
    g_Z2[(size_t)d * 32 + lane] += acc;
}

// ---------------------------------------------------------------------------
// per-edge decoder: out[p] = relu(U[s] + V[d] + bd1) . Wd2 + bd2
// ---------------------------------------------------------------------------
__global__ void __launch_bounds__(256) decoder2_kernel(
    const int* __restrict__ psrc, const int* __restrict__ pdst,
    const float* __restrict__ bd1, const float* __restrict__ Wd2,
    const float* __restrict__ bd2, float* __restrict__ out, int P) {
    __shared__ float sB1[64];
    __shared__ float sW2[64];
    int tid = threadIdx.x;
    if (tid < 64) { sB1[tid] = bd1[tid]; sW2[tid] = Wd2[tid]; }
    __syncthreads();

    int p = blockIdx.x * 256 + tid;
    if (p >= P) return;
    int s = psrc[p], d = pdst[p];
    const float* u = &g_UV[(size_t)s * 128];
    const float* v = &g_UV[(size_t)d * 128 + 64];

    float o = bd2[0];
#pragma unroll
    for (int q = 0; q < 16; q++) {
        float4 uu = *(const float4*)&u[q * 4];
        float4 vv = *(const float4*)&v[q * 4];
        float4 bb = *(const float4*)&sB1[q * 4];
        float4 ww = *(const float4*)&sW2[q * 4];
        o += fmaxf(uu.x + vv.x + bb.x, 0.f) * ww.x;
        o += fmaxf(uu.y + vv.y + bb.y, 0.f) * ww.y;
        o += fmaxf(uu.z + vv.z + bb.z, 0.f) * ww.z;
        o += fmaxf(uu.w + vv.w + bb.w, 0.f) * ww.w;
    }
    out[p] = o;
}

// ---------------------------------------------------------------------------
extern "C" void kernel_launch(void* const* d_in, const int* in_sizes, int n_in,
                              void* d_out, int out_size) {
    const float* x     = (const float*)d_in[0];
    const int*   ei    = (const int*)d_in[1];
    const int*   et    = (const int*)d_in[2];
    const int*   pe    = (const int*)d_in[3];
    const float* W1    = (const float*)d_in[4];
    const float* root1 = (const float*)d_in[5];
    const float* b1    = (const float*)d_in[6];
    const float* W2    = (const float*)d_in[7];
    const float* root2 = (const float*)d_in[8];
    const float* b2    = (const float*)d_in[9];
    const float* Wd1   = (const float*)d_in[10];
    const float* bd1   = (const float*)d_in[11];
    const float* Wd2   = (const float*)d_in[12];
    const float* bd2   = (const float*)d_in[13];
    float* out = (float*)d_out;

    const int E = in_sizes[1] / 2;
    const int P = in_sizes[3] / 2;
    const int* src = ei;
    const int* dst = ei + E;
    const int* ps  = pe;
    const int* pd  = pe + P;

    // index 3 = gemm1_bf16 (ncu capture slot)
    zero_cnt_kernel<<<(NN * 3 + 255) / 256, 256>>>(NN * 3);
    splitx_kernel<<<(NN * 32 + 255) / 256, 256>>>(x);
    wt1_kernel<<<(256 * 128 + 255) / 256, 256>>>(W1, root1);
    {
        dim3 g(2, (NN + 127) / 128);
        gemm1_bf16_kernel<<<g, 256>>>(b1);
    }
    wt2_kernel<<<(128 * 64 + 255) / 256, 256>>>(W2, root2);
    wd1c_kernel<<<(32 * 128 + 255) / 256, 256>>>(Wd1);

    // counts + inverse means + CSR (shared by both layers)
    count_kernel<<<(E + 255) / 256, 256>>>(dst, et, E);
    inv_kernel<<<(NN * 3 + 255) / 256, 256>>>(NN * 3);
    scan1_kernel<<<SCAN_NB, SCAN_BS>>>();
    scan2_kernel<<<1, 512>>>();
    scan3_kernel<<<(NN + 255) / 256, 256>>>();
    scatter_kernel<<<(E + 255) / 256, 256>>>(src, dst, et, E);

    // layer 1 aggregation, then relu+split Z1 for tensor-core layer 2
    agg1_csr_kernel<<<(NN * 32 + 255) / 256, 256>>>();
    splitz1_kernel<<<(NN * 16 + 255) / 256, 256>>>();

    // layer 2 (bf16 tensor core)
    {
        dim3 g(1, (NN + 127) / 128);
        gemm2_bf16_kernel<<<g, 256>>>(b2);
    }
    agg2_csr_kernel<<<(NN * 32 + 255) / 256, 256>>>();

    // decoder: per-node GEMM (UV), then cheap per-edge kernel
    {
        dim3 g(1, (NN + 127) / 128);
        gemm_uv_kernel<<<g, 256>>>(bd1);
    }
    decoder2_kernel<<<(P + 255) / 256, 256>>>(ps, pd, bd1, Wd2, bd2, out, P);
}

// round 12
// speedup vs baseline: 2.1533x; 1.0311x over previous
#include <cuda_runtime.h>
#include <cuda_bf16.h>

// ---------------------------------------------------------------------------
// RGCN link predictor:
//   split x -> bf16 hi/lo; GEMM1 + GEMM2 = tensor-core bf16 3-term compensated
//   (ldmatrix fragment loads), fused H/Z epilogues; prep: counts/inv/scan/CSR;
//   CSR warp-per-node agg (no atomics, unroll-4, agg1 fuses relu+bf16 split);
//   decoder decomposed (UV GEMM fp32 + cheap per-edge kernel).
// __device__ globals only referenced from device code (round-3 lesson).
// ---------------------------------------------------------------------------

#define NN    100000
#define REL   3
#define EMAX  1600000
#define SCAN_BS   256
#define SCAN_NB   ((NN + SCAN_BS - 1) / SCAN_BS)   // 391
#define BF_RS 24   // bf16 smem row stride (48 B): 16B-aligned + conflict-free

// scratch (static device globals; no allocation allowed)
__device__ int      g_cnt[NN * REL];
__device__ float    g_inv[NN * REL];
__device__ int      g_off[NN + 1];
__device__ int      g_cur[NN];
__device__ int      g_bsum[SCAN_NB];
__device__ int      g_bpre[SCAN_NB];
__device__ unsigned g_epk[EMAX];     // src | (rel << 20), sorted by dst
__device__ float    g_H1[NN * 192];
__device__ float    g_Z1[NN * 64];
__device__ float    g_H2[NN * 96];
__device__ float    g_Z2[NN * 32];
__device__ float    g_UV[NN * 128];  // cols 0-63: U, 64-127: V
__device__ float    g_Wd1c[32 * 128];
__device__ __nv_bfloat16 g_xh[(size_t)NN * 128];
__device__ __nv_bfloat16 g_xl[(size_t)NN * 128];
__device__ __nv_bfloat16 g_z1h[(size_t)NN * 64];
__device__ __nv_bfloat16 g_z1l[(size_t)NN * 64];
__device__ __nv_bfloat16 g_w1h[256 * 128];   // [n][k] transposed
__device__ __nv_bfloat16 g_w1l[256 * 128];
__device__ __nv_bfloat16 g_w2h[128 * 64];    // [n][k] transposed
__device__ __nv_bfloat16 g_w2l[128 * 64];

// ---------------------------------------------------------------------------
__global__ void zero_cnt_kernel(int n) {
    int i = blockIdx.x * blockDim.x + threadIdx.x;
    if (i < n) g_cnt[i] = 0;
}

// split x into bf16 hi + lo
__global__ void splitx_kernel(const float* __restrict__ x) {
    int i = blockIdx.x * blockDim.x + threadIdx.x;   // one float4
    if (i < NN * 32) {
        float4 v = ((const float4*)x)[i];
        __nv_bfloat16 h0 = __float2bfloat16(v.x), h1 = __float2bfloat16(v.y);
        __nv_bfloat16 h2 = __float2bfloat16(v.z), h3 = __float2bfloat16(v.w);
        __nv_bfloat16 l0 = __float2bfloat16(v.x - __bfloat162float(h0));
        __nv_bfloat16 l1 = __float2bfloat16(v.y - __bfloat162float(h1));
        __nv_bfloat16 l2 = __float2bfloat16(v.z - __bfloat162float(h2));
        __nv_bfloat16 l3 = __float2bfloat16(v.w - __bfloat162float(h3));
        __nv_bfloat162* oh = (__nv_bfloat162*)g_xh;
        __nv_bfloat162* ol = (__nv_bfloat162*)g_xl;
        oh[i * 2]     = __nv_bfloat162(h0, h1);
        oh[i * 2 + 1] = __nv_bfloat162(h2, h3);
        ol[i * 2]     = __nv_bfloat162(l0, l1);
        ol[i * 2 + 1] = __nv_bfloat162(l2, l3);
    }
}

// pack [W1 r0|r1|r2 | root1] transposed -> g_w1h/g_w1l [256][128] bf16
__global__ void wt1_kernel(const float* __restrict__ W1,
                           const float* __restrict__ root1) {
    int i = blockIdx.x * blockDim.x + threadIdx.x;
    if (i < 256 * 128) {
        int n = i >> 7, k = i & 127;
        float w;
        if (n < 192) {
            int r = n >> 6, j = n & 63;
            w = W1[r * 128 * 64 + k * 64 + j];
        } else {
            w = root1[k * 64 + (n - 192)];
        }
        __nv_bfloat16 h = __float2bfloat16(w);
        g_w1h[i] = h;
        g_w1l[i] = __float2bfloat16(w - __bfloat162float(h));
    }
}

// pack [W2 r0|r1|r2 | root2] transposed -> g_w2h/g_w2l [128][64] bf16
__global__ void wt2_kernel(const float* __restrict__ W2,
                           const float* __restrict__ root2) {
    int i = blockIdx.x * blockDim.x + threadIdx.x;
    if (i < 128 * 64) {
        int n = i >> 6, k = i & 63;
        float w;
        if (n < 96) {
            int r = n >> 5, j = n & 31;
            w = W2[r * 64 * 32 + k * 32 + j];
        } else {
            w = root2[k * 32 + (n - 96)];
        }
        __nv_bfloat16 h = __float2bfloat16(w);
        g_w2h[i] = h;
        g_w2l[i] = __float2bfloat16(w - __bfloat162float(h));
    }
}

__global__ void count_kernel(const int* __restrict__ dst,
                             const int* __restrict__ et, int E) {
    int e = blockIdx.x * blockDim.x + threadIdx.x;
    if (e < E) atomicAdd(&g_cnt[dst[e] * 3 + et[e]], 1);
}

__global__ void inv_kernel(int n) {
    int i = blockIdx.x * blockDim.x + threadIdx.x;
    if (i < n) g_inv[i] = 1.0f / fmaxf((float)g_cnt[i], 1.0f);
}

// ---- parallel 3-phase exclusive scan of node degrees ----------------------
__global__ void __launch_bounds__(SCAN_BS) scan1_kernel() {
    __shared__ int s[SCAN_BS];
    int t = threadIdx.x;
    int i = blockIdx.x * SCAN_BS + t;
    int d = 0;
    if (i < NN) d = g_cnt[3 * i] + g_cnt[3 * i + 1] + g_cnt[3 * i + 2];
    s[t] = d;
    __syncthreads();
#pragma unroll
    for (int o = 1; o < SCAN_BS; o <<= 1) {
        int v = (t >= o) ? s[t - o] : 0;
        __syncthreads();
        s[t] += v;
        __syncthreads();
    }
    if (i < NN) g_off[i] = s[t] - d;
    if (t == SCAN_BS - 1) g_bsum[blockIdx.x] = s[t];
}

__global__ void __launch_bounds__(512) scan2_kernel() {
    __shared__ int s[512];
    int t = threadIdx.x;
    int v0 = (t < SCAN_NB) ? g_bsum[t] : 0;
    s[t] = v0;
    __syncthreads();
#pragma unroll
    for (int o = 1; o < 512; o <<= 1) {
        int v = (t >= o) ? s[t - o] : 0;
        __syncthreads();
        s[t] += v;
        __syncthreads();
    }
    if (t < SCAN_NB) g_bpre[t] = s[t] - v0;
    if (t == 511) g_off[NN] = s[511];
}

__global__ void scan3_kernel() {
    int i = blockIdx.x * blockDim.x + threadIdx.x;
    if (i < NN) {
        int off = g_off[i] + g_bpre[i / SCAN_BS];
        g_off[i] = off;
        g_cur[i] = off;
    }
}

__global__ void scatter_kernel(const int* __restrict__ src,
                               const int* __restrict__ dst,
                               const int* __restrict__ et, int E) {
    int e = blockIdx.x * blockDim.x + threadIdx.x;
    if (e < E) {
        int pos = atomicAdd(&g_cur[dst[e]], 1);
        g_epk[pos] = (unsigned)src[e] | ((unsigned)et[e] << 20);
    }
}

// pack Wd1 [64,64] -> g_Wd1c [32,128]
__global__ void wd1c_kernel(const float* __restrict__ Wd1) {
    int i = blockIdx.x * blockDim.x + threadIdx.x;
    if (i < 32 * 128) {
        int k = i >> 7, c = i & 127;
        g_Wd1c[i] = (c < 64) ? Wd1[k * 64 + c] : Wd1[(32 + k) * 64 + (c - 64)];
    }
}

// ---------------------------------------------------------------------------
// cp.async / ldmatrix helpers
// ---------------------------------------------------------------------------
__device__ __forceinline__ void cp_async16(void* smem_dst, const void* gmem_src) {
    unsigned saddr = (unsigned)__cvta_generic_to_shared(smem_dst);
    asm volatile("cp.async.cg.shared.global [%0], [%1], 16;\n"
                 :: "r"(saddr), "l"(gmem_src) : "memory");
}
__device__ __forceinline__ void cp_async_commit() {
    asm volatile("cp.async.commit_group;\n" ::: "memory");
}
__device__ __forceinline__ void cp_async_wait0() {
    asm volatile("cp.async.wait_group 0;\n" ::: "memory");
}
__device__ __forceinline__ void ldsm_x4(unsigned& r0, unsigned& r1,
                                        unsigned& r2, unsigned& r3,
                                        const void* p) {
    unsigned addr = (unsigned)__cvta_generic_to_shared(p);
    asm volatile("ldmatrix.sync.aligned.m8n8.x4.shared.b16 {%0,%1,%2,%3}, [%4];"
                 : "=r"(r0), "=r"(r1), "=r"(r2), "=r"(r3) : "r"(addr));
}

#define MMA_BF16(c, a0, a1, a2, a3, b0, b1)                                   \
    asm volatile(                                                             \
        "mma.sync.aligned.m16n8k16.row.col.f32.bf16.bf16.f32 "                \
        "{%0,%1,%2,%3}, {%4,%5,%6,%7}, {%8,%9}, {%0,%1,%2,%3};"               \
        : "+f"((c)[0]), "+f"((c)[1]), "+f"((c)[2]), "+f"((c)[3])              \
        : "r"(a0), "r"(a1), "r"(a2), "r"(a3), "r"(b0), "r"(b1))

// ---------------------------------------------------------------------------
// bf16 tensor-core GEMM core, 3-term compensated, ldmatrix fragment loads.
// Block 128x128, BK=16, 256 thr = 8 warps (4m x 2n), warp tile 32x64.
// Epilogue per 8-col n-tile: col < HCOLS -> Hd (stride HCOLS) else Zd (+bias).
// ---------------------------------------------------------------------------
template <int K, int HCOLS, int ZW>
__device__ __forceinline__ void gemm_bf16_core(
    const __nv_bfloat16* __restrict__ Ahg, const __nv_bfloat16* __restrict__ Alg,
    const __nv_bfloat16* __restrict__ Bhg, const __nv_bfloat16* __restrict__ Blg,
    float* __restrict__ Hd, float* __restrict__ Zd,
    const float* __restrict__ bias) {

    __shared__ __align__(16) __nv_bfloat16 Ah[2][128][BF_RS];
    __shared__ __align__(16) __nv_bfloat16 Al[2][128][BF_RS];
    __shared__ __align__(16) __nv_bfloat16 Bh[2][128][BF_RS];
    __shared__ __align__(16) __nv_bfloat16 Bl[2][128][BF_RS];

    const int tid = threadIdx.x, lane = tid & 31, wid = tid >> 5;
    const int wm = wid & 3, wn = wid >> 2;
    const int g = lane >> 2, tg = lane & 3;
    const int m0 = blockIdx.y * 128, n0 = blockIdx.x * 128;
    const int row = tid >> 1, ch = tid & 1;

    // ldmatrix per-lane address components
    const int aRow = lane & 15, aK = (lane >> 4) * 8;            // A tiles
    const int bRow = ((lane >> 4) * 8) + (lane & 7);             // B nj-pair
    const int bK = ((lane >> 3) & 1) * 8;

    float acc[2][8][4] = {};

    auto issue = [&](int k0, int buf) {
        int gr = min(m0 + row, NN - 1);
        cp_async16(&Ah[buf][row][ch * 8], &Ahg[(size_t)gr * K + k0 + ch * 8]);
        cp_async16(&Al[buf][row][ch * 8], &Alg[(size_t)gr * K + k0 + ch * 8]);
        cp_async16(&Bh[buf][row][ch * 8], &Bhg[(n0 + row) * K + k0 + ch * 8]);
        cp_async16(&Bl[buf][row][ch * 8], &Blg[(n0 + row) * K + k0 + ch * 8]);
        cp_async_commit();
    };

    issue(0, 0);
    cp_async_wait0();
    __syncthreads();

    constexpr int KT = K / 16;
    int buf = 0;
#pragma unroll
    for (int kt = 0; kt < KT; kt++) {
        if (kt + 1 < KT) issue((kt + 1) * 16, buf ^ 1);

        unsigned bh[8][2], bl[8][2];
#pragma unroll
        for (int njp = 0; njp < 4; njp++) {
            int nb = wn * 64 + njp * 16 + bRow;
            ldsm_x4(bh[njp * 2][0], bh[njp * 2][1],
                    bh[njp * 2 + 1][0], bh[njp * 2 + 1][1], &Bh[buf][nb][bK]);
            ldsm_x4(bl[njp * 2][0], bl[njp * 2][1],
                    bl[njp * 2 + 1][0], bl[njp * 2 + 1][1], &Bl[buf][nb][bK]);
        }
#pragma unroll
        for (int mi = 0; mi < 2; mi++) {
            int ar = wm * 32 + mi * 16 + aRow;
            unsigned ah0, ah1, ah2, ah3, al0, al1, al2, al3;
            ldsm_x4(ah0, ah1, ah2, ah3, &Ah[buf][ar][aK]);
            ldsm_x4(al0, al1, al2, al3, &Al[buf][ar][aK]);
#pragma unroll
            for (int nj = 0; nj < 8; nj++) {
                MMA_BF16(acc[mi][nj], ah0, ah1, ah2, ah3, bh[nj][0], bh[nj][1]);
                MMA_BF16(acc[mi][nj], ah0, ah1, ah2, ah3, bl[nj][0], bl[nj][1]);
                MMA_BF16(acc[mi][nj], al0, al1, al2, al3, bh[nj][0], bh[nj][1]);
            }
        }

        if (kt + 1 < KT) {
            cp_async_wait0();
            __syncthreads();
            buf ^= 1;
        }
    }

#pragma unroll
    for (int mi = 0; mi < 2; mi++) {
#pragma unroll
        for (int nj = 0; nj < 8; nj++) {
            int r0 = m0 + wm * 32 + mi * 16 + g;
            int cb = n0 + wn * 64 + nj * 8 + 2 * tg;
            float* c = acc[mi][nj];
            if (cb >= HCOLS) {                   // uniform per nj (8 | HCOLS)
                int zc = cb - HCOLS;
                float bx = bias[zc], by = bias[zc + 1];
                if (r0 < NN)
                    *(float2*)&Zd[(size_t)r0 * ZW + zc] =
                        make_float2(c[0] + bx, c[1] + by);
                if (r0 + 8 < NN)
                    *(float2*)&Zd[(size_t)(r0 + 8) * ZW + zc] =
                        make_float2(c[2] + bx, c[3] + by);
            } else {
                if (r0 < NN)
                    *(float2*)&Hd[(size_t)r0 * HCOLS + cb] =
                        make_float2(c[0], c[1]);
                if (r0 + 8 < NN)
                    *(float2*)&Hd[(size_t)(r0 + 8) * HCOLS + cb] =
                        make_float2(c[2], c[3]);
            }
        }
    }
}

__global__ void __launch_bounds__(256, 2) gemm1_bf16_kernel(
    const float* __restrict__ b1) {
    gemm_bf16_core<128, 192, 64>(g_xh, g_xl, g_w1h, g_w1l, g_H1, g_Z1, b1);
}
__global__ void __launch_bounds__(256, 2) gemm2_bf16_kernel(
    const float* __restrict__ b2) {
    gemm_bf16_core<64, 96, 32>(g_z1h, g_z1l, g_w2h, g_w2l, g_H2, g_Z2, b2);
}

// ---------------------------------------------------------------------------
// fp32 FFMA2 GEMM core (UV only)
// ---------------------------------------------------------------------------
template <int NTOT, int K, int HCOLS, bool RELU>
__device__ __forceinline__ void gemm_fused_core(
    const float* __restrict__ A, const float* __restrict__ B,
    float* __restrict__ H, float* __restrict__ Z,
    const float* __restrict__ bias, int M) {

    __shared__ float As[2][16][128];
    __shared__ float Bs[2][16][128];

    const int tid = threadIdx.x;
    const int tx = tid & 15, ty = tid >> 4;
    const int m0 = blockIdx.y * 128, n0 = blockIdx.x * 128;

    float4 aReg[2];
    unsigned long long acc2[8][4] = {};

    auto loadA = [&](int k0) {
#pragma unroll
        for (int i = 0; i < 2; i++) {
            int idx = tid + i * 256;
            int row = idx >> 2, c4 = idx & 3;
            int gr = m0 + row;
            float4 v = make_float4(0.f, 0.f, 0.f, 0.f);
            if (gr < M) v = *(const float4*)&A[(size_t)gr * K + k0 + c4 * 4];
            if (RELU) {
                v.x = fmaxf(v.x, 0.f); v.y = fmaxf(v.y, 0.f);
                v.z = fmaxf(v.z, 0.f); v.w = fmaxf(v.w, 0.f);
            }
            aReg[i] = v;
        }
    };
    auto storeA = [&](int buf) {
#pragma unroll
        for (int i = 0; i < 2; i++) {
            int idx = tid + i * 256;
            int row = idx >> 2, c4 = idx & 3;
            As[buf][c4 * 4 + 0][row] = aReg[i].x;
            As[buf][c4 * 4 + 1][row] = aReg[i].y;
            As[buf][c4 * 4 + 2][row] = aReg[i].z;
            As[buf][c4 * 4 + 3][row] = aReg[i].w;
        }
    };
    auto issueB = [&](int k0, int buf) {
#pragma unroll
        for (int i = 0; i < 2; i++) {
            int idx = tid + i * 256;
            int row = idx >> 5, c4 = idx & 31;
            cp_async16(&Bs[buf][row][c4 * 4],
                       &B[(size_t)(k0 + row) * NTOT + n0 + c4 * 4]);
        }
        cp_async_commit();
    };

    constexpr int KT = K / 16;
    loadA(0);
    issueB(0, 0);
    storeA(0);
    cp_async_wait0();
    __syncthreads();

    int buf = 0;
#pragma unroll
    for (int kt = 0; kt < KT; kt++) {
        if (kt + 1 < KT) {
            loadA((kt + 1) * 16);
            issueB((kt + 1) * 16, buf ^ 1);
        }

#pragma unroll
        for (int kk = 0; kk < 16; kk++) {
            float4 a0 = *(float4*)&As[buf][kk][ty * 8];
            float4 a1 = *(float4*)&As[buf][kk][ty * 8 + 4];
            float4 b0 = *(float4*)&Bs[buf][kk][tx * 8];
            float4 b1 = *(float4*)&Bs[buf][kk][tx * 8 + 4];
            unsigned long long bb0, bb1, bb2, bb3;
            asm("mov.b64 %0, {%1, %2};" : "=l"(bb0)
                : "r"(__float_as_uint(b0.x)), "r"(__float_as_uint(b0.y)));
            asm("mov.b64 %0, {%1, %2};" : "=l"(bb1)
                : "r"(__float_as_uint(b0.z)), "r"(__float_as_uint(b0.w)));
            asm("mov.b64 %0, {%1, %2};" : "=l"(bb2)
                : "r"(__float_as_uint(b1.x)), "r"(__float_as_uint(b1.y)));
            asm("mov.b64 %0, {%1, %2};" : "=l"(bb3)
                : "r"(__float_as_uint(b1.z)), "r"(__float_as_uint(b1.w)));
            float av[8] = {a0.x, a0.y, a0.z, a0.w, a1.x, a1.y, a1.z, a1.w};
#pragma unroll
            for (int i = 0; i < 8; i++) {
                unsigned long long pa;
                asm("mov.b64 %0, {%1, %1};"
                    : "=l"(pa) : "r"(__float_as_uint(av[i])));
                asm("fma.rn.f32x2 %0, %1, %2, %0;"
                    : "+l"(acc2[i][0]) : "l"(pa), "l"(bb0));
                asm("fma.rn.f32x2 %0, %1, %2, %0;"
                    : "+l"(acc2[i][1]) : "l"(pa), "l"(bb1));
                asm("fma.rn.f32x2 %0, %1, %2, %0;"
                    : "+l"(acc2[i][2]) : "l"(pa), "l"(bb2));
                asm("fma.rn.f32x2 %0, %1, %2, %0;"
                    : "+l"(acc2[i][3]) : "l"(pa), "l"(bb3));
            }
        }

        if (kt + 1 < KT) {
            storeA(buf ^ 1);
            cp_async_wait0();
            __syncthreads();
            buf ^= 1;
        }
    }

    float acc[8][8];
#pragma unroll
    for (int i = 0; i < 8; i++)
#pragma unroll
        for (int jp = 0; jp < 4; jp++) {
            unsigned lo, hi;
            asm("mov.b64 {%0, %1}, %2;" : "=r"(lo), "=r"(hi) : "l"(acc2[i][jp]));
            acc[i][jp * 2]     = __uint_as_float(lo);
            acc[i][jp * 2 + 1] = __uint_as_float(hi);
        }

    const int cb = n0 + tx * 8;
    if (cb < HCOLS) {
#pragma unroll
        for (int i = 0; i < 8; i++) {
            int gr = m0 + ty * 8 + i;
            if (gr < M) {
                *(float4*)&H[(size_t)gr * HCOLS + cb] =
                    make_float4(acc[i][0], acc[i][1], acc[i][2], acc[i][3]);
                *(float4*)&H[(size_t)gr * HCOLS + cb + 4] =
                    make_float4(acc[i][4], acc[i][5], acc[i][6], acc[i][7]);
            }
        }
    }
}

__global__ void __launch_bounds__(256, 2) gemm_uv_kernel(const float* __restrict__ dummy_bias) {
    gemm_fused_core<128, 32, 128, false>(g_Z2, g_Wd1c, g_UV, g_UV, dummy_bias, NN);
}

// ---------------------------------------------------------------------------
// CSR warp-per-node aggregation, NO atomics, unroll-4.
// agg1 fuses: Z1 += acc, relu, bf16 hi/lo split -> g_z1h/g_z1l.
// ---------------------------------------------------------------------------
__global__ void __launch_bounds__(256) agg1_csr_kernel() {
    int d = (blockIdx.x * blockDim.x + threadIdx.x) >> 5;
    int lane = threadIdx.x & 31;
    if (d >= NN) return;
    int beg = g_off[d], end = g_off[d + 1];
    float i0 = g_inv[3 * d], i1 = g_inv[3 * d + 1], i2 = g_inv[3 * d + 2];

    float2 acc = make_float2(0.f, 0.f);
    int i = beg;
    for (; i + 3 < end; i += 4) {
        unsigned v0 = g_epk[i],     v1 = g_epk[i + 1];
        unsigned v2 = g_epk[i + 2], v3 = g_epk[i + 3];
        int s0 = v0 & 0xFFFFF, r0 = v0 >> 20;
        int s1 = v1 & 0xFFFFF, r1 = v1 >> 20;
        int s2 = v2 & 0xFFFFF, r2 = v2 >> 20;
        int s3 = v3 & 0xFFFFF, r3 = v3 >> 20;
        float c0 = (r0 == 0) ? i0 : ((r0 == 1) ? i1 : i2);
        float c1 = (r1 == 0) ? i0 : ((r1 == 1) ? i1 : i2);
        float c2 = (r2 == 0) ? i0 : ((r2 == 1) ? i1 : i2);
        float c3 = (r3 == 0) ? i0 : ((r3 == 1) ? i1 : i2);
        float2 h0 = *(const float2*)&g_H1[(size_t)s0 * 192 + r0 * 64 + lane * 2];
        float2 h1 = *(const float2*)&g_H1[(size_t)s1 * 192 + r1 * 64 + lane * 2];
        float2 h2 = *(const float2*)&g_H1[(size_t)s2 * 192 + r2 * 64 + lane * 2];
        float2 h3 = *(const float2*)&g_H1[(size_t)s3 * 192 + r3 * 64 + lane * 2];
        acc.x += h0.x * c0 + h1.x * c1 + h2.x * c2 + h3.x * c3;
        acc.y += h0.y * c0 + h1.y * c1 + h2.y * c2 + h3.y * c3;
    }
    for (; i < end; i++) {
        unsigned v = g_epk[i];
        int s = v & 0xFFFFF, r = v >> 20;
        float sc = (r == 0) ? i0 : ((r == 1) ? i1 : i2);
        float2 h = *(const float2*)&g_H1[(size_t)s * 192 + r * 64 + lane * 2];
        acc.x += h.x * sc; acc.y += h.y * sc;
    }
    float2 z = *(const float2*)&g_Z1[(size_t)d * 64 + lane * 2];
    float zx = fmaxf(z.x + acc.x, 0.f);
    float zy = fmaxf(z.y + acc.y, 0.f);
    __nv_bfloat16 hx = __float2bfloat16(zx), hy = __float2bfloat16(zy);
    __nv_bfloat16 lx = __float2bfloat16(zx - __bfloat162float(hx));
    __nv_bfloat16 ly = __float2bfloat16(zy - __bfloat162float(hy));
    *(__nv_bfloat162*)&g_z1h[(size_t)d * 64 + lane * 2] = __nv_bfloat162(hx, hy);
    *(__nv_bfloat162*)&g_z1l[(size_t)d * 64 + lane * 2] = __nv_bfloat162(lx, ly);
}

__global__ void __launch_bounds__(256) agg2_csr_kernel() {
    int d = (blockIdx.x * blockDim.x + threadIdx.x) >> 5;
    int lane = threadIdx.x & 31;
    if (d >= NN) return;
    int beg = g_off[d], end = g_off[d + 1];
    if (beg == end) return;
    float i0 = g_inv[3 * d], i1 = g_inv[3 * d + 1], i2 = g_inv[3 * d + 2];

    float acc = 0.f;
    int i = beg;
    for (; i + 3 < end; i += 4) {
        unsigned v0 = g_epk[i],     v1 = g_epk[i + 1];
        unsigned v2 = g_epk[i + 2], v3 = g_epk[i + 3];
        int s0 = v0 & 0xFFFFF, r0 = v0 >> 20;
        int s1 = v1 & 0xFFFFF, r1 = v1 >> 20;
        int s2 = v2 & 0xFFFFF, r2 = v2 >> 20;
        int s3 = v3 & 0xFFFFF, r3 = v3 >> 20;
        float c0 = (r0 == 0) ? i0 : ((r0 == 1) ? i1 : i2);
        float c1 = (r1 == 0) ? i0 : ((r1 == 1) ? i1 : i2);
        float c2 = (r2 == 0) ? i0 : ((r2 == 1) ? i1 : i2);
        float c3 = (r3 == 0) ? i0 : ((r3 == 1) ? i1 : i2);
        float h0 = g_H2[(size_t)s0 * 96 + r0 * 32 + lane];
        float h1 = g_H2[(size_t)s1 * 96 + r1 * 32 + lane];
        float h2 = g_H2[(size_t)s2 * 96 + r2 * 32 + lane];
        float h3 = g_H2[(size_t)s3 * 96 + r3 * 32 + lane];
        acc += h0 * c0 + h1 * c1 + h2 * c2 + h3 * c3;
    }
    for (; i < end; i++) {
        unsigned v = g_epk[i];
        int s = v & 0xFFFFF, r = v >> 20;
        float sc = (r == 0) ? i0 : ((r == 1) ? i1 : i2);
        acc += g_H2[(size_t)s * 96 + r * 32 + lane] * sc;
    }
    g_Z2[(size_t)d * 32 + lane] += acc;
}

// ---------------------------------------------------------------------------
// per-edge decoder: out[p] = relu(U[s] + V[d] + bd1) . Wd2 + bd2
// ---------------------------------------------------------------------------
__global__ void __launch_bounds__(256) decoder2_kernel(
    const int* __restrict__ psrc, const int* __restrict__ pdst,
    const float* __restrict__ bd1, const float* __restrict__ Wd2,
    const float* __restrict__ bd2, float* __restrict__ out, int P) {
    __shared__ float sB1[64];
    __shared__ float sW2[64];
    int tid = threadIdx.x;
    if (tid < 64) { sB1[tid] = bd1[tid]; sW2[tid] = Wd2[tid]; }
    __syncthreads();

    int p = blockIdx.x * 256 + tid;
    if (p >= P) return;
    int s = psrc[p], d = pdst[p];
    const float* u = &g_UV[(size_t)s * 128];
    const float* v = &g_UV[(size_t)d * 128 + 64];

    float o = bd2[0];
#pragma unroll
    for (int q = 0; q < 16; q++) {
        float4 uu = *(const float4*)&u[q * 4];
        float4 vv = *(const float4*)&v[q * 4];
        float4 bb = *(const float4*)&sB1[q * 4];
        float4 ww = *(const float4*)&sW2[q * 4];
        o += fmaxf(uu.x + vv.x + bb.x, 0.f) * ww.x;
        o += fmaxf(uu.y + vv.y + bb.y, 0.f) * ww.y;
        o += fmaxf(uu.z + vv.z + bb.z, 0.f) * ww.z;
        o += fmaxf(uu.w + vv.w + bb.w, 0.f) * ww.w;
    }
    out[p] = o;
}

// ---------------------------------------------------------------------------
extern "C" void kernel_launch(void* const* d_in, const int* in_sizes, int n_in,
                              void* d_out, int out_size) {
    const float* x     = (const float*)d_in[0];
    const int*   ei    = (const int*)d_in[1];
    const int*   et    = (const int*)d_in[2];
    const int*   pe    = (const int*)d_in[3];
    const float* W1    = (const float*)d_in[4];
    const float* root1 = (const float*)d_in[5];
    const float* b1    = (const float*)d_in[6];
    const float* W2    = (const float*)d_in[7];
    const float* root2 = (const float*)d_in[8];
    const float* b2    = (const float*)d_in[9];
    const float* Wd1   = (const float*)d_in[10];
    const float* bd1   = (const float*)d_in[11];
    const float* Wd2   = (const float*)d_in[12];
    const float* bd2   = (const float*)d_in[13];
    float* out = (float*)d_out;

    const int E = in_sizes[1] / 2;
    const int P = in_sizes[3] / 2;
    const int* src = ei;
    const int* dst = ei + E;
    const int* ps  = pe;
    const int* pd  = pe + P;

    // index 3 = gemm1_bf16 (ncu capture slot)
    zero_cnt_kernel<<<(NN * 3 + 255) / 256, 256>>>(NN * 3);
    splitx_kernel<<<(NN * 32 + 255) / 256, 256>>>(x);
    wt1_kernel<<<(256 * 128 + 255) / 256, 256>>>(W1, root1);
    {
        dim3 g(2, (NN + 127) / 128);
        gemm1_bf16_kernel<<<g, 256>>>(b1);
    }
    wt2_kernel<<<(128 * 64 + 255) / 256, 256>>>(W2, root2);
    wd1c_kernel<<<(32 * 128 + 255) / 256, 256>>>(Wd1);

    // counts + inverse means + CSR (shared by both layers)
    count_kernel<<<(E + 255) / 256, 256>>>(dst, et, E);
    inv_kernel<<<(NN * 3 + 255) / 256, 256>>>(NN * 3);
    scan1_kernel<<<SCAN_NB, SCAN_BS>>>();
    scan2_kernel<<<1, 512>>>();
    scan3_kernel<<<(NN + 255) / 256, 256>>>();
    scatter_kernel<<<(E + 255) / 256, 256>>>(src, dst, et, E);

    // layer 1 aggregation (fused relu + bf16 split for layer 2)
    agg1_csr_kernel<<<(NN * 32 + 255) / 256, 256>>>();

    // layer 2 (bf16 tensor core)
    {
        dim3 g(1, (NN + 127) / 128);
        gemm2_bf16_kernel<<<g, 256>>>(b2);
    }
    agg2_csr_kernel<<<(NN * 32 + 255) / 256, 256>>>();

    // decoder: per-node GEMM (UV), then cheap per-edge kernel
    {
        dim3 g(1, (NN + 127) / 128);
        gemm_uv_kernel<<<g, 256>>>(bd1);
    }
    decoder2_kernel<<<(P + 255) / 256, 256>>>(ps, pd, bd1, Wd2, bd2, out, P);
}

// round 13
// speedup vs baseline: 2.2094x; 1.0261x over previous
#include <cuda_runtime.h>
#include <cuda_bf16.h>

// ---------------------------------------------------------------------------
// RGCN link predictor:
//   split x -> bf16 hi/lo; GEMM1 + GEMM2 = tensor-core bf16 3-term compensated
//   (resident-B in dynamic smem, ldmatrix, double-buffered A), fused H/Z
//   epilogues; prep: fused small-pack kernel, counts/scan(inv)/CSR scatter;
//   CSR warp-per-node agg (no atomics, unroll-4, agg1 fuses relu+bf16 split);
//   decoder decomposed (UV GEMM fp32 + cheap per-edge kernel).
// __device__ globals only referenced from device code (round-3 lesson).
// ---------------------------------------------------------------------------

#define NN    100000
#define REL   3
#define EMAX  1600000
#define SCAN_BS   256
#define SCAN_NB   ((NN + SCAN_BS - 1) / SCAN_BS)   // 391

// scratch (static device globals; no allocation allowed)
__device__ int      g_cnt[NN * REL];
__device__ float    g_inv[NN * REL];
__device__ int      g_off[NN + 1];
__device__ int      g_cur[NN];
__device__ int      g_bsum[SCAN_NB];
__device__ int      g_bpre[SCAN_NB];
__device__ unsigned g_epk[EMAX];     // src | (rel << 20), sorted by dst
__device__ float    g_H1[NN * 192];
__device__ float    g_Z1[NN * 64];
__device__ float    g_H2[NN * 96];
__device__ float    g_Z2[NN * 32];
__device__ float    g_UV[NN * 128];  // cols 0-63: U, 64-127: V
__device__ float    g_Wd1c[32 * 128];
__device__ __nv_bfloat16 g_xh[(size_t)NN * 128];
__device__ __nv_bfloat16 g_xl[(size_t)NN * 128];
__device__ __nv_bfloat16 g_z1h[(size_t)NN * 64];
__device__ __nv_bfloat16 g_z1l[(size_t)NN * 64];
__device__ __nv_bfloat16 g_w1h[256 * 128];   // [n][k] transposed
__device__ __nv_bfloat16 g_w1l[256 * 128];
__device__ __nv_bfloat16 g_w2h[128 * 64];    // [n][k] transposed
__device__ __nv_bfloat16 g_w2l[128 * 64];

// ---------------------------------------------------------------------------
// fused small prep: zero cnt | pack W1 | pack W2 | pack Wd1
// ---------------------------------------------------------------------------
#define PREP_R0 (NN * 3)        // zero cnt
#define PREP_R1 (256 * 128)     // wt1
#define PREP_R2 (128 * 64)      // wt2
#define PREP_R3 (32 * 128)      // wd1c
#define PREP_TOT (PREP_R0 + PREP_R1 + PREP_R2 + PREP_R3)

__global__ void prep_small_kernel(const float* __restrict__ W1,
                                  const float* __restrict__ root1,
                                  const float* __restrict__ W2,
                                  const float* __restrict__ root2,
                                  const float* __restrict__ Wd1) {
    int i = blockIdx.x * blockDim.x + threadIdx.x;
    if (i < PREP_R0) { g_cnt[i] = 0; return; }
    i -= PREP_R0;
    if (i < PREP_R1) {
        int n = i >> 7, k = i & 127;
        float w;
        if (n < 192) {
            int r = n >> 6, j = n & 63;
            w = W1[r * 128 * 64 + k * 64 + j];
        } else {
            w = root1[k * 64 + (n - 192)];
        }
        __nv_bfloat16 h = __float2bfloat16(w);
        g_w1h[i] = h;
        g_w1l[i] = __float2bfloat16(w - __bfloat162float(h));
        return;
    }
    i -= PREP_R1;
    if (i < PREP_R2) {
        int n = i >> 6, k = i & 63;
        float w;
        if (n < 96) {
            int r = n >> 5, j = n & 31;
            w = W2[r * 64 * 32 + k * 32 + j];
        } else {
            w = root2[k * 32 + (n - 96)];
        }
        __nv_bfloat16 h = __float2bfloat16(w);
        g_w2h[i] = h;
        g_w2l[i] = __float2bfloat16(w - __bfloat162float(h));
        return;
    }
    i -= PREP_R2;
    if (i < PREP_R3) {
        int k = i >> 7, c = i & 127;
        g_Wd1c[i] = (c < 64) ? Wd1[k * 64 + c] : Wd1[(32 + k) * 64 + (c - 64)];
    }
}

// split x into bf16 hi + lo
__global__ void splitx_kernel(const float* __restrict__ x) {
    int i = blockIdx.x * blockDim.x + threadIdx.x;   // one float4
    if (i < NN * 32) {
        float4 v = ((const float4*)x)[i];
        __nv_bfloat16 h0 = __float2bfloat16(v.x), h1 = __float2bfloat16(v.y);
        __nv_bfloat16 h2 = __float2bfloat16(v.z), h3 = __float2bfloat16(v.w);
        __nv_bfloat16 l0 = __float2bfloat16(v.x - __bfloat162float(h0));
        __nv_bfloat16 l1 = __float2bfloat16(v.y - __bfloat162float(h1));
        __nv_bfloat16 l2 = __float2bfloat16(v.z - __bfloat162float(h2));
        __nv_bfloat16 l3 = __float2bfloat16(v.w - __bfloat162float(h3));
        __nv_bfloat162* oh = (__nv_bfloat162*)g_xh;
        __nv_bfloat162* ol = (__nv_bfloat162*)g_xl;
        oh[i * 2]     = __nv_bfloat162(h0, h1);
        oh[i * 2 + 1] = __nv_bfloat162(h2, h3);
        ol[i * 2]     = __nv_bfloat162(l0, l1);
        ol[i * 2 + 1] = __nv_bfloat162(l2, l3);
    }
}

__global__ void count_kernel(const int* __restrict__ dst,
                             const int* __restrict__ et, int E) {
    int e = blockIdx.x * blockDim.x + threadIdx.x;
    if (e < E) atomicAdd(&g_cnt[dst[e] * 3 + et[e]], 1);
}

// ---- parallel 3-phase exclusive scan of node degrees (+ inv fused) --------
__global__ void __launch_bounds__(SCAN_BS) scan1_kernel() {
    __shared__ int s[SCAN_BS];
    int t = threadIdx.x;
    int i = blockIdx.x * SCAN_BS + t;
    int d = 0;
    if (i < NN) {
        int c0 = g_cnt[3 * i], c1 = g_cnt[3 * i + 1], c2 = g_cnt[3 * i + 2];
        d = c0 + c1 + c2;
        g_inv[3 * i]     = 1.0f / fmaxf((float)c0, 1.0f);
        g_inv[3 * i + 1] = 1.0f / fmaxf((float)c1, 1.0f);
        g_inv[3 * i + 2] = 1.0f / fmaxf((float)c2, 1.0f);
    }
    s[t] = d;
    __syncthreads();
#pragma unroll
    for (int o = 1; o < SCAN_BS; o <<= 1) {
        int v = (t >= o) ? s[t - o] : 0;
        __syncthreads();
        s[t] += v;
        __syncthreads();
    }
    if (i < NN) g_off[i] = s[t] - d;
    if (t == SCAN_BS - 1) g_bsum[blockIdx.x] = s[t];
}

__global__ void __launch_bounds__(512) scan2_kernel() {
    __shared__ int s[512];
    int t = threadIdx.x;
    int v0 = (t < SCAN_NB) ? g_bsum[t] : 0;
    s[t] = v0;
    __syncthreads();
#pragma unroll
    for (int o = 1; o < 512; o <<= 1) {
        int v = (t >= o) ? s[t - o] : 0;
        __syncthreads();
        s[t] += v;
        __syncthreads();
    }
    if (t < SCAN_NB) g_bpre[t] = s[t] - v0;
    if (t == 511) g_off[NN] = s[511];
}

__global__ void scan3_kernel() {
    int i = blockIdx.x * blockDim.x + threadIdx.x;
    if (i < NN) {
        int off = g_off[i] + g_bpre[i / SCAN_BS];
        g_off[i] = off;
        g_cur[i] = off;
    }
}

__global__ void scatter_kernel(const int* __restrict__ src,
                               const int* __restrict__ dst,
                               const int* __restrict__ et, int E) {
    int e = blockIdx.x * blockDim.x + threadIdx.x;
    if (e < E) {
        int pos = atomicAdd(&g_cur[dst[e]], 1);
        g_epk[pos] = (unsigned)src[e] | ((unsigned)et[e] << 20);
    }
}

// ---------------------------------------------------------------------------
// cp.async / ldmatrix helpers
// ---------------------------------------------------------------------------
__device__ __forceinline__ void cp_async16(void* smem_dst, const void* gmem_src) {
    unsigned saddr = (unsigned)__cvta_generic_to_shared(smem_dst);
    asm volatile("cp.async.cg.shared.global [%0], [%1], 16;\n"
                 :: "r"(saddr), "l"(gmem_src) : "memory");
}
__device__ __forceinline__ void cp_async_commit() {
    asm volatile("cp.async.commit_group;\n" ::: "memory");
}
__device__ __forceinline__ void cp_async_wait0() {
    asm volatile("cp.async.wait_group 0;\n" ::: "memory");
}
__device__ __forceinline__ void ldsm_x4(unsigned& r0, unsigned& r1,
                                        unsigned& r2, unsigned& r3,
                                        const void* p) {
    unsigned addr = (unsigned)__cvta_generic_to_shared(p);
    asm volatile("ldmatrix.sync.aligned.m8n8.x4.shared.b16 {%0,%1,%2,%3}, [%4];"
                 : "=r"(r0), "=r"(r1), "=r"(r2), "=r"(r3) : "r"(addr));
}

#define MMA_BF16(c, a0, a1, a2, a3, b0, b1)                                   \
    asm volatile(                                                             \
        "mma.sync.aligned.m16n8k16.row.col.f32.bf16.bf16.f32 "                \
        "{%0,%1,%2,%3}, {%4,%5,%6,%7}, {%8,%9}, {%0,%1,%2,%3};"               \
        : "+f"((c)[0]), "+f"((c)[1]), "+f"((c)[2]), "+f"((c)[3])              \
        : "r"(a0), "r"(a1), "r"(a2), "r"(a3), "r"(b0), "r"(b1))

// ---------------------------------------------------------------------------
// bf16 tensor-core GEMM core, 3-term compensated, ldmatrix loads.
// Resident B (full n0-panel x K, stride K+8 -> 16B-mod-128 row offsets,
// conflict-free ldmatrix), double-buffered A tiles (stride 24).
// Block 128x128, BK=16, 256 thr = 8 warps (4m x 2n), warp tile 32x64.
// Epilogue per 8-col n-tile: col < HCOLS -> Hd (stride HCOLS) else Zd (+bias).
// ---------------------------------------------------------------------------
template <int K, int HCOLS, int ZW>
__device__ __forceinline__ void gemm_bf16_core(
    const __nv_bfloat16* __restrict__ Ahg, const __nv_bfloat16* __restrict__ Alg,
    const __nv_bfloat16* __restrict__ Bhg, const __nv_bfloat16* __restrict__ Blg,
    float* __restrict__ Hd, float* __restrict__ Zd,
    const float* __restrict__ bias) {

    constexpr int BST = K + 8;            // (K+8)*2B mod 128 == 16 -> ldsm ok
    extern __shared__ __align__(16) __nv_bfloat16 smem[];
    __nv_bfloat16* Ah = smem;                         // [2][128][24]
    __nv_bfloat16* Al = Ah + 2 * 128 * 24;
    __nv_bfloat16* Bh = Al + 2 * 128 * 24;            // [128][BST]
    __nv_bfloat16* Bl = Bh + 128 * BST;

    const int tid = threadIdx.x, lane = tid & 31, wid = tid >> 5;
    const int wm = wid & 3, wn = wid >> 2;
    const int g = lane >> 2, tg = lane & 3;
    const int m0 = blockIdx.y * 128, n0 = blockIdx.x * 128;
    const int row = tid >> 1, ch = tid & 1;

    // ldmatrix per-lane address components
    const int aRow = lane & 15, aK = (lane >> 4) * 8;            // A tiles
    const int bRow = ((lane >> 4) * 8) + (lane & 7);             // B nj-pair
    const int bK8 = ((lane >> 3) & 1) * 8;

    float acc[2][8][4] = {};

    auto issueA = [&](int k0, int buf) {
        int gr = min(m0 + row, NN - 1);
        cp_async16(&Ah[(buf * 128 + row) * 24 + ch * 8],
                   &Ahg[(size_t)gr * K + k0 + ch * 8]);
        cp_async16(&Al[(buf * 128 + row) * 24 + ch * 8],
                   &Alg[(size_t)gr * K + k0 + ch * 8]);
        cp_async_commit();
    };

    // full B panel load (once)
    {
        constexpr int CHUNKS = K / 8;
        constexpr int ITERS = 128 * CHUNKS / 256;
#pragma unroll
        for (int it = 0; it < ITERS; it++) {
            int idx = tid + it * 256;
            int r = idx / CHUNKS, c = idx % CHUNKS;
            cp_async16(&Bh[r * BST + c * 8], &Bhg[(n0 + r) * K + c * 8]);
            cp_async16(&Bl[r * BST + c * 8], &Blg[(n0 + r) * K + c * 8]);
        }
    }
    issueA(0, 0);
    cp_async_wait0();
    __syncthreads();

    constexpr int KT = K / 16;
    int buf = 0;
#pragma unroll
    for (int kt = 0; kt < KT; kt++) {
        if (kt + 1 < KT) issueA((kt + 1) * 16, buf ^ 1);

        const int kOff = kt * 16 + bK8;
        unsigned bh[8][2], bl[8][2];
#pragma unroll
        for (int njp = 0; njp < 4; njp++) {
            int nb = wn * 64 + njp * 16 + bRow;
            ldsm_x4(bh[njp * 2][0], bh[njp * 2][1],
                    bh[njp * 2 + 1][0], bh[njp * 2 + 1][1], &Bh[nb * BST + kOff]);
            ldsm_x4(bl[njp * 2][0], bl[njp * 2][1],
                    bl[njp * 2 + 1][0], bl[njp * 2 + 1][1], &Bl[nb * BST + kOff]);
        }
#pragma unroll
        for (int mi = 0; mi < 2; mi++) {
            int ar = wm * 32 + mi * 16 + aRow;
            unsigned ah0, ah1, ah2, ah3, al0, al1, al2, al3;
            ldsm_x4(ah0, ah1, ah2, ah3, &Ah[(buf * 128 + ar) * 24 + aK]);
            ldsm_x4(al0, al1, al2, al3, &Al[(buf * 128 + ar) * 24 + aK]);
#pragma unroll
            for (int nj = 0; nj < 8; nj++) {
                MMA_BF16(acc[mi][nj], ah0, ah1, ah2, ah3, bh[nj][0], bh[nj][1]);
                MMA_BF16(acc[mi][nj], ah0, ah1, ah2, ah3, bl[nj][0], bl[nj][1]);
                MMA_BF16(acc[mi][nj], al0, al1, al2, al3, bh[nj][0], bh[nj][1]);
            }
        }

        if (kt + 1 < KT) {
            cp_async_wait0();
            __syncthreads();
            buf ^= 1;
        }
    }

#pragma unroll
    for (int mi = 0; mi < 2; mi++) {
#pragma unroll
        for (int nj = 0; nj < 8; nj++) {
            int r0 = m0 + wm * 32 + mi * 16 + g;
            int cb = n0 + wn * 64 + nj * 8 + 2 * tg;
            float* c = acc[mi][nj];
            if (cb >= HCOLS) {                   // uniform per nj (8 | HCOLS)
                int zc = cb - HCOLS;
                float bx = bias[zc], by = bias[zc + 1];
                if (r0 < NN)
                    *(float2*)&Zd[(size_t)r0 * ZW + zc] =
                        make_float2(c[0] + bx, c[1] + by);
                if (r0 + 8 < NN)
                    *(float2*)&Zd[(size_t)(r0 + 8) * ZW + zc] =
                        make_float2(c[2] + bx, c[3] + by);
            } else {
                if (r0 < NN)
                    *(float2*)&Hd[(size_t)r0 * HCOLS + cb] =
                        make_float2(c[0], c[1]);
                if (r0 + 8 < NN)
                    *(float2*)&Hd[(size_t)(r0 + 8) * HCOLS + cb] =
                        make_float2(c[2], c[3]);
            }
        }
    }
}

__global__ void __launch_bounds__(256, 2) gemm1_bf16_kernel(
    const float* __restrict__ b1) {
    gemm_bf16_core<128, 192, 64>(g_xh, g_xl, g_w1h, g_w1l, g_H1, g_Z1, b1);
}
__global__ void __launch_bounds__(256, 2) gemm2_bf16_kernel(
    const float* __restrict__ b2) {
    gemm_bf16_core<64, 96, 32>(g_z1h, g_z1l, g_w2h, g_w2l, g_H2, g_Z2, b2);
}

#define GEMM1_SMEM (2 * 128 * 24 * 2 * 2 + 2 * 128 * (128 + 8) * 2)  // 94208
#define GEMM2_SMEM (2 * 128 * 24 * 2 * 2 + 2 * 128 * (64 + 8) * 2)   // 61440

// ---------------------------------------------------------------------------
// fp32 FFMA2 GEMM core (UV only)
// ---------------------------------------------------------------------------
template <int NTOT, int K, int HCOLS, bool RELU>
__device__ __forceinline__ void gemm_fused_core(
    const float* __restrict__ A, const float* __restrict__ B,
    float* __restrict__ H, float* __restrict__ Z,
    const float* __restrict__ bias, int M) {

    __shared__ float As[2][16][128];
    __shared__ float Bs[2][16][128];

    const int tid = threadIdx.x;
    const int tx = tid & 15, ty = tid >> 4;
    const int m0 = blockIdx.y * 128, n0 = blockIdx.x * 128;

    float4 aReg[2];
    unsigned long long acc2[8][4] = {};

    auto loadA = [&](int k0) {
#pragma unroll
        for (int i = 0; i < 2; i++) {
            int idx = tid + i * 256;
            int row = idx >> 2, c4 = idx & 3;
            int gr = m0 + row;
            float4 v = make_float4(0.f, 0.f, 0.f, 0.f);
            if (gr < M) v = *(const float4*)&A[(size_t)gr * K + k0 + c4 * 4];
            if (RELU) {
                v.x = fmaxf(v.x, 0.f); v.y = fmaxf(v.y, 0.f);
                v.z = fmaxf(v.z, 0.f); v.w = fmaxf(v.w, 0.f);
            }
            aReg[i] = v;
        }
    };
    auto storeA = [&](int buf) {
#pragma unroll
        for (int i = 0; i < 2; i++) {
            int idx = tid + i * 256;
            int row = idx >> 2, c4 = idx & 3;
            As[buf][c4 * 4 + 0][row] = aReg[i].x;
            As[buf][c4 * 4 + 1][row] = aReg[i].y;
            As[buf][c4 * 4 + 2][row] = aReg[i].z;
            As[buf][c4 * 4 + 3][row] = aReg[i].w;
        }
    };
    auto issueB = [&](int k0, int buf) {
#pragma unroll
        for (int i = 0; i < 2; i++) {
            int idx = tid + i * 256;
            int row = idx >> 5, c4 = idx & 31;
            cp_async16(&Bs[buf][row][c4 * 4],
                       &B[(size_t)(k0 + row) * NTOT + n0 + c4 * 4]);
        }
        cp_async_commit();
    };

    constexpr int KT = K / 16;
    loadA(0);
    issueB(0, 0);
    storeA(0);
    cp_async_wait0();
    __syncthreads();

    int buf = 0;
#pragma unroll
    for (int kt = 0; kt < KT; kt++) {
        if (kt + 1 < KT) {
            loadA((kt + 1) * 16);
            issueB((kt + 1) * 16, buf ^ 1);
        }

#pragma unroll
        for (int kk = 0; kk < 16; kk++) {
            float4 a0 = *(float4*)&As[buf][kk][ty * 8];
            float4 a1 = *(float4*)&As[buf][kk][ty * 8 + 4];
            float4 b0 = *(float4*)&Bs[buf][kk][tx * 8];
            float4 b1 = *(float4*)&Bs[buf][kk][tx * 8 + 4];
            unsigned long long bb0, bb1, bb2, bb3;
            asm("mov.b64 %0, {%1, %2};" : "=l"(bb0)
                : "r"(__float_as_uint(b0.x)), "r"(__float_as_uint(b0.y)));
            asm("mov.b64 %0, {%1, %2};" : "=l"(bb1)
                : "r"(__float_as_uint(b0.z)), "r"(__float_as_uint(b0.w)));
            asm("mov.b64 %0, {%1, %2};" : "=l"(bb2)
                : "r"(__float_as_uint(b1.x)), "r"(__float_as_uint(b1.y)));
            asm("mov.b64 %0, {%1, %2};" : "=l"(bb3)
                : "r"(__float_as_uint(b1.z)), "r"(__float_as_uint(b1.w)));
            float av[8] = {a0.x, a0.y, a0.z, a0.w, a1.x, a1.y, a1.z, a1.w};
#pragma unroll
            for (int i = 0; i < 8; i++) {
                unsigned long long pa;
                asm("mov.b64 %0, {%1, %1};"
                    : "=l"(pa) : "r"(__float_as_uint(av[i])));
                asm("fma.rn.f32x2 %0, %1, %2, %0;"
                    : "+l"(acc2[i][0]) : "l"(pa), "l"(bb0));
                asm("fma.rn.f32x2 %0, %1, %2, %0;"
                    : "+l"(acc2[i][1]) : "l"(pa), "l"(bb1));
                asm("fma.rn.f32x2 %0, %1, %2, %0;"
                    : "+l"(acc2[i][2]) : "l"(pa), "l"(bb2));
                asm("fma.rn.f32x2 %0, %1, %2, %0;"
                    : "+l"(acc2[i][3]) : "l"(pa), "l"(bb3));
            }
        }

        if (kt + 1 < KT) {
            storeA(buf ^ 1);
            cp_async_wait0();
            __syncthreads();
            buf ^= 1;
        }
    }

    float acc[8][8];
#pragma unroll
    for (int i = 0; i < 8; i++)
#pragma unroll
        for (int jp = 0; jp < 4; jp++) {
            unsigned lo, hi;
            asm("mov.b64 {%0, %1}, %2;" : "=r"(lo), "=r"(hi) : "l"(acc2[i][jp]));
            acc[i][jp * 2]     = __uint_as_float(lo);
            acc[i][jp * 2 + 1] = __uint_as_float(hi);
        }

    const int cb = n0 + tx * 8;
    if (cb < HCOLS) {
#pragma unroll
        for (int i = 0; i < 8; i++) {
            int gr = m0 + ty * 8 + i;
            if (gr < M) {
                *(float4*)&H[(size_t)gr * HCOLS + cb] =
                    make_float4(acc[i][0], acc[i][1], acc[i][2], acc[i][3]);
                *(float4*)&H[(size_t)gr * HCOLS + cb + 4] =
                    make_float4(acc[i][4], acc[i][5], acc[i][6], acc[i][7]);
            }
        }
    }
}

__global__ void __launch_bounds__(256, 2) gemm_uv_kernel(const float* __restrict__ dummy_bias) {
    gemm_fused_core<128, 32, 128, false>(g_Z2, g_Wd1c, g_UV, g_UV, dummy_bias, NN);
}

// ---------------------------------------------------------------------------
// CSR warp-per-node aggregation, NO atomics, unroll-4.
// agg1 fuses: Z1 += acc, relu, bf16 hi/lo split -> g_z1h/g_z1l.
// ---------------------------------------------------------------------------
__global__ void __launch_bounds__(256) agg1_csr_kernel() {
    int d = (blockIdx.x * blockDim.x + threadIdx.x) >> 5;
    int lane = threadIdx.x & 31;
    if (d >= NN) return;
    int beg = g_off[d], end = g_off[d + 1];
    float i0 = g_inv[3 * d], i1 = g_inv[3 * d + 1], i2 = g_inv[3 * d + 2];

    float2 acc = make_float2(0.f, 0.f);
    int i = beg;
    for (; i + 3 < end; i += 4) {
        unsigned v0 = g_epk[i],     v1 = g_epk[i + 1];
        unsigned v2 = g_epk[i + 2], v3 = g_epk[i + 3];
        int s0 = v0 & 0xFFFFF, r0 = v0 >> 20;
        int s1 = v1 & 0xFFFFF, r1 = v1 >> 20;
        int s2 = v2 & 0xFFFFF, r2 = v2 >> 20;
        int s3 = v3 & 0xFFFFF, r3 = v3 >> 20;
        float c0 = (r0 == 0) ? i0 : ((r0 == 1) ? i1 : i2);
        float c1 = (r1 == 0) ? i0 : ((r1 == 1) ? i1 : i2);
        float c2 = (r2 == 0) ? i0 : ((r2 == 1) ? i1 : i2);
        float c3 = (r3 == 0) ? i0 : ((r3 == 1) ? i1 : i2);
        float2 h0 = *(const float2*)&g_H1[(size_t)s0 * 192 + r0 * 64 + lane * 2];
        float2 h1 = *(const float2*)&g_H1[(size_t)s1 * 192 + r1 * 64 + lane * 2];
        float2 h2 = *(const float2*)&g_H1[(size_t)s2 * 192 + r2 * 64 + lane * 2];
        float2 h3 = *(const float2*)&g_H1[(size_t)s3 * 192 + r3 * 64 + lane * 2];
        acc.x += h0.x * c0 + h1.x * c1 + h2.x * c2 + h3.x * c3;
        acc.y += h0.y * c0 + h1.y * c1 + h2.y * c2 + h3.y * c3;
    }
    for (; i < end; i++) {
        unsigned v = g_epk[i];
        int s = v & 0xFFFFF, r = v >> 20;
        float sc = (r == 0) ? i0 : ((r == 1) ? i1 : i2);
        float2 h = *(const float2*)&g_H1[(size_t)s * 192 + r * 64 + lane * 2];
        acc.x += h.x * sc; acc.y += h.y * sc;
    }
    float2 z = *(const float2*)&g_Z1[(size_t)d * 64 + lane * 2];
    float zx = fmaxf(z.x + acc.x, 0.f);
    float zy = fmaxf(z.y + acc.y, 0.f);
    __nv_bfloat16 hx = __float2bfloat16(zx), hy = __float2bfloat16(zy);
    __nv_bfloat16 lx = __float2bfloat16(zx - __bfloat162float(hx));
    __nv_bfloat16 ly = __float2bfloat16(zy - __bfloat162float(hy));
    *(__nv_bfloat162*)&g_z1h[(size_t)d * 64 + lane * 2] = __nv_bfloat162(hx, hy);
    *(__nv_bfloat162*)&g_z1l[(size_t)d * 64 + lane * 2] = __nv_bfloat162(lx, ly);
}

__global__ void __launch_bounds__(256) agg2_csr_kernel() {
    int d = (blockIdx.x * blockDim.x + threadIdx.x) >> 5;
    int lane = threadIdx.x & 31;
    if (d >= NN) return;
    int beg = g_off[d], end = g_off[d + 1];
    if (beg == end) return;
    float i0 = g_inv[3 * d], i1 = g_inv[3 * d + 1], i2 = g_inv[3 * d + 2];

    float acc = 0.f;
    int i = beg;
    for (; i + 3 < end; i += 4) {
        unsigned v0 = g_epk[i],     v1 = g_epk[i + 1];
        unsigned v2 = g_epk[i + 2], v3 = g_epk[i + 3];
        int s0 = v0 & 0xFFFFF, r0 = v0 >> 20;
        int s1 = v1 & 0xFFFFF, r1 = v1 >> 20;
        int s2 = v2 & 0xFFFFF, r2 = v2 >> 20;
        int s3 = v3 & 0xFFFFF, r3 = v3 >> 20;
        float c0 = (r0 == 0) ? i0 : ((r0 == 1) ? i1 : i2);
        float c1 = (r1 == 0) ? i0 : ((r1 == 1) ? i1 : i2);
        float c2 = (r2 == 0) ? i0 : ((r2 == 1) ? i1 : i2);
        float c3 = (r3 == 0) ? i0 : ((r3 == 1) ? i1 : i2);
        float h0 = g_H2[(size_t)s0 * 96 + r0 * 32 + lane];
        float h1 = g_H2[(size_t)s1 * 96 + r1 * 32 + lane];
        float h2 = g_H2[(size_t)s2 * 96 + r2 * 32 + lane];
        float h3 = g_H2[(size_t)s3 * 96 + r3 * 32 + lane];
        acc += h0 * c0 + h1 * c1 + h2 * c2 + h3 * c3;
    }
    for (; i < end; i++) {
        unsigned v = g_epk[i];
        int s = v & 0xFFFFF, r = v >> 20;
        float sc = (r == 0) ? i0 : ((r == 1) ? i1 : i2);
        acc += g_H2[(size_t)s * 96 + r * 32 + lane] * sc;
    }
    g_Z2[(size_t)d * 32 + lane] += acc;
}

// ---------------------------------------------------------------------------
// per-edge decoder: out[p] = relu(U[s] + V[d] + bd1) . Wd2 + bd2
// ---------------------------------------------------------------------------
__global__ void __launch_bounds__(256) decoder2_kernel(
    const int* __restrict__ psrc, const int* __restrict__ pdst,
    const float* __restrict__ bd1, const float* __restrict__ Wd2,
    const float* __restrict__ bd2, float* __restrict__ out, int P) {
    __shared__ float sB1[64];
    __shared__ float sW2[64];
    int tid = threadIdx.x;
    if (tid < 64) { sB1[tid] = bd1[tid]; sW2[tid] = Wd2[tid]; }
    __syncthreads();

    int p = blockIdx.x * 256 + tid;
    if (p >= P) return;
    int s = psrc[p], d = pdst[p];
    const float* u = &g_UV[(size_t)s * 128];
    const float* v = &g_UV[(size_t)d * 128 + 64];

    float o = bd2[0];
#pragma unroll
    for (int q = 0; q < 16; q++) {
        float4 uu = *(const float4*)&u[q * 4];
        float4 vv = *(const float4*)&v[q * 4];
        float4 bb = *(const float4*)&sB1[q * 4];
        float4 ww = *(const float4*)&sW2[q * 4];
        o += fmaxf(uu.x + vv.x + bb.x, 0.f) * ww.x;
        o += fmaxf(uu.y + vv.y + bb.y, 0.f) * ww.y;
        o += fmaxf(uu.z + vv.z + bb.z, 0.f) * ww.z;
        o += fmaxf(uu.w + vv.w + bb.w, 0.f) * ww.w;
    }
    out[p] = o;
}

// ---------------------------------------------------------------------------
extern "C" void kernel_launch(void* const* d_in, const int* in_sizes, int n_in,
                              void* d_out, int out_size) {
    const float* x     = (const float*)d_in[0];
    const int*   ei    = (const int*)d_in[1];
    const int*   et    = (const int*)d_in[2];
    const int*   pe    = (const int*)d_in[3];
    const float* W1    = (const float*)d_in[4];
    const float* root1 = (const float*)d_in[5];
    const float* b1    = (const float*)d_in[6];
    const float* W2    = (const float*)d_in[7];
    const float* root2 = (const float*)d_in[8];
    const float* b2    = (const float*)d_in[9];
    const float* Wd1   = (const float*)d_in[10];
    const float* bd1   = (const float*)d_in[11];
    const float* Wd2   = (const float*)d_in[12];
    const float* bd2   = (const float*)d_in[13];
    float* out = (float*)d_out;

    const int E = in_sizes[1] / 2;
    const int P = in_sizes[3] / 2;
    const int* src = ei;
    const int* dst = ei + E;
    const int* ps  = pe;
    const int* pd  = pe + P;

    // opt-in to >48KB dynamic smem (immediate, capture-safe, idempotent)
    cudaFuncSetAttribute(gemm1_bf16_kernel,
                         cudaFuncAttributeMaxDynamicSharedMemorySize, GEMM1_SMEM);
    cudaFuncSetAttribute(gemm2_bf16_kernel,
                         cudaFuncAttributeMaxDynamicSharedMemorySize, GEMM2_SMEM);

    // launch index 3 = gemm1_bf16 (ncu capture slot)
    prep_small_kernel<<<(PREP_TOT + 255) / 256, 256>>>(W1, root1, W2, root2, Wd1);
    splitx_kernel<<<(NN * 32 + 255) / 256, 256>>>(x);
    count_kernel<<<(E + 255) / 256, 256>>>(dst, et, E);
    {
        dim3 g(2, (NN + 127) / 128);
        gemm1_bf16_kernel<<<g, 256, GEMM1_SMEM>>>(b1);
    }

    // CSR build (inv fused into scan1)
    scan1_kernel<<<SCAN_NB, SCAN_BS>>>();
    scan2_kernel<<<1, 512>>>();
    scan3_kernel<<<(NN + 255) / 256, 256>>>();
    scatter_kernel<<<(E + 255) / 256, 256>>>(src, dst, et, E);

    // layer 1 aggregation (fused relu + bf16 split for layer 2)
    agg1_csr_kernel<<<(NN * 32 + 255) / 256, 256>>>();

    // layer 2 (bf16 tensor core)
    {
        dim3 g(1, (NN + 127) / 128);
        gemm2_bf16_kernel<<<g, 256, GEMM2_SMEM>>>(b2);
    }
    agg2_csr_kernel<<<(NN * 32 + 255) / 256, 256>>>();

    // decoder: per-node GEMM (UV), then cheap per-edge kernel
    {
        dim3 g(1, (NN + 127) / 128);
        gemm_uv_kernel<<<g, 256>>>(bd1);
    }
    decoder2_kernel<<<(P + 255) / 256, 256>>>(ps, pd, bd1, Wd2, bd2, out, P);
}

// round 14
// speedup vs baseline: 2.2623x; 1.0239x over previous
#include <cuda_runtime.h>
#include <cuda_bf16.h>

// ---------------------------------------------------------------------------
// RGCN link predictor:
//   Dual-stream fork-join (capture-safe): GEMM chain (pack/splitx/gemm1) on
//   the capture stream overlaps the CSR chain (zero/count/scan/scatter) on a
//   static secondary stream; join before agg1.
//   GEMM1+GEMM2 = bf16 3-term compensated tensor-core (resident-B, ldmatrix);
//   CSR warp-per-node agg (no atomics, unroll-4, agg1 fuses relu+bf16 split);
//   decoder decomposed (UV GEMM fp32 + cheap per-edge kernel).
// __device__ globals only referenced from device code (round-3 lesson).
// ---------------------------------------------------------------------------

#define NN    100000
#define REL   3
#define EMAX  1600000
#define SCAN_BS   256
#define SCAN_NB   ((NN + SCAN_BS - 1) / SCAN_BS)   // 391

// scratch (static device globals; no allocation allowed)
__device__ int      g_cnt[NN * REL];
__device__ float    g_inv[NN * REL];
__device__ int      g_off[NN + 1];
__device__ int      g_cur[NN];
__device__ int      g_bsum[SCAN_NB];
__device__ int      g_bpre[SCAN_NB];
__device__ unsigned g_epk[EMAX];     // src | (rel << 20), sorted by dst
__device__ float    g_H1[NN * 192];
__device__ float    g_Z1[NN * 64];
__device__ float    g_H2[NN * 96];
__device__ float    g_Z2[NN * 32];
__device__ float    g_UV[NN * 128];  // cols 0-63: U, 64-127: V
__device__ float    g_Wd1c[32 * 128];
__device__ __nv_bfloat16 g_xh[(size_t)NN * 128];
__device__ __nv_bfloat16 g_xl[(size_t)NN * 128];
__device__ __nv_bfloat16 g_z1h[(size_t)NN * 64];
__device__ __nv_bfloat16 g_z1l[(size_t)NN * 64];
__device__ __nv_bfloat16 g_w1h[256 * 128];   // [n][k] transposed
__device__ __nv_bfloat16 g_w1l[256 * 128];
__device__ __nv_bfloat16 g_w2h[128 * 64];    // [n][k] transposed
__device__ __nv_bfloat16 g_w2l[128 * 64];

// ---------------------------------------------------------------------------
__global__ void zero_cnt_kernel(int n) {
    int i = blockIdx.x * blockDim.x + threadIdx.x;
    if (i < n) g_cnt[i] = 0;
}

// fused weight pack: W1 | W2 | Wd1
#define PREP_R1 (256 * 128)     // wt1
#define PREP_R2 (128 * 64)      // wt2
#define PREP_R3 (32 * 128)      // wd1c
#define PREP_TOT (PREP_R1 + PREP_R2 + PREP_R3)

__global__ void prep_w_kernel(const float* __restrict__ W1,
                              const float* __restrict__ root1,
                              const float* __restrict__ W2,
                              const float* __restrict__ root2,
                              const float* __restrict__ Wd1) {
    int i = blockIdx.x * blockDim.x + threadIdx.x;
    if (i < PREP_R1) {
        int n = i >> 7, k = i & 127;
        float w;
        if (n < 192) {
            int r = n >> 6, j = n & 63;
            w = W1[r * 128 * 64 + k * 64 + j];
        } else {
            w = root1[k * 64 + (n - 192)];
        }
        __nv_bfloat16 h = __float2bfloat16(w);
        g_w1h[i] = h;
        g_w1l[i] = __float2bfloat16(w - __bfloat162float(h));
        return;
    }
    i -= PREP_R1;
    if (i < PREP_R2) {
        int n = i >> 6, k = i & 63;
        float w;
        if (n < 96) {
            int r = n >> 5, j = n & 31;
            w = W2[r * 64 * 32 + k * 32 + j];
        } else {
            w = root2[k * 32 + (n - 96)];
        }
        __nv_bfloat16 h = __float2bfloat16(w);
        g_w2h[i] = h;
        g_w2l[i] = __float2bfloat16(w - __bfloat162float(h));
        return;
    }
    i -= PREP_R2;
    if (i < PREP_R3) {
        int k = i >> 7, c = i & 127;
        g_Wd1c[i] = (c < 64) ? Wd1[k * 64 + c] : Wd1[(32 + k) * 64 + (c - 64)];
    }
}

// split x into bf16 hi + lo
__global__ void splitx_kernel(const float* __restrict__ x) {
    int i = blockIdx.x * blockDim.x + threadIdx.x;   // one float4
    if (i < NN * 32) {
        float4 v = ((const float4*)x)[i];
        __nv_bfloat16 h0 = __float2bfloat16(v.x), h1 = __float2bfloat16(v.y);
        __nv_bfloat16 h2 = __float2bfloat16(v.z), h3 = __float2bfloat16(v.w);
        __nv_bfloat16 l0 = __float2bfloat16(v.x - __bfloat162float(h0));
        __nv_bfloat16 l1 = __float2bfloat16(v.y - __bfloat162float(h1));
        __nv_bfloat16 l2 = __float2bfloat16(v.z - __bfloat162float(h2));
        __nv_bfloat16 l3 = __float2bfloat16(v.w - __bfloat162float(h3));
        __nv_bfloat162* oh = (__nv_bfloat162*)g_xh;
        __nv_bfloat162* ol = (__nv_bfloat162*)g_xl;
        oh[i * 2]     = __nv_bfloat162(h0, h1);
        oh[i * 2 + 1] = __nv_bfloat162(h2, h3);
        ol[i * 2]     = __nv_bfloat162(l0, l1);
        ol[i * 2 + 1] = __nv_bfloat162(l2, l3);
    }
}

__global__ void count_kernel(const int* __restrict__ dst,
                             const int* __restrict__ et, int E) {
    int e = blockIdx.x * blockDim.x + threadIdx.x;
    if (e < E) atomicAdd(&g_cnt[dst[e] * 3 + et[e]], 1);
}

// ---- parallel 3-phase exclusive scan of node degrees (+ inv fused) --------
__global__ void __launch_bounds__(SCAN_BS) scan1_kernel() {
    __shared__ int s[SCAN_BS];
    int t = threadIdx.x;
    int i = blockIdx.x * SCAN_BS + t;
    int d = 0;
    if (i < NN) {
        int c0 = g_cnt[3 * i], c1 = g_cnt[3 * i + 1], c2 = g_cnt[3 * i + 2];
        d = c0 + c1 + c2;
        g_inv[3 * i]     = 1.0f / fmaxf((float)c0, 1.0f);
        g_inv[3 * i + 1] = 1.0f / fmaxf((float)c1, 1.0f);
        g_inv[3 * i + 2] = 1.0f / fmaxf((float)c2, 1.0f);
    }
    s[t] = d;
    __syncthreads();
#pragma unroll
    for (int o = 1; o < SCAN_BS; o <<= 1) {
        int v = (t >= o) ? s[t - o] : 0;
        __syncthreads();
        s[t] += v;
        __syncthreads();
    }
    if (i < NN) g_off[i] = s[t] - d;
    if (t == SCAN_BS - 1) g_bsum[blockIdx.x] = s[t];
}

__global__ void __launch_bounds__(512) scan2_kernel() {
    __shared__ int s[512];
    int t = threadIdx.x;
    int v0 = (t < SCAN_NB) ? g_bsum[t] : 0;
    s[t] = v0;
    __syncthreads();
#pragma unroll
    for (int o = 1; o < 512; o <<= 1) {
        int v = (t >= o) ? s[t - o] : 0;
        __syncthreads();
        s[t] += v;
        __syncthreads();
    }
    if (t < SCAN_NB) g_bpre[t] = s[t] - v0;
    if (t == 511) g_off[NN] = s[511];
}

__global__ void scan3_kernel() {
    int i = blockIdx.x * blockDim.x + threadIdx.x;
    if (i < NN) {
        int off = g_off[i] + g_bpre[i / SCAN_BS];
        g_off[i] = off;
        g_cur[i] = off;
    }
}

__global__ void scatter_kernel(const int* __restrict__ src,
                               const int* __restrict__ dst,
                               const int* __restrict__ et, int E) {
    int e = blockIdx.x * blockDim.x + threadIdx.x;
    if (e < E) {
        int pos = atomicAdd(&g_cur[dst[e]], 1);
        g_epk[pos] = (unsigned)src[e] | ((unsigned)et[e] << 20);
    }
}

// ---------------------------------------------------------------------------
// cp.async / ldmatrix helpers
// ---------------------------------------------------------------------------
__device__ __forceinline__ void cp_async16(void* smem_dst, const void* gmem_src) {
    unsigned saddr = (unsigned)__cvta_generic_to_shared(smem_dst);
    asm volatile("cp.async.cg.shared.global [%0], [%1], 16;\n"
                 :: "r"(saddr), "l"(gmem_src) : "memory");
}
__device__ __forceinline__ void cp_async_commit() {
    asm volatile("cp.async.commit_group;\n" ::: "memory");
}
__device__ __forceinline__ void cp_async_wait0() {
    asm volatile("cp.async.wait_group 0;\n" ::: "memory");
}
__device__ __forceinline__ void ldsm_x4(unsigned& r0, unsigned& r1,
                                        unsigned& r2, unsigned& r3,
                                        const void* p) {
    unsigned addr = (unsigned)__cvta_generic_to_shared(p);
    asm volatile("ldmatrix.sync.aligned.m8n8.x4.shared.b16 {%0,%1,%2,%3}, [%4];"
                 : "=r"(r0), "=r"(r1), "=r"(r2), "=r"(r3) : "r"(addr));
}

#define MMA_BF16(c, a0, a1, a2, a3, b0, b1)                                   \
    asm volatile(                                                             \
        "mma.sync.aligned.m16n8k16.row.col.f32.bf16.bf16.f32 "                \
        "{%0,%1,%2,%3}, {%4,%5,%6,%7}, {%8,%9}, {%0,%1,%2,%3};"               \
        : "+f"((c)[0]), "+f"((c)[1]), "+f"((c)[2]), "+f"((c)[3])              \
        : "r"(a0), "r"(a1), "r"(a2), "r"(a3), "r"(b0), "r"(b1))

// ---------------------------------------------------------------------------
// bf16 tensor-core GEMM core, 3-term compensated, ldmatrix loads.
// Resident B panel (stride K+8), double-buffered A tiles (stride 24).
// Block 128x128, BK=16, 256 thr = 8 warps (4m x 2n), warp tile 32x64.
// ---------------------------------------------------------------------------
template <int K, int HCOLS, int ZW>
__device__ __forceinline__ void gemm_bf16_core(
    const __nv_bfloat16* __restrict__ Ahg, const __nv_bfloat16* __restrict__ Alg,
    const __nv_bfloat16* __restrict__ Bhg, const __nv_bfloat16* __restrict__ Blg,
    float* __restrict__ Hd, float* __restrict__ Zd,
    const float* __restrict__ bias) {

    constexpr int BST = K + 8;            // (K+8)*2B mod 128 == 16 -> ldsm ok
    extern __shared__ __align__(16) __nv_bfloat16 smem[];
    __nv_bfloat16* Ah = smem;                         // [2][128][24]
    __nv_bfloat16* Al = Ah + 2 * 128 * 24;
    __nv_bfloat16* Bh = Al + 2 * 128 * 24;            // [128][BST]
    __nv_bfloat16* Bl = Bh + 128 * BST;

    const int tid = threadIdx.x, lane = tid & 31, wid = tid >> 5;
    const int wm = wid & 3, wn = wid >> 2;
    const int g = lane >> 2, tg = lane & 3;
    const int m0 = blockIdx.y * 128, n0 = blockIdx.x * 128;
    const int row = tid >> 1, ch = tid & 1;

    const int aRow = lane & 15, aK = (lane >> 4) * 8;
    const int bRow = ((lane >> 4) * 8) + (lane & 7);
    const int bK8 = ((lane >> 3) & 1) * 8;

    float acc[2][8][4] = {};

    auto issueA = [&](int k0, int buf) {
        int gr = min(m0 + row, NN - 1);
        cp_async16(&Ah[(buf * 128 + row) * 24 + ch * 8],
                   &Ahg[(size_t)gr * K + k0 + ch * 8]);
        cp_async16(&Al[(buf * 128 + row) * 24 + ch * 8],
                   &Alg[(size_t)gr * K + k0 + ch * 8]);
        cp_async_commit();
    };

    {
        constexpr int CHUNKS = K / 8;
        constexpr int ITERS = 128 * CHUNKS / 256;
#pragma unroll
        for (int it = 0; it < ITERS; it++) {
            int idx = tid + it * 256;
            int r = idx / CHUNKS, c = idx % CHUNKS;
            cp_async16(&Bh[r * BST + c * 8], &Bhg[(n0 + r) * K + c * 8]);
            cp_async16(&Bl[r * BST + c * 8], &Blg[(n0 + r) * K + c * 8]);
        }
    }
    issueA(0, 0);
    cp_async_wait0();
    __syncthreads();

    constexpr int KT = K / 16;
    int buf = 0;
#pragma unroll
    for (int kt = 0; kt < KT; kt++) {
        if (kt + 1 < KT) issueA((kt + 1) * 16, buf ^ 1);

        const int kOff = kt * 16 + bK8;
        unsigned bh[8][2], bl[8][2];
#pragma unroll
        for (int njp = 0; njp < 4; njp++) {
            int nb = wn * 64 + njp * 16 + bRow;
            ldsm_x4(bh[njp * 2][0], bh[njp * 2][1],
                    bh[njp * 2 + 1][0], bh[njp * 2 + 1][1], &Bh[nb * BST + kOff]);
            ldsm_x4(bl[njp * 2][0], bl[njp * 2][1],
                    bl[njp * 2 + 1][0], bl[njp * 2 + 1][1], &Bl[nb * BST + kOff]);
        }
#pragma unroll
        for (int mi = 0; mi < 2; mi++) {
            int ar = wm * 32 + mi * 16 + aRow;
            unsigned ah0, ah1, ah2, ah3, al0, al1, al2, al3;
            ldsm_x4(ah0, ah1, ah2, ah3, &Ah[(buf * 128 + ar) * 24 + aK]);
            ldsm_x4(al0, al1, al2, al3, &Al[(buf * 128 + ar) * 24 + aK]);
#pragma unroll
            for (int nj = 0; nj < 8; nj++) {
                MMA_BF16(acc[mi][nj], ah0, ah1, ah2, ah3, bh[nj][0], bh[nj][1]);
                MMA_BF16(acc[mi][nj], ah0, ah1, ah2, ah3, bl[nj][0], bl[nj][1]);
                MMA_BF16(acc[mi][nj], al0, al1, al2, al3, bh[nj][0], bh[nj][1]);
            }
        }

        if (kt + 1 < KT) {
            cp_async_wait0();
            __syncthreads();
            buf ^= 1;
        }
    }

#pragma unroll
    for (int mi = 0; mi < 2; mi++) {
#pragma unroll
        for (int nj = 0; nj < 8; nj++) {
            int r0 = m0 + wm * 32 + mi * 16 + g;
            int cb = n0 + wn * 64 + nj * 8 + 2 * tg;
            float* c = acc[mi][nj];
            if (cb >= HCOLS) {
                int zc = cb - HCOLS;
                float bx = bias[zc], by = bias[zc + 1];
                if (r0 < NN)
                    *(float2*)&Zd[(size_t)r0 * ZW + zc] =
                        make_float2(c[0] + bx, c[1] + by);
                if (r0 + 8 < NN)
                    *(float2*)&Zd[(size_t)(r0 + 8) * ZW + zc] =
                        make_float2(c[2] + bx, c[3] + by);
            } else {
                if (r0 < NN)
                    *(float2*)&Hd[(size_t)r0 * HCOLS + cb] =
                        make_float2(c[0], c[1]);
                if (r0 + 8 < NN)
                    *(float2*)&Hd[(size_t)(r0 + 8) * HCOLS + cb] =
                        make_float2(c[2], c[3]);
            }
        }
    }
}

__global__ void __launch_bounds__(256, 2) gemm1_bf16_kernel(
    const float* __restrict__ b1) {
    gemm_bf16_core<128, 192, 64>(g_xh, g_xl, g_w1h, g_w1l, g_H1, g_Z1, b1);
}
__global__ void __launch_bounds__(256, 2) gemm2_bf16_kernel(
    const float* __restrict__ b2) {
    gemm_bf16_core<64, 96, 32>(g_z1h, g_z1l, g_w2h, g_w2l, g_H2, g_Z2, b2);
}

#define GEMM1_SMEM (2 * 128 * 24 * 2 * 2 + 2 * 128 * (128 + 8) * 2)  // 94208
#define GEMM2_SMEM (2 * 128 * 24 * 2 * 2 + 2 * 128 * (64 + 8) * 2)   // 61440

// ---------------------------------------------------------------------------
// fp32 FFMA2 GEMM core (UV only)
// ---------------------------------------------------------------------------
template <int NTOT, int K, int HCOLS, bool RELU>
__device__ __forceinline__ void gemm_fused_core(
    const float* __restrict__ A, const float* __restrict__ B,
    float* __restrict__ H, float* __restrict__ Z,
    const float* __restrict__ bias, int M) {

    __shared__ float As[2][16][128];
    __shared__ float Bs[2][16][128];

    const int tid = threadIdx.x;
    const int tx = tid & 15, ty = tid >> 4;
    const int m0 = blockIdx.y * 128, n0 = blockIdx.x * 128;

    float4 aReg[2];
    unsigned long long acc2[8][4] = {};

    auto loadA = [&](int k0) {
#pragma unroll
        for (int i = 0; i < 2; i++) {
            int idx = tid + i * 256;
            int row = idx >> 2, c4 = idx & 3;
            int gr = m0 + row;
            float4 v = make_float4(0.f, 0.f, 0.f, 0.f);
            if (gr < M) v = *(const float4*)&A[(size_t)gr * K + k0 + c4 * 4];
            if (RELU) {
                v.x = fmaxf(v.x, 0.f); v.y = fmaxf(v.y, 0.f);
                v.z = fmaxf(v.z, 0.f); v.w = fmaxf(v.w, 0.f);
            }
            aReg[i] = v;
        }
    };
    auto storeA = [&](int buf) {
#pragma unroll
        for (int i = 0; i < 2; i++) {
            int idx = tid + i * 256;
            int row = idx >> 2, c4 = idx & 3;
            As[buf][c4 * 4 + 0][row] = aReg[i].x;
            As[buf][c4 * 4 + 1][row] = aReg[i].y;
            As[buf][c4 * 4 + 2][row] = aReg[i].z;
            As[buf][c4 * 4 + 3][row] = aReg[i].w;
        }
    };
    auto issueB = [&](int k0, int buf) {
#pragma unroll
        for (int i = 0; i < 2; i++) {
            int idx = tid + i * 256;
            int row = idx >> 5, c4 = idx & 31;
            cp_async16(&Bs[buf][row][c4 * 4],
                       &B[(size_t)(k0 + row) * NTOT + n0 + c4 * 4]);
        }
        cp_async_commit();
    };

    constexpr int KT = K / 16;
    loadA(0);
    issueB(0, 0);
    storeA(0);
    cp_async_wait0();
    __syncthreads();

    int buf = 0;
#pragma unroll
    for (int kt = 0; kt < KT; kt++) {
        if (kt + 1 < KT) {
            loadA((kt + 1) * 16);
            issueB((kt + 1) * 16, buf ^ 1);
        }

#pragma unroll
        for (int kk = 0; kk < 16; kk++) {
            float4 a0 = *(float4*)&As[buf][kk][ty * 8];
            float4 a1 = *(float4*)&As[buf][kk][ty * 8 + 4];
            float4 b0 = *(float4*)&Bs[buf][kk][tx * 8];
            float4 b1 = *(float4*)&Bs[buf][kk][tx * 8 + 4];
            unsigned long long bb0, bb1, bb2, bb3;
            asm("mov.b64 %0, {%1, %2};" : "=l"(bb0)
                : "r"(__float_as_uint(b0.x)), "r"(__float_as_uint(b0.y)));
            asm("mov.b64 %0, {%1, %2};" : "=l"(bb1)
                : "r"(__float_as_uint(b0.z)), "r"(__float_as_uint(b0.w)));
            asm("mov.b64 %0, {%1, %2};" : "=l"(bb2)
                : "r"(__float_as_uint(b1.x)), "r"(__float_as_uint(b1.y)));
            asm("mov.b64 %0, {%1, %2};" : "=l"(bb3)
                : "r"(__float_as_uint(b1.z)), "r"(__float_as_uint(b1.w)));
            float av[8] = {a0.x, a0.y, a0.z, a0.w, a1.x, a1.y, a1.z, a1.w};
#pragma unroll
            for (int i = 0; i < 8; i++) {
                unsigned long long pa;
                asm("mov.b64 %0, {%1, %1};"
                    : "=l"(pa) : "r"(__float_as_uint(av[i])));
                asm("fma.rn.f32x2 %0, %1, %2, %0;"
                    : "+l"(acc2[i][0]) : "l"(pa), "l"(bb0));
                asm("fma.rn.f32x2 %0, %1, %2, %0;"
                    : "+l"(acc2[i][1]) : "l"(pa), "l"(bb1));
                asm("fma.rn.f32x2 %0, %1, %2, %0;"
                    : "+l"(acc2[i][2]) : "l"(pa), "l"(bb2));
                asm("fma.rn.f32x2 %0, %1, %2, %0;"
                    : "+l"(acc2[i][3]) : "l"(pa), "l"(bb3));
            }
        }

        if (kt + 1 < KT) {
            storeA(buf ^ 1);
            cp_async_wait0();
            __syncthreads();
            buf ^= 1;
        }
    }

    float acc[8][8];
#pragma unroll
    for (int i = 0; i < 8; i++)
#pragma unroll
        for (int jp = 0; jp < 4; jp++) {
            unsigned lo, hi;
            asm("mov.b64 {%0, %1}, %2;" : "=r"(lo), "=r"(hi) : "l"(acc2[i][jp]));
            acc[i][jp * 2]     = __uint_as_float(lo);
            acc[i][jp * 2 + 1] = __uint_as_float(hi);
        }

    const int cb = n0 + tx * 8;
    if (cb < HCOLS) {
#pragma unroll
        for (int i = 0; i < 8; i++) {
            int gr = m0 + ty * 8 + i;
            if (gr < M) {
                *(float4*)&H[(size_t)gr * HCOLS + cb] =
                    make_float4(acc[i][0], acc[i][1], acc[i][2], acc[i][3]);
                *(float4*)&H[(size_t)gr * HCOLS + cb + 4] =
                    make_float4(acc[i][4], acc[i][5], acc[i][6], acc[i][7]);
            }
        }
    }
}

__global__ void __launch_bounds__(256, 2) gemm_uv_kernel(const float* __restrict__ dummy_bias) {
    gemm_fused_core<128, 32, 128, false>(g_Z2, g_Wd1c, g_UV, g_UV, dummy_bias, NN);
}

// ---------------------------------------------------------------------------
// CSR warp-per-node aggregation, NO atomics, unroll-4.
// agg1 fuses: Z1 += acc, relu, bf16 hi/lo split -> g_z1h/g_z1l.
// ---------------------------------------------------------------------------
__global__ void __launch_bounds__(256) agg1_csr_kernel() {
    int d = (blockIdx.x * blockDim.x + threadIdx.x) >> 5;
    int lane = threadIdx.x & 31;
    if (d >= NN) return;
    int beg = g_off[d], end = g_off[d + 1];
    float i0 = g_inv[3 * d], i1 = g_inv[3 * d + 1], i2 = g_inv[3 * d + 2];

    float2 acc = make_float2(0.f, 0.f);
    int i = beg;
    for (; i + 3 < end; i += 4) {
        unsigned v0 = g_epk[i],     v1 = g_epk[i + 1];
        unsigned v2 = g_epk[i + 2], v3 = g_epk[i + 3];
        int s0 = v0 & 0xFFFFF, r0 = v0 >> 20;
        int s1 = v1 & 0xFFFFF, r1 = v1 >> 20;
        int s2 = v2 & 0xFFFFF, r2 = v2 >> 20;
        int s3 = v3 & 0xFFFFF, r3 = v3 >> 20;
        float c0 = (r0 == 0) ? i0 : ((r0 == 1) ? i1 : i2);
        float c1 = (r1 == 0) ? i0 : ((r1 == 1) ? i1 : i2);
        float c2 = (r2 == 0) ? i0 : ((r2 == 1) ? i1 : i2);
        float c3 = (r3 == 0) ? i0 : ((r3 == 1) ? i1 : i2);
        float2 h0 = *(const float2*)&g_H1[(size_t)s0 * 192 + r0 * 64 + lane * 2];
        float2 h1 = *(const float2*)&g_H1[(size_t)s1 * 192 + r1 * 64 + lane * 2];
        float2 h2 = *(const float2*)&g_H1[(size_t)s2 * 192 + r2 * 64 + lane * 2];
        float2 h3 = *(const float2*)&g_H1[(size_t)s3 * 192 + r3 * 64 + lane * 2];
        acc.x += h0.x * c0 + h1.x * c1 + h2.x * c2 + h3.x * c3;
        acc.y += h0.y * c0 + h1.y * c1 + h2.y * c2 + h3.y * c3;
    }
    for (; i < end; i++) {
        unsigned v = g_epk[i];
        int s = v & 0xFFFFF, r = v >> 20;
        float sc = (r == 0) ? i0 : ((r == 1) ? i1 : i2);
        float2 h = *(const float2*)&g_H1[(size_t)s * 192 + r * 64 + lane * 2];
        acc.x += h.x * sc; acc.y += h.y * sc;
    }
    float2 z = *(const float2*)&g_Z1[(size_t)d * 64 + lane * 2];
    float zx = fmaxf(z.x + acc.x, 0.f);
    float zy = fmaxf(z.y + acc.y, 0.f);
    __nv_bfloat16 hx = __float2bfloat16(zx), hy = __float2bfloat16(zy);
    __nv_bfloat16 lx = __float2bfloat16(zx - __bfloat162float(hx));
    __nv_bfloat16 ly = __float2bfloat16(zy - __bfloat162float(hy));
    *(__nv_bfloat162*)&g_z1h[(size_t)d * 64 + lane * 2] = __nv_bfloat162(hx, hy);
    *(__nv_bfloat162*)&g_z1l[(size_t)d * 64 + lane * 2] = __nv_bfloat162(lx, ly);
}

__global__ void __launch_bounds__(256) agg2_csr_kernel() {
    int d = (blockIdx.x * blockDim.x + threadIdx.x) >> 5;
    int lane = threadIdx.x & 31;
    if (d >= NN) return;
    int beg = g_off[d], end = g_off[d + 1];
    if (beg == end) return;
    float i0 = g_inv[3 * d], i1 = g_inv[3 * d + 1], i2 = g_inv[3 * d + 2];

    float acc = 0.f;
    int i = beg;
    for (; i + 3 < end; i += 4) {
        unsigned v0 = g_epk[i],     v1 = g_epk[i + 1];
        unsigned v2 = g_epk[i + 2], v3 = g_epk[i + 3];
        int s0 = v0 & 0xFFFFF, r0 = v0 >> 20;
        int s1 = v1 & 0xFFFFF, r1 = v1 >> 20;
        int s2 = v2 & 0xFFFFF, r2 = v2 >> 20;
        int s3 = v3 & 0xFFFFF, r3 = v3 >> 20;
        float c0 = (r0 == 0) ? i0 : ((r0 == 1) ? i1 : i2);
        float c1 = (r1 == 0) ? i0 : ((r1 == 1) ? i1 : i2);
        float c2 = (r2 == 0) ? i0 : ((r2 == 1) ? i1 : i2);
        float c3 = (r3 == 0) ? i0 : ((r3 == 1) ? i1 : i2);
        float h0 = g_H2[(size_t)s0 * 96 + r0 * 32 + lane];
        float h1 = g_H2[(size_t)s1 * 96 + r1 * 32 + lane];
        float h2 = g_H2[(size_t)s2 * 96 + r2 * 32 + lane];
        float h3 = g_H2[(size_t)s3 * 96 + r3 * 32 + lane];
        acc += h0 * c0 + h1 * c1 + h2 * c2 + h3 * c3;
    }
    for (; i < end; i++) {
        unsigned v = g_epk[i];
        int s = v & 0xFFFFF, r = v >> 20;
        float sc = (r == 0) ? i0 : ((r == 1) ? i1 : i2);
        acc += g_H2[(size_t)s * 96 + r * 32 + lane] * sc;
    }
    g_Z2[(size_t)d * 32 + lane] += acc;
}

// ---------------------------------------------------------------------------
// per-edge decoder: out[p] = relu(U[s] + V[d] + bd1) . Wd2 + bd2
// ---------------------------------------------------------------------------
__global__ void __launch_bounds__(256) decoder2_kernel(
    const int* __restrict__ psrc, const int* __restrict__ pdst,
    const float* __restrict__ bd1, const float* __restrict__ Wd2,
    const float* __restrict__ bd2, float* __restrict__ out, int P) {
    __shared__ float sB1[64];
    __shared__ float sW2[64];
    int tid = threadIdx.x;
    if (tid < 64) { sB1[tid] = bd1[tid]; sW2[tid] = Wd2[tid]; }
    __syncthreads();

    int p = blockIdx.x * 256 + tid;
    if (p >= P) return;
    int s = psrc[p], d = pdst[p];
    const float* u = &g_UV[(size_t)s * 128];
    const float* v = &g_UV[(size_t)d * 128 + 64];

    float o = bd2[0];
#pragma unroll
    for (int q = 0; q < 16; q++) {
        float4 uu = *(const float4*)&u[q * 4];
        float4 vv = *(const float4*)&v[q * 4];
        float4 bb = *(const float4*)&sB1[q * 4];
        float4 ww = *(const float4*)&sW2[q * 4];
        o += fmaxf(uu.x + vv.x + bb.x, 0.f) * ww.x;
        o += fmaxf(uu.y + vv.y + bb.y, 0.f) * ww.y;
        o += fmaxf(uu.z + vv.z + bb.z, 0.f) * ww.z;
        o += fmaxf(uu.w + vv.w + bb.w, 0.f) * ww.w;
    }
    out[p] = o;
}

// ---------------------------------------------------------------------------
extern "C" void kernel_launch(void* const* d_in, const int* in_sizes, int n_in,
                              void* d_out, int out_size) {
    const float* x     = (const float*)d_in[0];
    const int*   ei    = (const int*)d_in[1];
    const int*   et    = (const int*)d_in[2];
    const int*   pe    = (const int*)d_in[3];
    const float* W1    = (const float*)d_in[4];
    const float* root1 = (const float*)d_in[5];
    const float* b1    = (const float*)d_in[6];
    const float* W2    = (const float*)d_in[7];
    const float* root2 = (const float*)d_in[8];
    const float* b2    = (const float*)d_in[9];
    const float* Wd1   = (const float*)d_in[10];
    const float* bd1   = (const float*)d_in[11];
    const float* Wd2   = (const float*)d_in[12];
    const float* bd2   = (const float*)d_in[13];
    float* out = (float*)d_out;

    const int E = in_sizes[1] / 2;
    const int P = in_sizes[3] / 2;
    const int* src = ei;
    const int* dst = ei + E;
    const int* ps  = pe;
    const int* pd  = pe + P;

    // one-time resources (created during the uncaptured correctness call;
    // reused unchanged during graph capture — no resource ops inside capture)
    static cudaStream_t s2 = nullptr;
    static cudaEvent_t evFork = nullptr, evJoin = nullptr;
    static bool attrDone = false;
    if (!attrDone) {
        cudaFuncSetAttribute(gemm1_bf16_kernel,
                             cudaFuncAttributeMaxDynamicSharedMemorySize, GEMM1_SMEM);
        cudaFuncSetAttribute(gemm2_bf16_kernel,
                             cudaFuncAttributeMaxDynamicSharedMemorySize, GEMM2_SMEM);
        cudaStreamCreateWithFlags(&s2, cudaStreamNonBlocking);
        cudaEventCreateWithFlags(&evFork, cudaEventDisableTiming);
        cudaEventCreateWithFlags(&evJoin, cudaEventDisableTiming);
        attrDone = true;
    }

    // ---- fork: CSR chain on s2, GEMM chain on capture stream ----
    cudaEventRecord(evFork, 0);
    cudaStreamWaitEvent(s2, evFork, 0);

    // stream s2: zero -> count -> scan(inv) -> scatter
    zero_cnt_kernel<<<(NN * 3 + 255) / 256, 256, 0, s2>>>(NN * 3);
    count_kernel<<<(E + 255) / 256, 256, 0, s2>>>(dst, et, E);
    scan1_kernel<<<SCAN_NB, SCAN_BS, 0, s2>>>();
    scan2_kernel<<<1, 512, 0, s2>>>();
    scan3_kernel<<<(NN + 255) / 256, 256, 0, s2>>>();
    scatter_kernel<<<(E + 255) / 256, 256, 0, s2>>>(src, dst, et, E);
    cudaEventRecord(evJoin, s2);

    // capture stream: pack weights -> splitx -> gemm1
    prep_w_kernel<<<(PREP_TOT + 255) / 256, 256>>>(W1, root1, W2, root2, Wd1);
    splitx_kernel<<<(NN * 32 + 255) / 256, 256>>>(x);
    {
        dim3 g(2, (NN + 127) / 128);
        gemm1_bf16_kernel<<<g, 256, GEMM1_SMEM>>>(b1);
    }

    // ---- join ----
    cudaStreamWaitEvent(0, evJoin, 0);

    // layer 1 aggregation (fused relu + bf16 split for layer 2)
    agg1_csr_kernel<<<(NN * 32 + 255) / 256, 256>>>();

    // layer 2 (bf16 tensor core)
    {
        dim3 g(1, (NN + 127) / 128);
        gemm2_bf16_kernel<<<g, 256, GEMM2_SMEM>>>(b2);
    }
    agg2_csr_kernel<<<(NN * 32 + 255) / 256, 256>>>();

    // decoder: per-node GEMM (UV), then cheap per-edge kernel
    {
        dim3 g(1, (NN + 127) / 128);
        gemm_uv_kernel<<<g, 256>>>(bd1);
    }
    decoder2_kernel<<<(P + 255) / 256, 256>>>(ps, pd, bd1, Wd2, bd2, out, P);
}